// round 1
// baseline (speedup 1.0000x reference)
#include <cuda_runtime.h>
#include <math.h>

#define NN 50000
#define EE 800000
#define IND 128
#define DD 256
#define LL 6
#define EPSF 1e-5f

// ---------------- scratch (static device arrays; no allocation) ----------------
__device__ __align__(16) float d_h[(size_t)NN * DD];        // 51.2 MB
__device__ __align__(16) float d_hn[(size_t)NN * DD];       // 51.2 MB
__device__ __align__(16) float d_xlxr[(size_t)NN * 2 * DD]; // 102.4 MB (xl | xr)
__device__ __align__(16) float d_hsum[(size_t)NN * DD];     // 51.2 MB
__device__ __align__(16) float d_y1[(size_t)NN * DD];       // 51.2 MB
__device__ __align__(16) float d_y2[(size_t)NN * (DD / 2)]; // 25.6 MB
__device__ int   d_rowptr[NN + 1];
__device__ int   d_deg[NN];
__device__ int   d_cursor[NN];
__device__ int   d_csrsrc[EE + NN];
__device__ float d_w[LL];

__device__ __forceinline__ float lrelu(float x, float a) { return x > 0.f ? x : a * x; }

// ---------------- tiny kernels ----------------
__global__ void k_softmax_w(const float* __restrict__ sw, float* __restrict__ w) {
    if (threadIdx.x == 0 && blockIdx.x == 0) {
        float m = -1e30f;
        for (int i = 0; i < LL; i++) m = fmaxf(m, sw[i]);
        float e[LL]; float s = 0.f;
        for (int i = 0; i < LL; i++) { e[i] = __expf(sw[i] - m); s += e[i]; }
        for (int i = 0; i < LL; i++) w[i] = e[i] / s;
    }
}

__global__ void k_deg_init(int* __restrict__ deg) {
    int i = blockIdx.x * blockDim.x + threadIdx.x;
    if (i < NN) deg[i] = 1; // self loop
}

__global__ void k_deg_count(const int* __restrict__ dst, int* __restrict__ deg) {
    int i = blockIdx.x * blockDim.x + threadIdx.x;
    if (i < EE) atomicAdd(&deg[dst[i]], 1);
}

// single-block (1024 thr) exclusive scan of deg -> rowptr
__global__ void k_scan(const int* __restrict__ deg, int* __restrict__ rowptr) {
    const int T = 1024;
    int t = threadIdx.x;
    int chunk = (NN + T - 1) / T;
    int start = t * chunk;
    int end = start + chunk; if (end > NN) end = NN;
    int s = 0;
    for (int i = start; i < end && i < NN; i++) s += deg[i];
    __shared__ int wsum[32];
    int lane = t & 31, wid = t >> 5;
    int v = s;
    for (int d = 1; d < 32; d <<= 1) {
        int u = __shfl_up_sync(0xffffffffu, v, d);
        if (lane >= d) v += u;
    }
    if (lane == 31) wsum[wid] = v;
    __syncthreads();
    if (wid == 0) {
        int x = wsum[lane];
        for (int d = 1; d < 32; d <<= 1) {
            int u = __shfl_up_sync(0xffffffffu, x, d);
            if (lane >= d) x += u;
        }
        wsum[lane] = x;
    }
    __syncthreads();
    int excl = v - s + (wid > 0 ? wsum[wid - 1] : 0);
    int off = excl;
    for (int i = start; i < end && i < NN; i++) { rowptr[i] = off; off += deg[i]; }
    if (t == T - 1) rowptr[NN] = off;
}

__global__ void k_selfloop(const int* __restrict__ rowptr, int* __restrict__ cursor,
                           int* __restrict__ csrsrc) {
    int v = blockIdx.x * blockDim.x + threadIdx.x;
    if (v < NN) { int p = rowptr[v]; csrsrc[p] = v; cursor[v] = p + 1; }
}

__global__ void k_scatter(const int* __restrict__ src, const int* __restrict__ dst,
                          int* __restrict__ cursor, int* __restrict__ csrsrc) {
    int i = blockIdx.x * blockDim.x + threadIdx.x;
    if (i < EE) {
        int p = atomicAdd(&cursor[dst[i]], 1);
        csrsrc[p] = src[i];
    }
}

// ---------------- layernorm: one warp per row of 256 ----------------
__global__ __launch_bounds__(256) void k_layernorm(
    const float* __restrict__ h, const float* __restrict__ g,
    const float* __restrict__ b, float* __restrict__ hn) {
    int v = (int)((blockIdx.x * blockDim.x + threadIdx.x) >> 5);
    if (v >= NN) return;
    int lane = threadIdx.x & 31;
    const float4* h4 = (const float4*)h;
    float4 x0 = h4[v * 64 + lane];
    float4 x1 = h4[v * 64 + 32 + lane];
    float s = x0.x + x0.y + x0.z + x0.w + x1.x + x1.y + x1.z + x1.w;
    float q = x0.x * x0.x + x0.y * x0.y + x0.z * x0.z + x0.w * x0.w
            + x1.x * x1.x + x1.y * x1.y + x1.z * x1.z + x1.w * x1.w;
    for (int d = 16; d; d >>= 1) {
        s += __shfl_xor_sync(0xffffffffu, s, d);
        q += __shfl_xor_sync(0xffffffffu, q, d);
    }
    float mu = s * (1.0f / 256.0f);
    float var = q * (1.0f / 256.0f) - mu * mu;
    float r = rsqrtf(var + EPSF);
    const float4* g4 = (const float4*)g;
    const float4* b4 = (const float4*)b;
    float4 ga = __ldg(&g4[lane]), gb = __ldg(&g4[lane + 32]);
    float4 ba = __ldg(&b4[lane]), bb = __ldg(&b4[lane + 32]);
    float4 o0, o1;
    o0.x = (x0.x - mu) * r * ga.x + ba.x;
    o0.y = (x0.y - mu) * r * ga.y + ba.y;
    o0.z = (x0.z - mu) * r * ga.z + ba.z;
    o0.w = (x0.w - mu) * r * ga.w + ba.w;
    o1.x = (x1.x - mu) * r * gb.x + bb.x;
    o1.y = (x1.y - mu) * r * gb.y + bb.y;
    o1.z = (x1.z - mu) * r * gb.z + bb.z;
    o1.w = (x1.w - mu) * r * gb.w + bb.w;
    ((float4*)hn)[v * 64 + lane] = o0;
    ((float4*)hn)[v * 64 + 32 + lane] = o1;
}

// ---------------- fp32 SIMT GEMM: C[M, coloff+n] = epi(A[M,K] @ B[K,Nc] + bias) ----------------
// EPI 0: +bias ; EPI 1: bn_eval + lrelu(0.1) ; EPI 2: lrelu(0.1)
template <int EPI>
__global__ __launch_bounds__(256) void k_gemm(
    const float* __restrict__ A, const float* __restrict__ B,
    const float* __restrict__ bias, const float* __restrict__ bng,
    const float* __restrict__ bnb, float* __restrict__ C,
    int M, int K, int Nc, int ldc, int coloff) {
    const int BM = 128, BN = 128, BK = 16;
    __shared__ float As[2][BK][BM + 4];
    __shared__ float Bs[2][BK][BN + 4];
    int bm = blockIdx.y * BM;
    int bn = blockIdx.x * BN;
    int tid = threadIdx.x;
    int trow = (tid >> 4) * 4;  // 0..60
    int tcol = (tid & 15) * 4;  // 0..60
    float acc[8][8];
#pragma unroll
    for (int i = 0; i < 8; i++)
#pragma unroll
        for (int j = 0; j < 8; j++) acc[i][j] = 0.f;

    float4 ra[2], rb[2];
    auto LOADG = [&](int kk) {
#pragma unroll
        for (int u = 0; u < 2; u++) {
            int s = tid + u * 256;
            int arow = s >> 2, ac = (s & 3) * 4;
            int gr = bm + arow;
            if (gr < M) ra[u] = *(const float4*)(A + (size_t)gr * K + kk + ac);
            else ra[u] = make_float4(0.f, 0.f, 0.f, 0.f);
            int brow = s >> 5, bc = (s & 31) * 4;
            rb[u] = *(const float4*)(B + (size_t)(kk + brow) * Nc + bn + bc);
        }
    };
    auto STORES = [&](int buf) {
#pragma unroll
        for (int u = 0; u < 2; u++) {
            int s = tid + u * 256;
            int arow = s >> 2, ac = (s & 3) * 4;
            As[buf][ac + 0][arow] = ra[u].x;
            As[buf][ac + 1][arow] = ra[u].y;
            As[buf][ac + 2][arow] = ra[u].z;
            As[buf][ac + 3][arow] = ra[u].w;
            int brow = s >> 5, bc = (s & 31) * 4;
            *(float4*)&Bs[buf][brow][bc] = rb[u];
        }
    };
    int nk = K / BK;
    LOADG(0);
    STORES(0);
    __syncthreads();
    for (int t = 0; t < nk; t++) {
        int cur = t & 1;
        if (t + 1 < nk) LOADG((t + 1) * BK);
#pragma unroll
        for (int k = 0; k < BK; k++) {
            float a[8], b[8];
            *(float4*)&a[0] = *(float4*)&As[cur][k][trow];
            *(float4*)&a[4] = *(float4*)&As[cur][k][trow + 64];
            *(float4*)&b[0] = *(float4*)&Bs[cur][k][tcol];
            *(float4*)&b[4] = *(float4*)&Bs[cur][k][tcol + 64];
#pragma unroll
            for (int i = 0; i < 8; i++)
#pragma unroll
                for (int j = 0; j < 8; j++) acc[i][j] = fmaf(a[i], b[j], acc[i][j]);
        }
        if (t + 1 < nk) STORES(cur ^ 1);
        __syncthreads();
    }

    float rsb = rsqrtf(1.0f + EPSF);
#pragma unroll
    for (int i = 0; i < 8; i++) {
        int r = bm + trow + (i < 4 ? i : 60 + i);
        if (r >= M) continue;
#pragma unroll
        for (int j = 0; j < 8; j++) {
            int c = bn + tcol + (j < 4 ? j : 60 + j);
            float v = acc[i][j] + __ldg(&bias[c]);
            if (EPI == 1) {
                v = v * rsb * __ldg(&bng[c]) + __ldg(&bnb[c]);
                v = lrelu(v, 0.1f);
            } else if (EPI == 2) {
                v = lrelu(v, 0.1f);
            }
            C[(size_t)r * ldc + coloff + c] = v;
        }
    }
}

// ---------------- GATv2 attention aggregation: one warp per node, online softmax ----------------
// lane layout: lane holds channels [4l..4l+3] (head A = l>>3) and [128+4l..128+4l+3] (head B = 4+(l>>3))
__global__ __launch_bounds__(256) void k_gat(
    const float* __restrict__ xlxr, const int* __restrict__ rowptr,
    const int* __restrict__ csrsrc, const float* __restrict__ att,
    const float* __restrict__ convb, const float* __restrict__ scales,
    const float* __restrict__ wvec, int li,
    float* __restrict__ h, float* __restrict__ hsum) {
    int v = (int)((blockIdx.x * blockDim.x + threadIdx.x) >> 5);
    if (v >= NN) return;
    int lane = threadIdx.x & 31;
    const float4* x4 = (const float4*)xlxr;
    const float4* att4 = (const float4*)att;
    int hA = lane >> 3;
    float4 aA = __ldg(&att4[hA * 8 + (lane & 7)]);
    float4 aB = __ldg(&att4[(hA + 4) * 8 + (lane & 7)]);
    int vb = v * 128;
    float4 xrA = __ldg(&x4[vb + 64 + lane]);
    float4 xrB = __ldg(&x4[vb + 96 + lane]);
    float mA = -1e30f, mB = -1e30f, dA = 0.f, dB = 0.f;
    float4 accA = make_float4(0.f, 0.f, 0.f, 0.f);
    float4 accB = make_float4(0.f, 0.f, 0.f, 0.f);
    int e1 = __ldg(&rowptr[v + 1]);
    for (int e = __ldg(&rowptr[v]); e < e1; e++) {
        int s = __ldg(&csrsrc[e]);
        int sb = s * 128;
        float4 xlA = __ldg(&x4[sb + lane]);
        float4 xlB = __ldg(&x4[sb + 32 + lane]);
        float pA = lrelu(xlA.x + xrA.x, 0.2f) * aA.x
                 + lrelu(xlA.y + xrA.y, 0.2f) * aA.y
                 + lrelu(xlA.z + xrA.z, 0.2f) * aA.z
                 + lrelu(xlA.w + xrA.w, 0.2f) * aA.w;
        float pB = lrelu(xlB.x + xrB.x, 0.2f) * aB.x
                 + lrelu(xlB.y + xrB.y, 0.2f) * aB.y
                 + lrelu(xlB.z + xrB.z, 0.2f) * aB.z
                 + lrelu(xlB.w + xrB.w, 0.2f) * aB.w;
        // reduce over the 8-lane head group
        pA += __shfl_xor_sync(0xffffffffu, pA, 1);
        pB += __shfl_xor_sync(0xffffffffu, pB, 1);
        pA += __shfl_xor_sync(0xffffffffu, pA, 2);
        pB += __shfl_xor_sync(0xffffffffu, pB, 2);
        pA += __shfl_xor_sync(0xffffffffu, pA, 4);
        pB += __shfl_xor_sync(0xffffffffu, pB, 4);
        // online softmax update head A
        float nmA = fmaxf(mA, pA);
        float scA = __expf(mA - nmA);
        float epA = __expf(pA - nmA);
        dA = dA * scA + epA;
        accA.x = accA.x * scA + xlA.x * epA;
        accA.y = accA.y * scA + xlA.y * epA;
        accA.z = accA.z * scA + xlA.z * epA;
        accA.w = accA.w * scA + xlA.w * epA;
        mA = nmA;
        // head B
        float nmB = fmaxf(mB, pB);
        float scB = __expf(mB - nmB);
        float epB = __expf(pB - nmB);
        dB = dB * scB + epB;
        accB.x = accB.x * scB + xlB.x * epB;
        accB.y = accB.y * scB + xlB.y * epB;
        accB.z = accB.z * scB + xlB.z * epB;
        accB.w = accB.w * scB + xlB.w * epB;
        mB = nmB;
    }
    const float4* cb4 = (const float4*)convb;
    float4 cbA = __ldg(&cb4[lane]);
    float4 cbB = __ldg(&cb4[lane + 32]);
    float sci = __ldg(&scales[li]);
    float wi = __ldg(&wvec[li]);
    float4* h4 = (float4*)h;
    float4 rA = h4[v * 64 + lane];
    float4 rB = h4[v * 64 + 32 + lane];
    float idA = 1.0f / dA, idB = 1.0f / dB;
    float4 hnA, hnB;
    hnA.x = rA.x + sci * lrelu(accA.x * idA + cbA.x, 0.1f);
    hnA.y = rA.y + sci * lrelu(accA.y * idA + cbA.y, 0.1f);
    hnA.z = rA.z + sci * lrelu(accA.z * idA + cbA.z, 0.1f);
    hnA.w = rA.w + sci * lrelu(accA.w * idA + cbA.w, 0.1f);
    hnB.x = rB.x + sci * lrelu(accB.x * idB + cbB.x, 0.1f);
    hnB.y = rB.y + sci * lrelu(accB.y * idB + cbB.y, 0.1f);
    hnB.z = rB.z + sci * lrelu(accB.z * idB + cbB.z, 0.1f);
    hnB.w = rB.w + sci * lrelu(accB.w * idB + cbB.w, 0.1f);
    h4[v * 64 + lane] = hnA;
    h4[v * 64 + 32 + lane] = hnB;
    float4* hs4 = (float4*)hsum;
    if (li == 0) {
        float4 sa, sb;
        sa.x = wi * hnA.x; sa.y = wi * hnA.y; sa.z = wi * hnA.z; sa.w = wi * hnA.w;
        sb.x = wi * hnB.x; sb.y = wi * hnB.y; sb.z = wi * hnB.z; sb.w = wi * hnB.w;
        hs4[v * 64 + lane] = sa;
        hs4[v * 64 + 32 + lane] = sb;
    } else {
        float4 sa = hs4[v * 64 + lane];
        float4 sb = hs4[v * 64 + 32 + lane];
        sa.x += wi * hnA.x; sa.y += wi * hnA.y; sa.z += wi * hnA.z; sa.w += wi * hnA.w;
        sb.x += wi * hnB.x; sb.y += wi * hnB.y; sb.z += wi * hnB.z; sb.w += wi * hnB.w;
        hs4[v * 64 + lane] = sa;
        hs4[v * 64 + 32 + lane] = sb;
    }
}

// ---------------- final projection: out[v] = y2[v,:128] . h3_w + h3_b ----------------
__global__ __launch_bounds__(256) void k_final(
    const float* __restrict__ y2, const float* __restrict__ w,
    const float* __restrict__ b, float* __restrict__ out) {
    int v = (int)((blockIdx.x * blockDim.x + threadIdx.x) >> 5);
    if (v >= NN) return;
    int lane = threadIdx.x & 31;
    const float4* y4 = (const float4*)y2;
    const float4* w4 = (const float4*)w;
    float4 a = y4[v * 32 + lane];
    float4 ww = __ldg(&w4[lane]);
    float p = a.x * ww.x + a.y * ww.y + a.z * ww.z + a.w * ww.w;
    for (int d = 16; d; d >>= 1) p += __shfl_xor_sync(0xffffffffu, p, d);
    if (lane == 0) out[v] = p + __ldg(&b[0]);
}

// ---------------- launcher ----------------
extern "C" void kernel_launch(void* const* d_in, const int* in_sizes, int n_in,
                              void* d_out, int out_size) {
    (void)in_sizes; (void)n_in; (void)out_size;
    const float* x      = (const float*)d_in[0];
    const int*   ei     = (const int*)d_in[1];
    const float* win_w  = (const float*)d_in[2];
    const float* win_b  = (const float*)d_in[3];
    const float* bn1_g  = (const float*)d_in[4];
    const float* bn1_b  = (const float*)d_in[5];
    const float* ln_g   = (const float*)d_in[6];
    const float* ln_b   = (const float*)d_in[7];
    const float* Wl     = (const float*)d_in[8];
    const float* bl     = (const float*)d_in[9];
    const float* Wr     = (const float*)d_in[10];
    const float* br     = (const float*)d_in[11];
    const float* att    = (const float*)d_in[12];
    const float* conv_b = (const float*)d_in[13];
    const float* scales = (const float*)d_in[14];
    const float* sw     = (const float*)d_in[15];
    const float* h1_w   = (const float*)d_in[16];
    const float* h1_b   = (const float*)d_in[17];
    const float* bn2_g  = (const float*)d_in[18];
    const float* bn2_b  = (const float*)d_in[19];
    const float* h2_w   = (const float*)d_in[20];
    const float* h2_b   = (const float*)d_in[21];
    const float* h3_w   = (const float*)d_in[22];
    const float* h3_b   = (const float*)d_in[23];
    float* out = (float*)d_out;

    float *p_h, *p_hn, *p_xlxr, *p_hsum, *p_y1, *p_y2, *p_w;
    int *p_rowptr, *p_deg, *p_cursor, *p_csr;
    cudaGetSymbolAddress((void**)&p_h, d_h);
    cudaGetSymbolAddress((void**)&p_hn, d_hn);
    cudaGetSymbolAddress((void**)&p_xlxr, d_xlxr);
    cudaGetSymbolAddress((void**)&p_hsum, d_hsum);
    cudaGetSymbolAddress((void**)&p_y1, d_y1);
    cudaGetSymbolAddress((void**)&p_y2, d_y2);
    cudaGetSymbolAddress((void**)&p_w, d_w);
    cudaGetSymbolAddress((void**)&p_rowptr, d_rowptr);
    cudaGetSymbolAddress((void**)&p_deg, d_deg);
    cudaGetSymbolAddress((void**)&p_cursor, d_cursor);
    cudaGetSymbolAddress((void**)&p_csr, d_csrsrc);

    const int* e_src = ei;
    const int* e_dst = ei + EE;

    // softmax of scale_weights
    k_softmax_w<<<1, 32>>>(sw, p_w);

    // CSR build (by destination)
    k_deg_init<<<(NN + 255) / 256, 256>>>(p_deg);
    k_deg_count<<<(EE + 255) / 256, 256>>>(e_dst, p_deg);
    k_scan<<<1, 1024>>>(p_deg, p_rowptr);
    k_selfloop<<<(NN + 255) / 256, 256>>>(p_rowptr, p_cursor, p_csr);
    k_scatter<<<(EE + 255) / 256, 256>>>(e_src, e_dst, p_cursor, p_csr);

    const int warpBlocks = (NN * 32 + 255) / 256;

    // input projection: h = lrelu(bn1(x @ win_w + win_b))
    {
        dim3 g(DD / 128, (NN + 127) / 128);
        k_gemm<1><<<g, 256>>>(x, win_w, win_b, bn1_g, bn1_b, p_h, NN, IND, DD, DD, 0);
    }

    // layers
    for (int i = 0; i < LL; i++) {
        k_layernorm<<<warpBlocks, 256>>>(p_h, ln_g + i * DD, ln_b + i * DD, p_hn);
        dim3 g(DD / 128, (NN + 127) / 128);
        k_gemm<0><<<g, 256>>>(p_hn, Wl + (size_t)i * DD * DD, bl + i * DD,
                              nullptr, nullptr, p_xlxr, NN, DD, DD, 2 * DD, 0);
        k_gemm<0><<<g, 256>>>(p_hn, Wr + (size_t)i * DD * DD, br + i * DD,
                              nullptr, nullptr, p_xlxr, NN, DD, DD, 2 * DD, DD);
        k_gat<<<warpBlocks, 256>>>(p_xlxr, p_rowptr, p_csr, att + i * DD,
                                   conv_b + i * DD, scales, p_w, i, p_h, p_hsum);
    }

    // head
    {
        dim3 g(DD / 128, (NN + 127) / 128);
        k_gemm<1><<<g, 256>>>(p_hsum, h1_w, h1_b, bn2_g, bn2_b, p_y1, NN, DD, DD, DD, 0);
        dim3 g2((DD / 2) / 128, (NN + 127) / 128);
        k_gemm<2><<<g2, 256>>>(p_y1, h2_w, h2_b, nullptr, nullptr, p_y2, NN, DD, DD / 2, DD / 2, 0);
    }
    k_final<<<warpBlocks, 256>>>(p_y2, h3_w, h3_b, out);
}

// round 3
// speedup vs baseline: 1.7850x; 1.7850x over previous
#include <cuda_runtime.h>
#include <cuda_bf16.h>
#include <stdint.h>
#include <math.h>

#define NN 50000
#define EE 800000
#define IND 128
#define DD 256
#define LL 6
#define EPSF 1e-5f
#define NB 196

// smem stage layout (bytes)
#define AH_OFF 0
#define AL_OFF 10240
#define BH_OFF 20480
#define BL_OFF 29184
#define STAGE_BYTES 37888
// A: 128 rows x 40 b16 stride (32 used); B: 32 rows x 136 b16 stride (128 used)

// ---------------- scratch ----------------
__device__ __align__(16) float d_h[(size_t)NN * DD];
__device__ __align__(16) float d_hn[(size_t)NN * DD];
__device__ __align__(16) float d_xlxr[(size_t)NN * 2 * DD];
__device__ __align__(16) float d_hsum[(size_t)NN * DD];
__device__ __align__(16) float d_y1[(size_t)NN * DD];
__device__ __align__(16) float d_y2[(size_t)NN * (DD / 2)];
__device__ int   d_rowptr[NN + 1];
__device__ int   d_deg[NN];
__device__ int   d_bsum[NB];
__device__ int   d_cursor[NN];
__device__ int   d_csrsrc[EE + NN];
__device__ float d_w[LL];

__device__ __forceinline__ float lrelu(float x, float a) { return x > 0.f ? x : a * x; }

// ---------------- tiny kernels ----------------
__global__ void k_softmax_w(const float* __restrict__ sw, float* __restrict__ w) {
    if (threadIdx.x == 0 && blockIdx.x == 0) {
        float m = -1e30f;
        for (int i = 0; i < LL; i++) m = fmaxf(m, sw[i]);
        float e[LL];
        float s = 0.f;
        for (int i = 0; i < LL; i++) { e[i] = __expf(sw[i] - m); s += e[i]; }
        for (int i = 0; i < LL; i++) w[i] = e[i] / s;
    }
}

__global__ void k_deg_init(int* __restrict__ deg) {
    int i = blockIdx.x * blockDim.x + threadIdx.x;
    if (i < NN) deg[i] = 1;
}

__global__ void k_deg_count(const int* __restrict__ dst, int* __restrict__ deg) {
    int i = blockIdx.x * blockDim.x + threadIdx.x;
    if (i < EE) atomicAdd(&deg[dst[i]], 1);
}

__global__ void k_blocksum(const int* __restrict__ deg, int* __restrict__ bsum) {
    int i = blockIdx.x * 256 + threadIdx.x;
    int v = (i < NN) ? deg[i] : 0;
    int lane = threadIdx.x & 31;
    int wid = threadIdx.x >> 5;
    for (int d = 16; d; d >>= 1) v += __shfl_xor_sync(0xffffffffu, v, d);
    __shared__ int ws[8];
    if (lane == 0) ws[wid] = v;
    __syncthreads();
    if (threadIdx.x == 0) {
        int s = 0;
        for (int k = 0; k < 8; k++) s += ws[k];
        bsum[blockIdx.x] = s;
    }
}

__global__ void k_bscan(int* __restrict__ bsum) {
    int t = threadIdx.x;
    int v = (t < NB) ? bsum[t] : 0;
    int lane = t & 31;
    int wid = t >> 5;
    int x = v;
    for (int d = 1; d < 32; d <<= 1) {
        int u = __shfl_up_sync(0xffffffffu, x, d);
        if (lane >= d) x += u;
    }
    __shared__ int ws[8];
    if (lane == 31) ws[wid] = x;
    __syncthreads();
    if (wid == 0 && lane < 8) {
        int y = ws[lane];
        for (int d = 1; d < 8; d <<= 1) {
            int u = __shfl_up_sync(0xffu, y, d);
            if (lane >= d) y += u;
        }
        ws[lane] = y;
    }
    __syncthreads();
    int incl = x + (wid > 0 ? ws[wid - 1] : 0);
    if (t < NB) bsum[t] = incl - v;
}

__global__ void k_scanout(const int* __restrict__ deg, const int* __restrict__ boff,
                          int* __restrict__ rowptr) {
    int t = threadIdx.x;
    int i = blockIdx.x * 256 + t;
    int v = (i < NN) ? deg[i] : 0;
    int lane = t & 31;
    int wid = t >> 5;
    int x = v;
    for (int d = 1; d < 32; d <<= 1) {
        int u = __shfl_up_sync(0xffffffffu, x, d);
        if (lane >= d) x += u;
    }
    __shared__ int ws[8];
    if (lane == 31) ws[wid] = x;
    __syncthreads();
    if (wid == 0 && lane < 8) {
        int y = ws[lane];
        for (int d = 1; d < 8; d <<= 1) {
            int u = __shfl_up_sync(0xffu, y, d);
            if (lane >= d) y += u;
        }
        ws[lane] = y;
    }
    __syncthreads();
    int excl = x - v + (wid > 0 ? ws[wid - 1] : 0) + boff[blockIdx.x];
    if (i < NN) rowptr[i] = excl;
    if (i == 0) rowptr[NN] = EE + NN;
}

__global__ void k_selfloop(const int* __restrict__ rowptr, int* __restrict__ cursor,
                           int* __restrict__ csrsrc) {
    int v = blockIdx.x * blockDim.x + threadIdx.x;
    if (v < NN) {
        int p = rowptr[v];
        csrsrc[p] = v;
        cursor[v] = p + 1;
    }
}

__global__ void k_scatter(const int* __restrict__ src, const int* __restrict__ dst,
                          int* __restrict__ cursor, int* __restrict__ csrsrc) {
    int i = blockIdx.x * blockDim.x + threadIdx.x;
    if (i < EE) {
        int p = atomicAdd(&cursor[dst[i]], 1);
        csrsrc[p] = src[i];
    }
}

// ---------------- layernorm ----------------
__global__ __launch_bounds__(256) void k_layernorm(
    const float* __restrict__ h, const float* __restrict__ g,
    const float* __restrict__ b, float* __restrict__ hn) {
    int v = (int)((blockIdx.x * blockDim.x + threadIdx.x) >> 5);
    if (v >= NN) return;
    int lane = threadIdx.x & 31;
    const float4* h4 = (const float4*)h;
    float4 x0 = h4[v * 64 + lane];
    float4 x1 = h4[v * 64 + 32 + lane];
    float s = x0.x + x0.y + x0.z + x0.w + x1.x + x1.y + x1.z + x1.w;
    float q = x0.x * x0.x + x0.y * x0.y + x0.z * x0.z + x0.w * x0.w
            + x1.x * x1.x + x1.y * x1.y + x1.z * x1.z + x1.w * x1.w;
    for (int d = 16; d; d >>= 1) {
        s += __shfl_xor_sync(0xffffffffu, s, d);
        q += __shfl_xor_sync(0xffffffffu, q, d);
    }
    float mu = s * (1.0f / 256.0f);
    float var = q * (1.0f / 256.0f) - mu * mu;
    float r = rsqrtf(var + EPSF);
    const float4* g4 = (const float4*)g;
    const float4* b4 = (const float4*)b;
    float4 ga = __ldg(&g4[lane]);
    float4 gb = __ldg(&g4[lane + 32]);
    float4 ba = __ldg(&b4[lane]);
    float4 bb = __ldg(&b4[lane + 32]);
    float4 o0, o1;
    o0.x = (x0.x - mu) * r * ga.x + ba.x;
    o0.y = (x0.y - mu) * r * ga.y + ba.y;
    o0.z = (x0.z - mu) * r * ga.z + ba.z;
    o0.w = (x0.w - mu) * r * ga.w + ba.w;
    o1.x = (x1.x - mu) * r * gb.x + bb.x;
    o1.y = (x1.y - mu) * r * gb.y + bb.y;
    o1.z = (x1.z - mu) * r * gb.z + bb.z;
    o1.w = (x1.w - mu) * r * gb.w + bb.w;
    ((float4*)hn)[v * 64 + lane] = o0;
    ((float4*)hn)[v * 64 + 32 + lane] = o1;
}

// ---------------- tensor-core GEMM helpers ----------------
__device__ __forceinline__ unsigned int pack_hi(float a, float b) {
    unsigned short ha = __bfloat16_as_ushort(__float2bfloat16(a));
    unsigned short hb = __bfloat16_as_ushort(__float2bfloat16(b));
    return (unsigned int)ha | ((unsigned int)hb << 16);
}

__device__ __forceinline__ unsigned int pack_lo(float a, float b) {
    float ra = a - __bfloat162float(__float2bfloat16(a));
    float rb = b - __bfloat162float(__float2bfloat16(b));
    unsigned short la = __bfloat16_as_ushort(__float2bfloat16(ra));
    unsigned short lb = __bfloat16_as_ushort(__float2bfloat16(rb));
    return (unsigned int)la | ((unsigned int)lb << 16);
}

__device__ __forceinline__ void ldsm_x4(unsigned int* r, unsigned int addr) {
    asm volatile("ldmatrix.sync.aligned.m8n8.x4.shared.b16 {%0,%1,%2,%3}, [%4];"
                 : "=r"(r[0]), "=r"(r[1]), "=r"(r[2]), "=r"(r[3]) : "r"(addr));
}

__device__ __forceinline__ void ldsm_x4t(unsigned int* r, unsigned int addr) {
    asm volatile("ldmatrix.sync.aligned.m8n8.x4.trans.shared.b16 {%0,%1,%2,%3}, [%4];"
                 : "=r"(r[0]), "=r"(r[1]), "=r"(r[2]), "=r"(r[3]) : "r"(addr));
}

__device__ __forceinline__ void mma_bf16(float* c, const unsigned int* a,
                                         const unsigned int* b) {
    asm volatile(
        "mma.sync.aligned.m16n8k16.row.col.f32.bf16.bf16.f32 "
        "{%0,%1,%2,%3}, {%4,%5,%6,%7}, {%8,%9}, {%0,%1,%2,%3};"
        : "+f"(c[0]), "+f"(c[1]), "+f"(c[2]), "+f"(c[3])
        : "r"(a[0]), "r"(a[1]), "r"(a[2]), "r"(a[3]), "r"(b[0]), "r"(b[1]));
}

__device__ __forceinline__ void g_load(const float* __restrict__ A,
                                       const float* __restrict__ Bg,
                                       int bm, int bn_l, int M, int K, int ldb,
                                       int tid, int kk, float4* rA, float4* rB) {
#pragma unroll
    for (int u = 0; u < 4; u++) {
        int s = tid + u * 256;
        int am = s >> 3;
        int ak = (s & 7) << 2;
        int gr = bm + am;
        if (gr < M) rA[u] = *(const float4*)(A + (size_t)gr * K + kk + ak);
        else rA[u] = make_float4(0.f, 0.f, 0.f, 0.f);
        int bk = s >> 5;
        int bq = (s & 31) << 2;
        rB[u] = *(const float4*)(Bg + (size_t)(kk + bk) * ldb + bn_l + bq);
    }
}

__device__ __forceinline__ void s_store(char* st, int tid,
                                        const float4* rA, const float4* rB) {
    unsigned int* Ah = (unsigned int*)(st + AH_OFF);
    unsigned int* Al = (unsigned int*)(st + AL_OFF);
    unsigned int* Bh = (unsigned int*)(st + BH_OFF);
    unsigned int* Bl = (unsigned int*)(st + BL_OFF);
#pragma unroll
    for (int u = 0; u < 4; u++) {
        int s = tid + u * 256;
        int am = s >> 3;
        int aw = (s & 7) << 1;
        uint2 hv, lv;
        hv.x = pack_hi(rA[u].x, rA[u].y);
        hv.y = pack_hi(rA[u].z, rA[u].w);
        lv.x = pack_lo(rA[u].x, rA[u].y);
        lv.y = pack_lo(rA[u].z, rA[u].w);
        *(uint2*)(Ah + am * 20 + aw) = hv;
        *(uint2*)(Al + am * 20 + aw) = lv;
        int bk = s >> 5;
        int bw = (s & 31) << 1;
        hv.x = pack_hi(rB[u].x, rB[u].y);
        hv.y = pack_hi(rB[u].z, rB[u].w);
        lv.x = pack_lo(rB[u].x, rB[u].y);
        lv.y = pack_lo(rB[u].z, rB[u].w);
        *(uint2*)(Bh + bk * 68 + bw) = hv;
        *(uint2*)(Bl + bk * 68 + bw) = lv;
    }
}

__device__ __forceinline__ void tile_mma(unsigned int stg, int wm0, int wn0,
                                         int aRow, int aKof, int bRow, int bNof,
                                         float acc[4][4][4]) {
#pragma unroll
    for (int ks = 0; ks < 32; ks += 16) {
        unsigned int ah[4][4];
        unsigned int al[4][4];
        unsigned int bh[4][2];
        unsigned int bl[4][2];
#pragma unroll
        for (int mi = 0; mi < 4; mi++) {
            unsigned int ad = stg + AH_OFF
                + (unsigned int)((wm0 + mi * 16 + aRow) * 40 + ks + aKof) * 2u;
            ldsm_x4(ah[mi], ad);
            ldsm_x4(al[mi], ad + (AL_OFF - AH_OFF));
        }
#pragma unroll
        for (int np = 0; np < 2; np++) {
            unsigned int bd = stg + BH_OFF
                + (unsigned int)((ks + bRow) * 136 + wn0 + np * 16 + bNof) * 2u;
            unsigned int tb[4];
            ldsm_x4t(tb, bd);
            bh[np * 2][0] = tb[0];
            bh[np * 2][1] = tb[1];
            bh[np * 2 + 1][0] = tb[2];
            bh[np * 2 + 1][1] = tb[3];
            ldsm_x4t(tb, bd + (BL_OFF - BH_OFF));
            bl[np * 2][0] = tb[0];
            bl[np * 2][1] = tb[1];
            bl[np * 2 + 1][0] = tb[2];
            bl[np * 2 + 1][1] = tb[3];
        }
#pragma unroll
        for (int mi = 0; mi < 4; mi++) {
#pragma unroll
            for (int ni = 0; ni < 4; ni++) {
                mma_bf16(acc[mi][ni], ah[mi], bh[ni]);
                mma_bf16(acc[mi][ni], ah[mi], bl[ni]);
                mma_bf16(acc[mi][ni], al[mi], bh[ni]);
            }
        }
    }
}

// C[M, 0..511] = epi(A @ [B0|B1]); B split at col 256. EPI 0:+bias 1:bn+lrelu 2:lrelu
template <int EPI>
__global__ __launch_bounds__(256) void k_gemm_tc(
    const float* __restrict__ A, const float* __restrict__ B0,
    const float* __restrict__ B1, const float* __restrict__ bias0,
    const float* __restrict__ bias1, const float* __restrict__ bng,
    const float* __restrict__ bnb, float* __restrict__ C,
    int M, int K, int ldb, int ldc) {
    extern __shared__ char smem[];
    const int tid = threadIdx.x;
    const int lane = tid & 31;
    const int wid = tid >> 5;
    const int bm = blockIdx.y * 128;
    const int bn = blockIdx.x * 128;
    const float* Bg = (bn < 256) ? B0 : B1;
    const float* biasp = (bn < 256) ? bias0 : bias1;
    const int bn_l = bn & 255;
    const int wm0 = (wid & 1) * 64;
    const int wn0 = (wid >> 1) * 32;
    unsigned int sbase = (unsigned int)__cvta_generic_to_shared(smem);

    float acc[4][4][4];
#pragma unroll
    for (int i = 0; i < 4; i++) {
#pragma unroll
        for (int j = 0; j < 4; j++) {
#pragma unroll
            for (int k = 0; k < 4; k++) acc[i][j][k] = 0.f;
        }
    }

    const int grp = lane & 7;
    const int seg = lane >> 3;
    const int aRow = (seg & 1) * 8 + grp;
    const int aKof = (seg >> 1) * 8;
    const int bRow = (seg & 1) * 8 + grp;
    const int bNof = (seg >> 1) * 8;

    float4 rA[4];
    float4 rB[4];
    g_load(A, Bg, bm, bn_l, M, K, ldb, tid, 0, rA, rB);
    s_store(smem, tid, rA, rB);
    __syncthreads();

    int nk = K / 32;
    for (int t = 0; t < nk; t++) {
        if (t + 1 < nk) g_load(A, Bg, bm, bn_l, M, K, ldb, tid, (t + 1) * 32, rA, rB);
        unsigned int stg = sbase + (unsigned int)(t & 1) * STAGE_BYTES;
        tile_mma(stg, wm0, wn0, aRow, aKof, bRow, bNof, acc);
        if (t + 1 < nk) s_store(smem + ((t & 1) ^ 1) * STAGE_BYTES, tid, rA, rB);
        __syncthreads();
    }

    const float rsb = rsqrtf(1.0f + EPSF);
    const int cg = lane >> 2;
    const int cc = lane & 3;
#pragma unroll
    for (int mi = 0; mi < 4; mi++) {
        int r0 = bm + wm0 + mi * 16 + cg;
#pragma unroll
        for (int ni = 0; ni < 4; ni++) {
            int colL = wn0 + ni * 8 + 2 * cc;
            int colB = bn_l + colL;
            float b0v = __ldg(&biasp[colB]);
            float b1v = __ldg(&biasp[colB + 1]);
            float v0 = acc[mi][ni][0] + b0v;
            float v1 = acc[mi][ni][1] + b1v;
            float v2 = acc[mi][ni][2] + b0v;
            float v3 = acc[mi][ni][3] + b1v;
            if (EPI == 1) {
                float g0 = __ldg(&bng[colB]);
                float g1 = __ldg(&bng[colB + 1]);
                float q0 = __ldg(&bnb[colB]);
                float q1 = __ldg(&bnb[colB + 1]);
                v0 = lrelu(v0 * rsb * g0 + q0, 0.1f);
                v1 = lrelu(v1 * rsb * g1 + q1, 0.1f);
                v2 = lrelu(v2 * rsb * g0 + q0, 0.1f);
                v3 = lrelu(v3 * rsb * g1 + q1, 0.1f);
            }
            if (EPI == 2) {
                v0 = lrelu(v0, 0.1f);
                v1 = lrelu(v1, 0.1f);
                v2 = lrelu(v2, 0.1f);
                v3 = lrelu(v3, 0.1f);
            }
            int col = bn + colL;
            if (r0 < M) *(float2*)(C + (size_t)r0 * ldc + col) = make_float2(v0, v1);
            if (r0 + 8 < M) *(float2*)(C + (size_t)(r0 + 8) * ldc + col) = make_float2(v2, v3);
        }
    }
}

// ---------------- GATv2 aggregation: one warp per node, online softmax ----------------
__global__ __launch_bounds__(256) void k_gat(
    const float* __restrict__ xlxr, const int* __restrict__ rowptr,
    const int* __restrict__ csrsrc, const float* __restrict__ att,
    const float* __restrict__ convb, const float* __restrict__ scales,
    const float* __restrict__ wvec, int li,
    float* __restrict__ h, float* __restrict__ hsum) {
    int v = (int)((blockIdx.x * blockDim.x + threadIdx.x) >> 5);
    if (v >= NN) return;
    int lane = threadIdx.x & 31;
    const float4* x4 = (const float4*)xlxr;
    const float4* att4 = (const float4*)att;
    int hA = lane >> 3;
    float4 aA = __ldg(&att4[hA * 8 + (lane & 7)]);
    float4 aB = __ldg(&att4[(hA + 4) * 8 + (lane & 7)]);
    int vb = v * 128;
    float4 xrA = __ldg(&x4[vb + 64 + lane]);
    float4 xrB = __ldg(&x4[vb + 96 + lane]);
    float mA = -1e30f;
    float mB = -1e30f;
    float dA = 0.f;
    float dB = 0.f;
    float4 accA = make_float4(0.f, 0.f, 0.f, 0.f);
    float4 accB = make_float4(0.f, 0.f, 0.f, 0.f);
    int e1 = __ldg(&rowptr[v + 1]);
    for (int e = __ldg(&rowptr[v]); e < e1; e++) {
        int s = __ldg(&csrsrc[e]);
        int sb = s * 128;
        float4 xlA = __ldg(&x4[sb + lane]);
        float4 xlB = __ldg(&x4[sb + 32 + lane]);
        float pA = lrelu(xlA.x + xrA.x, 0.2f) * aA.x
                 + lrelu(xlA.y + xrA.y, 0.2f) * aA.y
                 + lrelu(xlA.z + xrA.z, 0.2f) * aA.z
                 + lrelu(xlA.w + xrA.w, 0.2f) * aA.w;
        float pB = lrelu(xlB.x + xrB.x, 0.2f) * aB.x
                 + lrelu(xlB.y + xrB.y, 0.2f) * aB.y
                 + lrelu(xlB.z + xrB.z, 0.2f) * aB.z
                 + lrelu(xlB.w + xrB.w, 0.2f) * aB.w;
        pA += __shfl_xor_sync(0xffffffffu, pA, 1);
        pB += __shfl_xor_sync(0xffffffffu, pB, 1);
        pA += __shfl_xor_sync(0xffffffffu, pA, 2);
        pB += __shfl_xor_sync(0xffffffffu, pB, 2);
        pA += __shfl_xor_sync(0xffffffffu, pA, 4);
        pB += __shfl_xor_sync(0xffffffffu, pB, 4);
        float nmA = fmaxf(mA, pA);
        float scA = __expf(mA - nmA);
        float epA = __expf(pA - nmA);
        dA = dA * scA + epA;
        accA.x = accA.x * scA + xlA.x * epA;
        accA.y = accA.y * scA + xlA.y * epA;
        accA.z = accA.z * scA + xlA.z * epA;
        accA.w = accA.w * scA + xlA.w * epA;
        mA = nmA;
        float nmB = fmaxf(mB, pB);
        float scB = __expf(mB - nmB);
        float epB = __expf(pB - nmB);
        dB = dB * scB + epB;
        accB.x = accB.x * scB + xlB.x * epB;
        accB.y = accB.y * scB + xlB.y * epB;
        accB.z = accB.z * scB + xlB.z * epB;
        accB.w = accB.w * scB + xlB.w * epB;
        mB = nmB;
    }
    const float4* cb4 = (const float4*)convb;
    float4 cbA = __ldg(&cb4[lane]);
    float4 cbB = __ldg(&cb4[lane + 32]);
    float sci = __ldg(&scales[li]);
    float wi = __ldg(&wvec[li]);
    float4* h4 = (float4*)h;
    float4 rA = h4[v * 64 + lane];
    float4 rB = h4[v * 64 + 32 + lane];
    float idA = 1.0f / dA;
    float idB = 1.0f / dB;
    float4 hnA, hnB;
    hnA.x = rA.x + sci * lrelu(accA.x * idA + cbA.x, 0.1f);
    hnA.y = rA.y + sci * lrelu(accA.y * idA + cbA.y, 0.1f);
    hnA.z = rA.z + sci * lrelu(accA.z * idA + cbA.z, 0.1f);
    hnA.w = rA.w + sci * lrelu(accA.w * idA + cbA.w, 0.1f);
    hnB.x = rB.x + sci * lrelu(accB.x * idB + cbB.x, 0.1f);
    hnB.y = rB.y + sci * lrelu(accB.y * idB + cbB.y, 0.1f);
    hnB.z = rB.z + sci * lrelu(accB.z * idB + cbB.z, 0.1f);
    hnB.w = rB.w + sci * lrelu(accB.w * idB + cbB.w, 0.1f);
    h4[v * 64 + lane] = hnA;
    h4[v * 64 + 32 + lane] = hnB;
    float4* hs4 = (float4*)hsum;
    float4 sa, sb;
    if (li == 0) {
        sa = make_float4(0.f, 0.f, 0.f, 0.f);
        sb = make_float4(0.f, 0.f, 0.f, 0.f);
    } else {
        sa = hs4[v * 64 + lane];
        sb = hs4[v * 64 + 32 + lane];
    }
    sa.x += wi * hnA.x;
    sa.y += wi * hnA.y;
    sa.z += wi * hnA.z;
    sa.w += wi * hnA.w;
    sb.x += wi * hnB.x;
    sb.y += wi * hnB.y;
    sb.z += wi * hnB.z;
    sb.w += wi * hnB.w;
    hs4[v * 64 + lane] = sa;
    hs4[v * 64 + 32 + lane] = sb;
}

// ---------------- final projection ----------------
__global__ __launch_bounds__(256) void k_final(
    const float* __restrict__ y2, const float* __restrict__ w,
    const float* __restrict__ b, float* __restrict__ out) {
    int v = (int)((blockIdx.x * blockDim.x + threadIdx.x) >> 5);
    if (v >= NN) return;
    int lane = threadIdx.x & 31;
    const float4* y4 = (const float4*)y2;
    const float4* w4 = (const float4*)w;
    float4 a = y4[v * 32 + lane];
    float4 ww = __ldg(&w4[lane]);
    float p = a.x * ww.x + a.y * ww.y + a.z * ww.z + a.w * ww.w;
    for (int d = 16; d; d >>= 1) p += __shfl_xor_sync(0xffffffffu, p, d);
    if (lane == 0) out[v] = p + __ldg(&b[0]);
}

// ---------------- launcher ----------------
extern "C" void kernel_launch(void* const* d_in, const int* in_sizes, int n_in,
                              void* d_out, int out_size) {
    (void)in_sizes; (void)n_in; (void)out_size;
    const float* x      = (const float*)d_in[0];
    const int*   ei     = (const int*)d_in[1];
    const float* win_w  = (const float*)d_in[2];
    const float* win_b  = (const float*)d_in[3];
    const float* bn1_g  = (const float*)d_in[4];
    const float* bn1_b  = (const float*)d_in[5];
    const float* ln_g   = (const float*)d_in[6];
    const float* ln_b   = (const float*)d_in[7];
    const float* Wl     = (const float*)d_in[8];
    const float* bl     = (const float*)d_in[9];
    const float* Wr     = (const float*)d_in[10];
    const float* br     = (const float*)d_in[11];
    const float* att    = (const float*)d_in[12];
    const float* conv_b = (const float*)d_in[13];
    const float* scales = (const float*)d_in[14];
    const float* sw     = (const float*)d_in[15];
    const float* h1_w   = (const float*)d_in[16];
    const float* h1_b   = (const float*)d_in[17];
    const float* bn2_g  = (const float*)d_in[18];
    const float* bn2_b  = (const float*)d_in[19];
    const float* h2_w   = (const float*)d_in[20];
    const float* h2_b   = (const float*)d_in[21];
    const float* h3_w   = (const float*)d_in[22];
    const float* h3_b   = (const float*)d_in[23];
    float* out = (float*)d_out;

    float *p_h, *p_hn, *p_xlxr, *p_hsum, *p_y1, *p_y2, *p_w;
    int *p_rowptr, *p_deg, *p_bsum, *p_cursor, *p_csr;
    cudaGetSymbolAddress((void**)&p_h, d_h);
    cudaGetSymbolAddress((void**)&p_hn, d_hn);
    cudaGetSymbolAddress((void**)&p_xlxr, d_xlxr);
    cudaGetSymbolAddress((void**)&p_hsum, d_hsum);
    cudaGetSymbolAddress((void**)&p_y1, d_y1);
    cudaGetSymbolAddress((void**)&p_y2, d_y2);
    cudaGetSymbolAddress((void**)&p_w, d_w);
    cudaGetSymbolAddress((void**)&p_rowptr, d_rowptr);
    cudaGetSymbolAddress((void**)&p_deg, d_deg);
    cudaGetSymbolAddress((void**)&p_bsum, d_bsum);
    cudaGetSymbolAddress((void**)&p_cursor, d_cursor);
    cudaGetSymbolAddress((void**)&p_csr, d_csrsrc);

    cudaFuncSetAttribute(k_gemm_tc<0>, cudaFuncAttributeMaxDynamicSharedMemorySize,
                         2 * STAGE_BYTES);
    cudaFuncSetAttribute(k_gemm_tc<1>, cudaFuncAttributeMaxDynamicSharedMemorySize,
                         2 * STAGE_BYTES);
    cudaFuncSetAttribute(k_gemm_tc<2>, cudaFuncAttributeMaxDynamicSharedMemorySize,
                         2 * STAGE_BYTES);

    const int* e_src = ei;
    const int* e_dst = ei + EE;

    k_softmax_w<<<1, 32>>>(sw, p_w);

    k_deg_init<<<(NN + 255) / 256, 256>>>(p_deg);
    k_deg_count<<<(EE + 255) / 256, 256>>>(e_dst, p_deg);
    k_blocksum<<<NB, 256>>>(p_deg, p_bsum);
    k_bscan<<<1, 256>>>(p_bsum);
    k_scanout<<<NB, 256>>>(p_deg, p_bsum, p_rowptr);
    k_selfloop<<<(NN + 255) / 256, 256>>>(p_rowptr, p_cursor, p_csr);
    k_scatter<<<(EE + 255) / 256, 256>>>(e_src, e_dst, p_cursor, p_csr);

    const int warpBlocks = (NN * 32 + 255) / 256;
    const int smemB = 2 * STAGE_BYTES;

    {
        dim3 g(2, (NN + 127) / 128);
        k_gemm_tc<1><<<g, 256, smemB>>>(x, win_w, win_w, win_b, win_b,
                                        bn1_g, bn1_b, p_h, NN, IND, DD, DD);
    }

    for (int i = 0; i < LL; i++) {
        k_layernorm<<<warpBlocks, 256>>>(p_h, ln_g + i * DD, ln_b + i * DD, p_hn);
        dim3 g(4, (NN + 127) / 128);
        k_gemm_tc<0><<<g, 256, smemB>>>(p_hn, Wl + (size_t)i * DD * DD,
                                        Wr + (size_t)i * DD * DD,
                                        bl + i * DD, br + i * DD,
                                        NULL, NULL, p_xlxr, NN, DD, DD, 2 * DD);
        k_gat<<<warpBlocks, 256>>>(p_xlxr, p_rowptr, p_csr, att + i * DD,
                                   conv_b + i * DD, scales, p_w, i, p_h, p_hsum);
    }

    {
        dim3 g(2, (NN + 127) / 128);
        k_gemm_tc<1><<<g, 256, smemB>>>(p_hsum, h1_w, h1_w, h1_b, h1_b,
                                        bn2_g, bn2_b, p_y1, NN, DD, DD, DD);
        dim3 g2(1, (NN + 127) / 128);
        k_gemm_tc<2><<<g2, 256, smemB>>>(p_y1, h2_w, h2_w, h2_b, h2_b,
                                         NULL, NULL, p_y2, NN, DD, DD / 2, DD / 2);
    }
    k_final<<<warpBlocks, 256>>>(p_y2, h3_w, h3_b, out);
}

// round 4
// speedup vs baseline: 1.8959x; 1.0621x over previous
#include <cuda_runtime.h>
#include <cuda_bf16.h>
#include <cuda_fp16.h>
#include <stdint.h>
#include <math.h>

#define NN 50000
#define EE 800000
#define IND 128
#define DD 256
#define LL 6
#define EPSF 1e-5f
#define NB 196

// smem stage layout (bytes)
#define AH_OFF 0
#define AL_OFF 10240
#define BH_OFF 20480
#define BL_OFF 29184
#define STAGE_BYTES 37888

// ---------------- scratch ----------------
__device__ __align__(16) float  d_h[(size_t)NN * DD];
__device__ __align__(16) float  d_hn[(size_t)NN * DD];
__device__ __align__(16) __half d_xl[(size_t)NN * DD];   // 25.6 MB, L2-resident gather set
__device__ __align__(16) float  d_xr[(size_t)NN * DD];
__device__ __align__(16) float  d_hsum[(size_t)NN * DD];
__device__ __align__(16) float  d_y1[(size_t)NN * DD];
__device__ __align__(16) float  d_y2[(size_t)NN * (DD / 2)];
__device__ int   d_rowptr[NN + 1];
__device__ int   d_deg[NN];
__device__ int   d_bsum[NB];
__device__ int   d_cursor[NN];
__device__ int   d_csrsrc[EE + NN];
__device__ float d_w[LL];

__device__ __forceinline__ float lrelu(float x, float a) { return x > 0.f ? x : a * x; }

// ---------------- tiny kernels ----------------
__global__ void k_softmax_w(const float* __restrict__ sw, float* __restrict__ w) {
    if (threadIdx.x == 0 && blockIdx.x == 0) {
        float m = -1e30f;
        for (int i = 0; i < LL; i++) m = fmaxf(m, sw[i]);
        float e[LL];
        float s = 0.f;
        for (int i = 0; i < LL; i++) { e[i] = __expf(sw[i] - m); s += e[i]; }
        for (int i = 0; i < LL; i++) w[i] = e[i] / s;
    }
}

__global__ void k_deg_init(int* __restrict__ deg) {
    int i = blockIdx.x * blockDim.x + threadIdx.x;
    if (i < NN) deg[i] = 1;
}

__global__ void k_deg_count(const int* __restrict__ dst, int* __restrict__ deg) {
    int i = blockIdx.x * blockDim.x + threadIdx.x;
    if (i < EE) atomicAdd(&deg[dst[i]], 1);
}

__global__ void k_blocksum(const int* __restrict__ deg, int* __restrict__ bsum) {
    int i = blockIdx.x * 256 + threadIdx.x;
    int v = (i < NN) ? deg[i] : 0;
    int lane = threadIdx.x & 31;
    int wid = threadIdx.x >> 5;
    for (int d = 16; d; d >>= 1) v += __shfl_xor_sync(0xffffffffu, v, d);
    __shared__ int ws[8];
    if (lane == 0) ws[wid] = v;
    __syncthreads();
    if (threadIdx.x == 0) {
        int s = 0;
        for (int k = 0; k < 8; k++) s += ws[k];
        bsum[blockIdx.x] = s;
    }
}

__global__ void k_bscan(int* __restrict__ bsum) {
    int t = threadIdx.x;
    int v = (t < NB) ? bsum[t] : 0;
    int lane = t & 31;
    int wid = t >> 5;
    int x = v;
    for (int d = 1; d < 32; d <<= 1) {
        int u = __shfl_up_sync(0xffffffffu, x, d);
        if (lane >= d) x += u;
    }
    __shared__ int ws[8];
    if (lane == 31) ws[wid] = x;
    __syncthreads();
    if (wid == 0 && lane < 8) {
        int y = ws[lane];
        for (int d = 1; d < 8; d <<= 1) {
            int u = __shfl_up_sync(0xffu, y, d);
            if (lane >= d) y += u;
        }
        ws[lane] = y;
    }
    __syncthreads();
    int incl = x + (wid > 0 ? ws[wid - 1] : 0);
    if (t < NB) bsum[t] = incl - v;
}

__global__ void k_scanout(const int* __restrict__ deg, const int* __restrict__ boff,
                          int* __restrict__ rowptr) {
    int t = threadIdx.x;
    int i = blockIdx.x * 256 + t;
    int v = (i < NN) ? deg[i] : 0;
    int lane = t & 31;
    int wid = t >> 5;
    int x = v;
    for (int d = 1; d < 32; d <<= 1) {
        int u = __shfl_up_sync(0xffffffffu, x, d);
        if (lane >= d) x += u;
    }
    __shared__ int ws[8];
    if (lane == 31) ws[wid] = x;
    __syncthreads();
    if (wid == 0 && lane < 8) {
        int y = ws[lane];
        for (int d = 1; d < 8; d <<= 1) {
            int u = __shfl_up_sync(0xffu, y, d);
            if (lane >= d) y += u;
        }
        ws[lane] = y;
    }
    __syncthreads();
    int excl = x - v + (wid > 0 ? ws[wid - 1] : 0) + boff[blockIdx.x];
    if (i < NN) rowptr[i] = excl;
    if (i == 0) rowptr[NN] = EE + NN;
}

__global__ void k_selfloop(const int* __restrict__ rowptr, int* __restrict__ cursor,
                           int* __restrict__ csrsrc) {
    int v = blockIdx.x * blockDim.x + threadIdx.x;
    if (v < NN) {
        int p = rowptr[v];
        csrsrc[p] = v;
        cursor[v] = p + 1;
    }
}

__global__ void k_scatter(const int* __restrict__ src, const int* __restrict__ dst,
                          int* __restrict__ cursor, int* __restrict__ csrsrc) {
    int i = blockIdx.x * blockDim.x + threadIdx.x;
    if (i < EE) {
        int p = atomicAdd(&cursor[dst[i]], 1);
        csrsrc[p] = src[i];
    }
}

// ---------------- layernorm (only for layer 0 input) ----------------
__global__ __launch_bounds__(256) void k_layernorm(
    const float* __restrict__ h, const float* __restrict__ g,
    const float* __restrict__ b, float* __restrict__ hn) {
    int v = (int)((blockIdx.x * blockDim.x + threadIdx.x) >> 5);
    if (v >= NN) return;
    int lane = threadIdx.x & 31;
    const float4* h4 = (const float4*)h;
    float4 x0 = h4[v * 64 + lane];
    float4 x1 = h4[v * 64 + 32 + lane];
    float s = x0.x + x0.y + x0.z + x0.w + x1.x + x1.y + x1.z + x1.w;
    float q = x0.x * x0.x + x0.y * x0.y + x0.z * x0.z + x0.w * x0.w
            + x1.x * x1.x + x1.y * x1.y + x1.z * x1.z + x1.w * x1.w;
    for (int d = 16; d; d >>= 1) {
        s += __shfl_xor_sync(0xffffffffu, s, d);
        q += __shfl_xor_sync(0xffffffffu, q, d);
    }
    float mu = s * (1.0f / 256.0f);
    float var = q * (1.0f / 256.0f) - mu * mu;
    float r = rsqrtf(var + EPSF);
    const float4* g4 = (const float4*)g;
    const float4* b4 = (const float4*)b;
    float4 ga = __ldg(&g4[lane]);
    float4 gb = __ldg(&g4[lane + 32]);
    float4 ba = __ldg(&b4[lane]);
    float4 bb = __ldg(&b4[lane + 32]);
    float4 o0, o1;
    o0.x = (x0.x - mu) * r * ga.x + ba.x;
    o0.y = (x0.y - mu) * r * ga.y + ba.y;
    o0.z = (x0.z - mu) * r * ga.z + ba.z;
    o0.w = (x0.w - mu) * r * ga.w + ba.w;
    o1.x = (x1.x - mu) * r * gb.x + bb.x;
    o1.y = (x1.y - mu) * r * gb.y + bb.y;
    o1.z = (x1.z - mu) * r * gb.z + bb.z;
    o1.w = (x1.w - mu) * r * gb.w + bb.w;
    ((float4*)hn)[v * 64 + lane] = o0;
    ((float4*)hn)[v * 64 + 32 + lane] = o1;
}

// ---------------- tensor-core GEMM helpers ----------------
__device__ __forceinline__ unsigned int pack_hi(float a, float b) {
    unsigned short ha = __bfloat16_as_ushort(__float2bfloat16(a));
    unsigned short hb = __bfloat16_as_ushort(__float2bfloat16(b));
    return (unsigned int)ha | ((unsigned int)hb << 16);
}

__device__ __forceinline__ unsigned int pack_lo(float a, float b) {
    float ra = a - __bfloat162float(__float2bfloat16(a));
    float rb = b - __bfloat162float(__float2bfloat16(b));
    unsigned short la = __bfloat16_as_ushort(__float2bfloat16(ra));
    unsigned short lb = __bfloat16_as_ushort(__float2bfloat16(rb));
    return (unsigned int)la | ((unsigned int)lb << 16);
}

__device__ __forceinline__ void ldsm_x4(unsigned int* r, unsigned int addr) {
    asm volatile("ldmatrix.sync.aligned.m8n8.x4.shared.b16 {%0,%1,%2,%3}, [%4];"
                 : "=r"(r[0]), "=r"(r[1]), "=r"(r[2]), "=r"(r[3]) : "r"(addr));
}

__device__ __forceinline__ void ldsm_x4t(unsigned int* r, unsigned int addr) {
    asm volatile("ldmatrix.sync.aligned.m8n8.x4.trans.shared.b16 {%0,%1,%2,%3}, [%4];"
                 : "=r"(r[0]), "=r"(r[1]), "=r"(r[2]), "=r"(r[3]) : "r"(addr));
}

__device__ __forceinline__ void mma_bf16(float* c, const unsigned int* a,
                                         const unsigned int* b) {
    asm volatile(
        "mma.sync.aligned.m16n8k16.row.col.f32.bf16.bf16.f32 "
        "{%0,%1,%2,%3}, {%4,%5,%6,%7}, {%8,%9}, {%0,%1,%2,%3};"
        : "+f"(c[0]), "+f"(c[1]), "+f"(c[2]), "+f"(c[3])
        : "r"(a[0]), "r"(a[1]), "r"(a[2]), "r"(a[3]), "r"(b[0]), "r"(b[1]));
}

__device__ __forceinline__ void g_load(const float* __restrict__ A,
                                       const float* __restrict__ Bg,
                                       int bm, int bn_l, int M, int K, int ldb,
                                       int tid, int kk, float4* rA, float4* rB) {
#pragma unroll
    for (int u = 0; u < 4; u++) {
        int s = tid + u * 256;
        int am = s >> 3;
        int ak = (s & 7) << 2;
        int gr = bm + am;
        if (gr < M) rA[u] = *(const float4*)(A + (size_t)gr * K + kk + ak);
        else rA[u] = make_float4(0.f, 0.f, 0.f, 0.f);
        int bk = s >> 5;
        int bq = (s & 31) << 2;
        rB[u] = *(const float4*)(Bg + (size_t)(kk + bk) * ldb + bn_l + bq);
    }
}

__device__ __forceinline__ void s_store(char* st, int tid,
                                        const float4* rA, const float4* rB) {
    unsigned int* Ah = (unsigned int*)(st + AH_OFF);
    unsigned int* Al = (unsigned int*)(st + AL_OFF);
    unsigned int* Bh = (unsigned int*)(st + BH_OFF);
    unsigned int* Bl = (unsigned int*)(st + BL_OFF);
#pragma unroll
    for (int u = 0; u < 4; u++) {
        int s = tid + u * 256;
        int am = s >> 3;
        int aw = (s & 7) << 1;
        uint2 hv, lv;
        hv.x = pack_hi(rA[u].x, rA[u].y);
        hv.y = pack_hi(rA[u].z, rA[u].w);
        lv.x = pack_lo(rA[u].x, rA[u].y);
        lv.y = pack_lo(rA[u].z, rA[u].w);
        *(uint2*)(Ah + am * 20 + aw) = hv;
        *(uint2*)(Al + am * 20 + aw) = lv;
        int bk = s >> 5;
        int bw = (s & 31) << 1;
        hv.x = pack_hi(rB[u].x, rB[u].y);
        hv.y = pack_hi(rB[u].z, rB[u].w);
        lv.x = pack_lo(rB[u].x, rB[u].y);
        lv.y = pack_lo(rB[u].z, rB[u].w);
        *(uint2*)(Bh + bk * 68 + bw) = hv;
        *(uint2*)(Bl + bk * 68 + bw) = lv;
    }
}

__device__ __forceinline__ void tile_mma(unsigned int stg, int wm0, int wn0,
                                         int aRow, int aKof, int bRow, int bNof,
                                         float acc[4][4][4]) {
#pragma unroll
    for (int ks = 0; ks < 32; ks += 16) {
        unsigned int ah[4][4];
        unsigned int al[4][4];
        unsigned int bh[4][2];
        unsigned int bl[4][2];
#pragma unroll
        for (int mi = 0; mi < 4; mi++) {
            unsigned int ad = stg + AH_OFF
                + (unsigned int)((wm0 + mi * 16 + aRow) * 40 + ks + aKof) * 2u;
            ldsm_x4(ah[mi], ad);
            ldsm_x4(al[mi], ad + (AL_OFF - AH_OFF));
        }
#pragma unroll
        for (int np = 0; np < 2; np++) {
            unsigned int bd = stg + BH_OFF
                + (unsigned int)((ks + bRow) * 136 + wn0 + np * 16 + bNof) * 2u;
            unsigned int tb[4];
            ldsm_x4t(tb, bd);
            bh[np * 2][0] = tb[0];
            bh[np * 2][1] = tb[1];
            bh[np * 2 + 1][0] = tb[2];
            bh[np * 2 + 1][1] = tb[3];
            ldsm_x4t(tb, bd + (BL_OFF - BH_OFF));
            bl[np * 2][0] = tb[0];
            bl[np * 2][1] = tb[1];
            bl[np * 2 + 1][0] = tb[2];
            bl[np * 2 + 1][1] = tb[3];
        }
#pragma unroll
        for (int mi = 0; mi < 4; mi++) {
#pragma unroll
            for (int ni = 0; ni < 4; ni++) {
                mma_bf16(acc[mi][ni], ah[mi], bh[ni]);
                mma_bf16(acc[mi][ni], ah[mi], bl[ni]);
                mma_bf16(acc[mi][ni], al[mi], bh[ni]);
            }
        }
    }
}

// EPI 0: fused Wl|Wr -> xl(half, cols<256) / xr(float, cols>=256), +bias
// EPI 1: bn_eval + lrelu(0.1) -> C ; EPI 2: lrelu(0.1) -> C
template <int EPI>
__global__ __launch_bounds__(256) void k_gemm_tc(
    const float* __restrict__ A, const float* __restrict__ B0,
    const float* __restrict__ B1, const float* __restrict__ bias0,
    const float* __restrict__ bias1, const float* __restrict__ bng,
    const float* __restrict__ bnb, float* __restrict__ C,
    __half* __restrict__ Cxl, float* __restrict__ Cxr,
    int M, int K, int ldb, int ldc) {
    extern __shared__ char smem[];
    const int tid = threadIdx.x;
    const int lane = tid & 31;
    const int wid = tid >> 5;
    const int bm = blockIdx.y * 128;
    const int bn = blockIdx.x * 128;
    const float* Bg = (bn < 256) ? B0 : B1;
    const float* biasp = (bn < 256) ? bias0 : bias1;
    const int bn_l = bn & 255;
    const int wm0 = (wid & 1) * 64;
    const int wn0 = (wid >> 1) * 32;
    unsigned int sbase = (unsigned int)__cvta_generic_to_shared(smem);

    float acc[4][4][4];
#pragma unroll
    for (int i = 0; i < 4; i++) {
#pragma unroll
        for (int j = 0; j < 4; j++) {
#pragma unroll
            for (int k = 0; k < 4; k++) acc[i][j][k] = 0.f;
        }
    }

    const int grp = lane & 7;
    const int seg = lane >> 3;
    const int aRow = (seg & 1) * 8 + grp;
    const int aKof = (seg >> 1) * 8;
    const int bRow = (seg & 1) * 8 + grp;
    const int bNof = (seg >> 1) * 8;

    float4 rA[4];
    float4 rB[4];
    g_load(A, Bg, bm, bn_l, M, K, ldb, tid, 0, rA, rB);
    s_store(smem, tid, rA, rB);
    __syncthreads();

    int nk = K / 32;
    for (int t = 0; t < nk; t++) {
        if (t + 1 < nk) g_load(A, Bg, bm, bn_l, M, K, ldb, tid, (t + 1) * 32, rA, rB);
        unsigned int stg = sbase + (unsigned int)(t & 1) * STAGE_BYTES;
        tile_mma(stg, wm0, wn0, aRow, aKof, bRow, bNof, acc);
        if (t + 1 < nk) s_store(smem + ((t & 1) ^ 1) * STAGE_BYTES, tid, rA, rB);
        __syncthreads();
    }

    const float rsb = rsqrtf(1.0f + EPSF);
    const int cg = lane >> 2;
    const int cc = lane & 3;
#pragma unroll
    for (int mi = 0; mi < 4; mi++) {
        int r0 = bm + wm0 + mi * 16 + cg;
#pragma unroll
        for (int ni = 0; ni < 4; ni++) {
            int colL = wn0 + ni * 8 + 2 * cc;
            int colB = bn_l + colL;
            float b0v = __ldg(&biasp[colB]);
            float b1v = __ldg(&biasp[colB + 1]);
            float v0 = acc[mi][ni][0] + b0v;
            float v1 = acc[mi][ni][1] + b1v;
            float v2 = acc[mi][ni][2] + b0v;
            float v3 = acc[mi][ni][3] + b1v;
            if (EPI == 0) {
                if (bn < 256) {
                    if (r0 < M)
                        *(__half2*)(Cxl + (size_t)r0 * DD + colB) = __floats2half2_rn(v0, v1);
                    if (r0 + 8 < M)
                        *(__half2*)(Cxl + (size_t)(r0 + 8) * DD + colB) = __floats2half2_rn(v2, v3);
                } else {
                    if (r0 < M)
                        *(float2*)(Cxr + (size_t)r0 * DD + colB) = make_float2(v0, v1);
                    if (r0 + 8 < M)
                        *(float2*)(Cxr + (size_t)(r0 + 8) * DD + colB) = make_float2(v2, v3);
                }
            } else {
                if (EPI == 1) {
                    float g0 = __ldg(&bng[colB]);
                    float g1 = __ldg(&bng[colB + 1]);
                    float q0 = __ldg(&bnb[colB]);
                    float q1 = __ldg(&bnb[colB + 1]);
                    v0 = lrelu(v0 * rsb * g0 + q0, 0.1f);
                    v1 = lrelu(v1 * rsb * g1 + q1, 0.1f);
                    v2 = lrelu(v2 * rsb * g0 + q0, 0.1f);
                    v3 = lrelu(v3 * rsb * g1 + q1, 0.1f);
                }
                if (EPI == 2) {
                    v0 = lrelu(v0, 0.1f);
                    v1 = lrelu(v1, 0.1f);
                    v2 = lrelu(v2, 0.1f);
                    v3 = lrelu(v3, 0.1f);
                }
                int col = bn + colL;
                if (r0 < M) *(float2*)(C + (size_t)r0 * ldc + col) = make_float2(v0, v1);
                if (r0 + 8 < M) *(float2*)(C + (size_t)(r0 + 8) * ldc + col) = make_float2(v2, v3);
            }
        }
    }
}

// ---------------- GATv2 aggregation + residual + fused next-layer LN ----------------
// lane l holds channels [8l, 8l+8); head = l>>2; logit reduced over 4-lane groups.
__global__ __launch_bounds__(256) void k_gat(
    const __half* __restrict__ xl, const float* __restrict__ xr,
    const int* __restrict__ rowptr, const int* __restrict__ csrsrc,
    const float* __restrict__ att, const float* __restrict__ convb,
    const float* __restrict__ scales, const float* __restrict__ wvec, int li,
    float* __restrict__ h, float* __restrict__ hsum,
    const float* __restrict__ lng, const float* __restrict__ lnb,
    float* __restrict__ hn) {
    int v = (int)((blockIdx.x * blockDim.x + threadIdx.x) >> 5);
    if (v >= NN) return;
    int lane = threadIdx.x & 31;

    const float4* att4 = (const float4*)att;
    float4 a0 = __ldg(&att4[2 * lane]);
    float4 a1 = __ldg(&att4[2 * lane + 1]);
    const float4* xr4 = (const float4*)(xr + (size_t)v * DD);
    float4 r0 = __ldg(&xr4[2 * lane]);
    float4 r1 = __ldg(&xr4[2 * lane + 1]);

    float m = -1e30f;
    float den = 0.f;
    float acc[8];
#pragma unroll
    for (int j = 0; j < 8; j++) acc[j] = 0.f;

    int e1 = __ldg(&rowptr[v + 1]);
    for (int e = __ldg(&rowptr[v]); e < e1; e++) {
        int s = __ldg(&csrsrc[e]);
        uint4 raw = __ldg((const uint4*)(xl + (size_t)s * DD) + lane);
        const __half2* hp = (const __half2*)&raw;
        float2 f0 = __half22float2(hp[0]);
        float2 f1 = __half22float2(hp[1]);
        float2 f2 = __half22float2(hp[2]);
        float2 f3 = __half22float2(hp[3]);
        float p = 0.f;
        p = fmaf(lrelu(f0.x + r0.x, 0.2f), a0.x, p);
        p = fmaf(lrelu(f0.y + r0.y, 0.2f), a0.y, p);
        p = fmaf(lrelu(f1.x + r0.z, 0.2f), a0.z, p);
        p = fmaf(lrelu(f1.y + r0.w, 0.2f), a0.w, p);
        p = fmaf(lrelu(f2.x + r1.x, 0.2f), a1.x, p);
        p = fmaf(lrelu(f2.y + r1.y, 0.2f), a1.y, p);
        p = fmaf(lrelu(f3.x + r1.z, 0.2f), a1.z, p);
        p = fmaf(lrelu(f3.y + r1.w, 0.2f), a1.w, p);
        p += __shfl_xor_sync(0xffffffffu, p, 1);
        p += __shfl_xor_sync(0xffffffffu, p, 2);
        float nm = fmaxf(m, p);
        float sc = __expf(m - nm);
        float ep = __expf(p - nm);
        den = den * sc + ep;
        acc[0] = acc[0] * sc + f0.x * ep;
        acc[1] = acc[1] * sc + f0.y * ep;
        acc[2] = acc[2] * sc + f1.x * ep;
        acc[3] = acc[3] * sc + f1.y * ep;
        acc[4] = acc[4] * sc + f2.x * ep;
        acc[5] = acc[5] * sc + f2.y * ep;
        acc[6] = acc[6] * sc + f3.x * ep;
        acc[7] = acc[7] * sc + f3.y * ep;
        m = nm;
    }

    const float4* cb4 = (const float4*)convb;
    float4 cb0 = __ldg(&cb4[2 * lane]);
    float4 cb1 = __ldg(&cb4[2 * lane + 1]);
    float sci = __ldg(&scales[li]);
    float wi = __ldg(&wvec[li]);
    float4* h4 = (float4*)(h + (size_t)v * DD);
    float4 res0 = h4[2 * lane];
    float4 res1 = h4[2 * lane + 1];
    float id = 1.0f / den;
    float nh[8];
    nh[0] = res0.x + sci * lrelu(acc[0] * id + cb0.x, 0.1f);
    nh[1] = res0.y + sci * lrelu(acc[1] * id + cb0.y, 0.1f);
    nh[2] = res0.z + sci * lrelu(acc[2] * id + cb0.z, 0.1f);
    nh[3] = res0.w + sci * lrelu(acc[3] * id + cb0.w, 0.1f);
    nh[4] = res1.x + sci * lrelu(acc[4] * id + cb1.x, 0.1f);
    nh[5] = res1.y + sci * lrelu(acc[5] * id + cb1.y, 0.1f);
    nh[6] = res1.z + sci * lrelu(acc[6] * id + cb1.z, 0.1f);
    nh[7] = res1.w + sci * lrelu(acc[7] * id + cb1.w, 0.1f);
    h4[2 * lane] = make_float4(nh[0], nh[1], nh[2], nh[3]);
    h4[2 * lane + 1] = make_float4(nh[4], nh[5], nh[6], nh[7]);

    // hsum accumulation
    float4* hs4 = (float4*)(hsum + (size_t)v * DD);
    float4 sa, sb;
    if (li == 0) {
        sa = make_float4(0.f, 0.f, 0.f, 0.f);
        sb = make_float4(0.f, 0.f, 0.f, 0.f);
    } else {
        sa = hs4[2 * lane];
        sb = hs4[2 * lane + 1];
    }
    sa.x += wi * nh[0]; sa.y += wi * nh[1]; sa.z += wi * nh[2]; sa.w += wi * nh[3];
    sb.x += wi * nh[4]; sb.y += wi * nh[5]; sb.z += wi * nh[6]; sb.w += wi * nh[7];
    hs4[2 * lane] = sa;
    hs4[2 * lane + 1] = sb;

    // fused layernorm for next layer
    if (li < LL - 1) {
        float s = 0.f;
        float q = 0.f;
#pragma unroll
        for (int j = 0; j < 8; j++) {
            s += nh[j];
            q += nh[j] * nh[j];
        }
        for (int d = 16; d; d >>= 1) {
            s += __shfl_xor_sync(0xffffffffu, s, d);
            q += __shfl_xor_sync(0xffffffffu, q, d);
        }
        float mu = s * (1.0f / 256.0f);
        float var = q * (1.0f / 256.0f) - mu * mu;
        float rr = rsqrtf(var + EPSF);
        const float4* g4 = (const float4*)lng;
        const float4* b4 = (const float4*)lnb;
        float4 g0 = __ldg(&g4[2 * lane]);
        float4 g1 = __ldg(&g4[2 * lane + 1]);
        float4 bb0 = __ldg(&b4[2 * lane]);
        float4 bb1 = __ldg(&b4[2 * lane + 1]);
        float4 o0, o1;
        o0.x = (nh[0] - mu) * rr * g0.x + bb0.x;
        o0.y = (nh[1] - mu) * rr * g0.y + bb0.y;
        o0.z = (nh[2] - mu) * rr * g0.z + bb0.z;
        o0.w = (nh[3] - mu) * rr * g0.w + bb0.w;
        o1.x = (nh[4] - mu) * rr * g1.x + bb1.x;
        o1.y = (nh[5] - mu) * rr * g1.y + bb1.y;
        o1.z = (nh[6] - mu) * rr * g1.z + bb1.z;
        o1.w = (nh[7] - mu) * rr * g1.w + bb1.w;
        float4* hn4 = (float4*)(hn + (size_t)v * DD);
        hn4[2 * lane] = o0;
        hn4[2 * lane + 1] = o1;
    }
}

// ---------------- final projection ----------------
__global__ __launch_bounds__(256) void k_final(
    const float* __restrict__ y2, const float* __restrict__ w,
    const float* __restrict__ b, float* __restrict__ out) {
    int v = (int)((blockIdx.x * blockDim.x + threadIdx.x) >> 5);
    if (v >= NN) return;
    int lane = threadIdx.x & 31;
    const float4* y4 = (const float4*)y2;
    const float4* w4 = (const float4*)w;
    float4 a = y4[v * 32 + lane];
    float4 ww = __ldg(&w4[lane]);
    float p = a.x * ww.x + a.y * ww.y + a.z * ww.z + a.w * ww.w;
    for (int d = 16; d; d >>= 1) p += __shfl_xor_sync(0xffffffffu, p, d);
    if (lane == 0) out[v] = p + __ldg(&b[0]);
}

// ---------------- launcher ----------------
extern "C" void kernel_launch(void* const* d_in, const int* in_sizes, int n_in,
                              void* d_out, int out_size) {
    (void)in_sizes; (void)n_in; (void)out_size;
    const float* x      = (const float*)d_in[0];
    const int*   ei     = (const int*)d_in[1];
    const float* win_w  = (const float*)d_in[2];
    const float* win_b  = (const float*)d_in[3];
    const float* bn1_g  = (const float*)d_in[4];
    const float* bn1_b  = (const float*)d_in[5];
    const float* ln_g   = (const float*)d_in[6];
    const float* ln_b   = (const float*)d_in[7];
    const float* Wl     = (const float*)d_in[8];
    const float* bl     = (const float*)d_in[9];
    const float* Wr     = (const float*)d_in[10];
    const float* br     = (const float*)d_in[11];
    const float* att    = (const float*)d_in[12];
    const float* conv_b = (const float*)d_in[13];
    const float* scales = (const float*)d_in[14];
    const float* sw     = (const float*)d_in[15];
    const float* h1_w   = (const float*)d_in[16];
    const float* h1_b   = (const float*)d_in[17];
    const float* bn2_g  = (const float*)d_in[18];
    const float* bn2_b  = (const float*)d_in[19];
    const float* h2_w   = (const float*)d_in[20];
    const float* h2_b   = (const float*)d_in[21];
    const float* h3_w   = (const float*)d_in[22];
    const float* h3_b   = (const float*)d_in[23];
    float* out = (float*)d_out;

    float *p_h, *p_hn, *p_xr, *p_hsum, *p_y1, *p_y2, *p_w;
    __half* p_xl;
    int *p_rowptr, *p_deg, *p_bsum, *p_cursor, *p_csr;
    cudaGetSymbolAddress((void**)&p_h, d_h);
    cudaGetSymbolAddress((void**)&p_hn, d_hn);
    cudaGetSymbolAddress((void**)&p_xl, d_xl);
    cudaGetSymbolAddress((void**)&p_xr, d_xr);
    cudaGetSymbolAddress((void**)&p_hsum, d_hsum);
    cudaGetSymbolAddress((void**)&p_y1, d_y1);
    cudaGetSymbolAddress((void**)&p_y2, d_y2);
    cudaGetSymbolAddress((void**)&p_w, d_w);
    cudaGetSymbolAddress((void**)&p_rowptr, d_rowptr);
    cudaGetSymbolAddress((void**)&p_deg, d_deg);
    cudaGetSymbolAddress((void**)&p_bsum, d_bsum);
    cudaGetSymbolAddress((void**)&p_cursor, d_cursor);
    cudaGetSymbolAddress((void**)&p_csr, d_csrsrc);

    cudaFuncSetAttribute(k_gemm_tc<0>, cudaFuncAttributeMaxDynamicSharedMemorySize,
                         2 * STAGE_BYTES);
    cudaFuncSetAttribute(k_gemm_tc<1>, cudaFuncAttributeMaxDynamicSharedMemorySize,
                         2 * STAGE_BYTES);
    cudaFuncSetAttribute(k_gemm_tc<2>, cudaFuncAttributeMaxDynamicSharedMemorySize,
                         2 * STAGE_BYTES);

    const int* e_src = ei;
    const int* e_dst = ei + EE;
    const int warpBlocks = (NN * 32 + 255) / 256;
    const int smemB = 2 * STAGE_BYTES;

    // launch order arranged so ncu (-s 5) profiles the first layer GEMM
    k_softmax_w<<<1, 32>>>(sw, p_w);                                 // 0
    k_deg_init<<<(NN + 255) / 256, 256>>>(p_deg);                    // 1
    k_deg_count<<<(EE + 255) / 256, 256>>>(e_dst, p_deg);            // 2
    {
        dim3 g(2, (NN + 127) / 128);                                 // 3: input proj
        k_gemm_tc<1><<<g, 256, smemB>>>(x, win_w, win_w, win_b, win_b,
                                        bn1_g, bn1_b, p_h, NULL, NULL,
                                        NN, IND, DD, DD);
    }
    k_layernorm<<<warpBlocks, 256>>>(p_h, ln_g, ln_b, p_hn);         // 4
    {
        dim3 g(4, (NN + 127) / 128);                                 // 5: layer0 GEMM
        k_gemm_tc<0><<<g, 256, smemB>>>(p_hn, Wl, Wr, bl, br,
                                        NULL, NULL, NULL, p_xl, p_xr,
                                        NN, DD, DD, 0);
    }
    k_blocksum<<<NB, 256>>>(p_deg, p_bsum);
    k_bscan<<<1, 256>>>(p_bsum);
    k_scanout<<<NB, 256>>>(p_deg, p_bsum, p_rowptr);
    k_selfloop<<<(NN + 255) / 256, 256>>>(p_rowptr, p_cursor, p_csr);
    k_scatter<<<(EE + 255) / 256, 256>>>(e_src, e_dst, p_cursor, p_csr);

    for (int i = 0; i < LL; i++) {
        if (i > 0) {
            dim3 g(4, (NN + 127) / 128);
            k_gemm_tc<0><<<g, 256, smemB>>>(p_hn, Wl + (size_t)i * DD * DD,
                                            Wr + (size_t)i * DD * DD,
                                            bl + i * DD, br + i * DD,
                                            NULL, NULL, NULL, p_xl, p_xr,
                                            NN, DD, DD, 0);
        }
        k_gat<<<warpBlocks, 256>>>(p_xl, p_xr, p_rowptr, p_csr, att + i * DD,
                                   conv_b + i * DD, scales, p_w, i, p_h, p_hsum,
                                   ln_g + (i + 1 < LL ? (i + 1) * DD : 0),
                                   ln_b + (i + 1 < LL ? (i + 1) * DD : 0), p_hn);
    }

    {
        dim3 g(2, (NN + 127) / 128);
        k_gemm_tc<1><<<g, 256, smemB>>>(p_hsum, h1_w, h1_w, h1_b, h1_b,
                                        bn2_g, bn2_b, p_y1, NULL, NULL,
                                        NN, DD, DD, DD);
        dim3 g2(1, (NN + 127) / 128);
        k_gemm_tc<2><<<g2, 256, smemB>>>(p_y1, h2_w, h2_w, h2_b, h2_b,
                                         NULL, NULL, p_y2, NULL, NULL,
                                         NN, DD, DD / 2, DD / 2);
    }
    k_final<<<warpBlocks, 256>>>(p_y2, h3_w, h3_b, out);
}

// round 5
// speedup vs baseline: 2.4648x; 1.3001x over previous
#include <cuda_runtime.h>
#include <cuda_bf16.h>
#include <cuda_fp16.h>
#include <stdint.h>
#include <math.h>

#define NN 50000
#define EE 800000
#define IND 128
#define DD 256
#define LL 6
#define EPSF 1e-5f
#define NB 196

// smem stage layout (bytes); A: 128 rows x 40 b16 stride; B: 32 rows x 136 b16 stride
#define AH_OFF 0
#define AL_OFF 10240
#define BH_OFF 20480
#define BL_OFF 29184
#define STAGE_BYTES 37888
#define NSTAGE 3
#define SMEM_TOTAL (NSTAGE * STAGE_BYTES)

// weight-split pool offsets (elements)
#define W_WIN 0
#define W_WL 32768
#define W_WR 425984
#define W_H1 819200
#define W_H2 884736
#define W_TOT 917504

// ---------------- scratch ----------------
__device__ __align__(16) float  d_h[(size_t)NN * DD];
__device__ __align__(16) __nv_bfloat16 d_xh[(size_t)NN * IND];
__device__ __align__(16) __nv_bfloat16 d_xlo[(size_t)NN * IND];
__device__ __align__(16) __nv_bfloat16 d_hnh[(size_t)NN * DD];
__device__ __align__(16) __nv_bfloat16 d_hnl[(size_t)NN * DD];
__device__ __align__(16) __half d_xl[(size_t)NN * DD];
__device__ __align__(16) float  d_xr[(size_t)NN * DD];
__device__ __align__(16) float  d_hsum[(size_t)NN * DD];
__device__ __align__(16) __nv_bfloat16 d_hsh[(size_t)NN * DD];
__device__ __align__(16) __nv_bfloat16 d_hsl[(size_t)NN * DD];
__device__ __align__(16) __nv_bfloat16 d_y1h[(size_t)NN * DD];
__device__ __align__(16) __nv_bfloat16 d_y1l[(size_t)NN * DD];
__device__ __align__(16) float  d_y2[(size_t)NN * (DD / 2)];
__device__ __align__(16) __nv_bfloat16 d_wbh[W_TOT];
__device__ __align__(16) __nv_bfloat16 d_wbl[W_TOT];
__device__ int   d_rowptr[NN + 1];
__device__ int   d_deg[NN];
__device__ int   d_bsum[NB];
__device__ int   d_cursor[NN];
__device__ int   d_csrsrc[EE + NN];
__device__ float d_w[LL];

__device__ __forceinline__ float lrelu(float x, float a) { return x > 0.f ? x : a * x; }

// ---------------- tiny kernels ----------------
__global__ void k_softmax_w(const float* __restrict__ sw, float* __restrict__ w) {
    if (threadIdx.x == 0 && blockIdx.x == 0) {
        float m = -1e30f;
        for (int i = 0; i < LL; i++) m = fmaxf(m, sw[i]);
        float e[LL];
        float s = 0.f;
        for (int i = 0; i < LL; i++) { e[i] = __expf(sw[i] - m); s += e[i]; }
        for (int i = 0; i < LL; i++) w[i] = e[i] / s;
    }
}

// split fp32 -> bf16 hi/lo (n4 = elems/4)
__global__ void k_split(const float* __restrict__ in, __nv_bfloat16* __restrict__ hi,
                        __nv_bfloat16* __restrict__ lo, int n4) {
    int i = blockIdx.x * blockDim.x + threadIdx.x;
    if (i >= n4) return;
    float4 v = ((const float4*)in)[i];
    __nv_bfloat16 h[4];
    __nv_bfloat16 l[4];
    h[0] = __float2bfloat16(v.x); l[0] = __float2bfloat16(v.x - __bfloat162float(h[0]));
    h[1] = __float2bfloat16(v.y); l[1] = __float2bfloat16(v.y - __bfloat162float(h[1]));
    h[2] = __float2bfloat16(v.z); l[2] = __float2bfloat16(v.z - __bfloat162float(h[2]));
    h[3] = __float2bfloat16(v.w); l[3] = __float2bfloat16(v.w - __bfloat162float(h[3]));
    ((uint2*)hi)[i] = *(uint2*)h;
    ((uint2*)lo)[i] = *(uint2*)l;
}

__global__ void k_deg_init(int* __restrict__ deg) {
    int i = blockIdx.x * blockDim.x + threadIdx.x;
    if (i < NN) deg[i] = 1;
}

__global__ void k_deg_count(const int* __restrict__ dst, int* __restrict__ deg) {
    int i = blockIdx.x * blockDim.x + threadIdx.x;
    if (i < EE) atomicAdd(&deg[dst[i]], 1);
}

__global__ void k_blocksum(const int* __restrict__ deg, int* __restrict__ bsum) {
    int i = blockIdx.x * 256 + threadIdx.x;
    int v = (i < NN) ? deg[i] : 0;
    int lane = threadIdx.x & 31;
    int wid = threadIdx.x >> 5;
    for (int d = 16; d; d >>= 1) v += __shfl_xor_sync(0xffffffffu, v, d);
    __shared__ int ws[8];
    if (lane == 0) ws[wid] = v;
    __syncthreads();
    if (threadIdx.x == 0) {
        int s = 0;
        for (int k = 0; k < 8; k++) s += ws[k];
        bsum[blockIdx.x] = s;
    }
}

__global__ void k_bscan(int* __restrict__ bsum) {
    int t = threadIdx.x;
    int v = (t < NB) ? bsum[t] : 0;
    int lane = t & 31;
    int wid = t >> 5;
    int x = v;
    for (int d = 1; d < 32; d <<= 1) {
        int u = __shfl_up_sync(0xffffffffu, x, d);
        if (lane >= d) x += u;
    }
    __shared__ int ws[8];
    if (lane == 31) ws[wid] = x;
    __syncthreads();
    if (wid == 0 && lane < 8) {
        int y = ws[lane];
        for (int d = 1; d < 8; d <<= 1) {
            int u = __shfl_up_sync(0xffu, y, d);
            if (lane >= d) y += u;
        }
        ws[lane] = y;
    }
    __syncthreads();
    int incl = x + (wid > 0 ? ws[wid - 1] : 0);
    if (t < NB) bsum[t] = incl - v;
}

__global__ void k_scanout(const int* __restrict__ deg, const int* __restrict__ boff,
                          int* __restrict__ rowptr) {
    int t = threadIdx.x;
    int i = blockIdx.x * 256 + t;
    int v = (i < NN) ? deg[i] : 0;
    int lane = t & 31;
    int wid = t >> 5;
    int x = v;
    for (int d = 1; d < 32; d <<= 1) {
        int u = __shfl_up_sync(0xffffffffu, x, d);
        if (lane >= d) x += u;
    }
    __shared__ int ws[8];
    if (lane == 31) ws[wid] = x;
    __syncthreads();
    if (wid == 0 && lane < 8) {
        int y = ws[lane];
        for (int d = 1; d < 8; d <<= 1) {
            int u = __shfl_up_sync(0xffu, y, d);
            if (lane >= d) y += u;
        }
        ws[lane] = y;
    }
    __syncthreads();
    int excl = x - v + (wid > 0 ? ws[wid - 1] : 0) + boff[blockIdx.x];
    if (i < NN) rowptr[i] = excl;
    if (i == 0) rowptr[NN] = EE + NN;
}

__global__ void k_selfloop(const int* __restrict__ rowptr, int* __restrict__ cursor,
                           int* __restrict__ csrsrc) {
    int v = blockIdx.x * blockDim.x + threadIdx.x;
    if (v < NN) {
        int p = rowptr[v];
        csrsrc[p] = v;
        cursor[v] = p + 1;
    }
}

__global__ void k_scatter(const int* __restrict__ src, const int* __restrict__ dst,
                          int* __restrict__ cursor, int* __restrict__ csrsrc) {
    int i = blockIdx.x * blockDim.x + threadIdx.x;
    if (i < EE) {
        int p = atomicAdd(&cursor[dst[i]], 1);
        csrsrc[p] = src[i];
    }
}

// ---------------- layernorm (layer 0 only): fp32 in -> split bf16 out ----------------
__global__ __launch_bounds__(256) void k_layernorm(
    const float* __restrict__ h, const float* __restrict__ g,
    const float* __restrict__ b, __nv_bfloat16* __restrict__ hnh,
    __nv_bfloat16* __restrict__ hnl) {
    int v = (int)((blockIdx.x * blockDim.x + threadIdx.x) >> 5);
    if (v >= NN) return;
    int lane = threadIdx.x & 31;
    const float4* h4 = (const float4*)(h + (size_t)v * DD);
    float4 x0 = h4[2 * lane];
    float4 x1 = h4[2 * lane + 1];
    float s = x0.x + x0.y + x0.z + x0.w + x1.x + x1.y + x1.z + x1.w;
    float q = x0.x * x0.x + x0.y * x0.y + x0.z * x0.z + x0.w * x0.w
            + x1.x * x1.x + x1.y * x1.y + x1.z * x1.z + x1.w * x1.w;
    for (int d = 16; d; d >>= 1) {
        s += __shfl_xor_sync(0xffffffffu, s, d);
        q += __shfl_xor_sync(0xffffffffu, q, d);
    }
    float mu = s * (1.0f / 256.0f);
    float var = q * (1.0f / 256.0f) - mu * mu;
    float r = rsqrtf(var + EPSF);
    const float4* g4 = (const float4*)g;
    const float4* b4 = (const float4*)b;
    float4 g0 = __ldg(&g4[2 * lane]);
    float4 g1 = __ldg(&g4[2 * lane + 1]);
    float4 b0 = __ldg(&b4[2 * lane]);
    float4 b1 = __ldg(&b4[2 * lane + 1]);
    float o[8];
    o[0] = (x0.x - mu) * r * g0.x + b0.x;
    o[1] = (x0.y - mu) * r * g0.y + b0.y;
    o[2] = (x0.z - mu) * r * g0.z + b0.z;
    o[3] = (x0.w - mu) * r * g0.w + b0.w;
    o[4] = (x1.x - mu) * r * g1.x + b1.x;
    o[5] = (x1.y - mu) * r * g1.y + b1.y;
    o[6] = (x1.z - mu) * r * g1.z + b1.z;
    o[7] = (x1.w - mu) * r * g1.w + b1.w;
    __nv_bfloat16 ph[8];
    __nv_bfloat16 pl[8];
#pragma unroll
    for (int j = 0; j < 8; j++) {
        ph[j] = __float2bfloat16(o[j]);
        pl[j] = __float2bfloat16(o[j] - __bfloat162float(ph[j]));
    }
    *(uint4*)(hnh + (size_t)v * DD + 8 * lane) = *(uint4*)ph;
    *(uint4*)(hnl + (size_t)v * DD + 8 * lane) = *(uint4*)pl;
}

// ---------------- tensor-core GEMM ----------------
__device__ __forceinline__ void cp16(unsigned int dst, const void* src, int srcsize) {
    asm volatile("cp.async.cg.shared.global [%0], [%1], 16, %2;"
                 :: "r"(dst), "l"(src), "r"(srcsize));
}

__device__ __forceinline__ void ldsm_x4(unsigned int* r, unsigned int addr) {
    asm volatile("ldmatrix.sync.aligned.m8n8.x4.shared.b16 {%0,%1,%2,%3}, [%4];"
                 : "=r"(r[0]), "=r"(r[1]), "=r"(r[2]), "=r"(r[3]) : "r"(addr));
}

__device__ __forceinline__ void ldsm_x4t(unsigned int* r, unsigned int addr) {
    asm volatile("ldmatrix.sync.aligned.m8n8.x4.trans.shared.b16 {%0,%1,%2,%3}, [%4];"
                 : "=r"(r[0]), "=r"(r[1]), "=r"(r[2]), "=r"(r[3]) : "r"(addr));
}

__device__ __forceinline__ void mma_bf16(float* c, const unsigned int* a,
                                         const unsigned int* b) {
    asm volatile(
        "mma.sync.aligned.m16n8k16.row.col.f32.bf16.bf16.f32 "
        "{%0,%1,%2,%3}, {%4,%5,%6,%7}, {%8,%9}, {%0,%1,%2,%3};"
        : "+f"(c[0]), "+f"(c[1]), "+f"(c[2]), "+f"(c[3])
        : "r"(a[0]), "r"(a[1]), "r"(a[2]), "r"(a[3]), "r"(b[0]), "r"(b[1]));
}

__device__ __forceinline__ void issue_stage(
    const __nv_bfloat16* __restrict__ Ah, const __nv_bfloat16* __restrict__ Al,
    const __nv_bfloat16* __restrict__ Bh, const __nv_bfloat16* __restrict__ Bl,
    unsigned int sdst, int bm, int bn_l, int M, int K, int ldb, int tid, int kk) {
#pragma unroll
    for (int u = 0; u < 2; u++) {
        int c = tid + u * 256;
        int row = c >> 2;
        int seg = c & 3;
        int gr = bm + row;
        size_t go = (size_t)gr * K + kk + seg * 8;
        unsigned int dd = sdst + AH_OFF + row * 80 + seg * 16;
        int p = (gr < M) ? 16 : 0;
        cp16(dd, Ah + go, p);
        cp16(dd + (AL_OFF - AH_OFF), Al + go, p);
    }
#pragma unroll
    for (int u = 0; u < 2; u++) {
        int c = tid + u * 256;
        int row = c >> 4;
        int seg = c & 15;
        size_t go = (size_t)(kk + row) * ldb + bn_l + seg * 8;
        unsigned int dd = sdst + BH_OFF + row * 272 + seg * 16;
        cp16(dd, Bh + go, 16);
        cp16(dd + (BL_OFF - BH_OFF), Bl + go, 16);
    }
}

__device__ __forceinline__ void tile_mma(unsigned int stg, int wm0, int wn0,
                                         int aRow, int aKof, int bRow, int bNof,
                                         float acc[4][4][4]) {
#pragma unroll
    for (int ks = 0; ks < 32; ks += 16) {
        unsigned int ah[4][4];
        unsigned int al[4][4];
        unsigned int bh[4][2];
        unsigned int bl[4][2];
#pragma unroll
        for (int mi = 0; mi < 4; mi++) {
            unsigned int ad = stg + AH_OFF
                + (unsigned int)((wm0 + mi * 16 + aRow) * 40 + ks + aKof) * 2u;
            ldsm_x4(ah[mi], ad);
            ldsm_x4(al[mi], ad + (AL_OFF - AH_OFF));
        }
#pragma unroll
        for (int np = 0; np < 2; np++) {
            unsigned int bd = stg + BH_OFF
                + (unsigned int)((ks + bRow) * 136 + wn0 + np * 16 + bNof) * 2u;
            unsigned int tb[4];
            ldsm_x4t(tb, bd);
            bh[np * 2][0] = tb[0];
            bh[np * 2][1] = tb[1];
            bh[np * 2 + 1][0] = tb[2];
            bh[np * 2 + 1][1] = tb[3];
            ldsm_x4t(tb, bd + (BL_OFF - BH_OFF));
            bl[np * 2][0] = tb[0];
            bl[np * 2][1] = tb[1];
            bl[np * 2 + 1][0] = tb[2];
            bl[np * 2 + 1][1] = tb[3];
        }
#pragma unroll
        for (int mi = 0; mi < 4; mi++) {
#pragma unroll
            for (int ni = 0; ni < 4; ni++) {
                mma_bf16(acc[mi][ni], ah[mi], bh[ni]);
                mma_bf16(acc[mi][ni], ah[mi], bl[ni]);
                mma_bf16(acc[mi][ni], al[mi], bh[ni]);
            }
        }
    }
}

// EPI 0: layer -> xl(half,<256)/xr(float,>=256). EPI 1: bn+lrelu -> C fp32.
// EPI 2: lrelu -> C fp32. EPI 3: bn+lrelu -> split bf16 (Coh/Col).
template <int EPI>
__global__ __launch_bounds__(256, 2) void k_gemm_tc(
    const __nv_bfloat16* __restrict__ Ah, const __nv_bfloat16* __restrict__ Al,
    const __nv_bfloat16* __restrict__ B0h, const __nv_bfloat16* __restrict__ B0l,
    const __nv_bfloat16* __restrict__ B1h, const __nv_bfloat16* __restrict__ B1l,
    const float* __restrict__ bias0, const float* __restrict__ bias1,
    const float* __restrict__ bng, const float* __restrict__ bnb,
    float* __restrict__ C, __half* __restrict__ Cxl, float* __restrict__ Cxr,
    __nv_bfloat16* __restrict__ Coh, __nv_bfloat16* __restrict__ Col,
    int M, int K, int ldb, int ldc) {
    extern __shared__ char smem[];
    const int tid = threadIdx.x;
    const int lane = tid & 31;
    const int wid = tid >> 5;
    const int bm = blockIdx.y * 128;
    const int bn = blockIdx.x * 128;
    const __nv_bfloat16* Bh = (bn < 256) ? B0h : B1h;
    const __nv_bfloat16* Bl = (bn < 256) ? B0l : B1l;
    const float* biasp = (bn < 256) ? bias0 : bias1;
    const int bn_l = bn & 255;
    const int wm0 = (wid & 1) * 64;
    const int wn0 = (wid >> 1) * 32;
    unsigned int sbase = (unsigned int)__cvta_generic_to_shared(smem);

    float acc[4][4][4];
#pragma unroll
    for (int i = 0; i < 4; i++) {
#pragma unroll
        for (int j = 0; j < 4; j++) {
#pragma unroll
            for (int k = 0; k < 4; k++) acc[i][j][k] = 0.f;
        }
    }

    const int grp = lane & 7;
    const int seg = lane >> 3;
    const int aRow = (seg & 1) * 8 + grp;
    const int aKof = (seg >> 1) * 8;
    const int bRow = (seg & 1) * 8 + grp;
    const int bNof = (seg >> 1) * 8;

    int nk = K / 32;
    issue_stage(Ah, Al, Bh, Bl, sbase, bm, bn_l, M, K, ldb, tid, 0);
    asm volatile("cp.async.commit_group;");
    issue_stage(Ah, Al, Bh, Bl, sbase + STAGE_BYTES, bm, bn_l, M, K, ldb, tid, 32);
    asm volatile("cp.async.commit_group;");

    for (int t = 0; t < nk; t++) {
        asm volatile("cp.async.wait_group 1;");
        __syncthreads();
        int sidx = t % NSTAGE;
        tile_mma(sbase + (unsigned int)sidx * STAGE_BYTES,
                 wm0, wn0, aRow, aKof, bRow, bNof, acc);
        if (t + 2 < nk) {
            issue_stage(Ah, Al, Bh, Bl,
                        sbase + (unsigned int)((t + 2) % NSTAGE) * STAGE_BYTES,
                        bm, bn_l, M, K, ldb, tid, (t + 2) * 32);
        }
        asm volatile("cp.async.commit_group;");
    }

    const float rsb = rsqrtf(1.0f + EPSF);
    const int cg = lane >> 2;
    const int cc = lane & 3;
#pragma unroll
    for (int mi = 0; mi < 4; mi++) {
        int r0 = bm + wm0 + mi * 16 + cg;
#pragma unroll
        for (int ni = 0; ni < 4; ni++) {
            int colL = wn0 + ni * 8 + 2 * cc;
            int colB = bn_l + colL;
            float b0v = __ldg(&biasp[colB]);
            float b1v = __ldg(&biasp[colB + 1]);
            float v0 = acc[mi][ni][0] + b0v;
            float v1 = acc[mi][ni][1] + b1v;
            float v2 = acc[mi][ni][2] + b0v;
            float v3 = acc[mi][ni][3] + b1v;
            if (EPI == 0) {
                if (bn < 256) {
                    if (r0 < M)
                        *(__half2*)(Cxl + (size_t)r0 * DD + colB) = __floats2half2_rn(v0, v1);
                    if (r0 + 8 < M)
                        *(__half2*)(Cxl + (size_t)(r0 + 8) * DD + colB) = __floats2half2_rn(v2, v3);
                } else {
                    if (r0 < M)
                        *(float2*)(Cxr + (size_t)r0 * DD + colB) = make_float2(v0, v1);
                    if (r0 + 8 < M)
                        *(float2*)(Cxr + (size_t)(r0 + 8) * DD + colB) = make_float2(v2, v3);
                }
            } else {
                if (EPI == 1 || EPI == 3) {
                    float g0 = __ldg(&bng[colB]);
                    float g1 = __ldg(&bng[colB + 1]);
                    float q0 = __ldg(&bnb[colB]);
                    float q1 = __ldg(&bnb[colB + 1]);
                    v0 = lrelu(v0 * rsb * g0 + q0, 0.1f);
                    v1 = lrelu(v1 * rsb * g1 + q1, 0.1f);
                    v2 = lrelu(v2 * rsb * g0 + q0, 0.1f);
                    v3 = lrelu(v3 * rsb * g1 + q1, 0.1f);
                }
                if (EPI == 2) {
                    v0 = lrelu(v0, 0.1f);
                    v1 = lrelu(v1, 0.1f);
                    v2 = lrelu(v2, 0.1f);
                    v3 = lrelu(v3, 0.1f);
                }
                int col = bn + colL;
                if (EPI == 3) {
                    __nv_bfloat16 h0 = __float2bfloat16(v0);
                    __nv_bfloat16 h1 = __float2bfloat16(v1);
                    __nv_bfloat16 h2 = __float2bfloat16(v2);
                    __nv_bfloat16 h3 = __float2bfloat16(v3);
                    __nv_bfloat16 l0 = __float2bfloat16(v0 - __bfloat162float(h0));
                    __nv_bfloat16 l1 = __float2bfloat16(v1 - __bfloat162float(h1));
                    __nv_bfloat16 l2 = __float2bfloat16(v2 - __bfloat162float(h2));
                    __nv_bfloat16 l3 = __float2bfloat16(v3 - __bfloat162float(h3));
                    if (r0 < M) {
                        __nv_bfloat16 th[2] = {h0, h1};
                        __nv_bfloat16 tl[2] = {l0, l1};
                        *(unsigned int*)(Coh + (size_t)r0 * ldc + col) = *(unsigned int*)th;
                        *(unsigned int*)(Col + (size_t)r0 * ldc + col) = *(unsigned int*)tl;
                    }
                    if (r0 + 8 < M) {
                        __nv_bfloat16 th[2] = {h2, h3};
                        __nv_bfloat16 tl[2] = {l2, l3};
                        *(unsigned int*)(Coh + (size_t)(r0 + 8) * ldc + col) = *(unsigned int*)th;
                        *(unsigned int*)(Col + (size_t)(r0 + 8) * ldc + col) = *(unsigned int*)tl;
                    }
                } else {
                    if (r0 < M)
                        *(float2*)(C + (size_t)r0 * ldc + col) = make_float2(v0, v1);
                    if (r0 + 8 < M)
                        *(float2*)(C + (size_t)(r0 + 8) * ldc + col) = make_float2(v2, v3);
                }
            }
        }
    }
}

// ---------------- GATv2 aggregation + residual + fused next-layer LN (split out) ----------------
__global__ __launch_bounds__(256) void k_gat(
    const __half* __restrict__ xl, const float* __restrict__ xr,
    const int* __restrict__ rowptr, const int* __restrict__ csrsrc,
    const float* __restrict__ att, const float* __restrict__ convb,
    const float* __restrict__ scales, const float* __restrict__ wvec, int li,
    float* __restrict__ h, float* __restrict__ hsum,
    const float* __restrict__ lng, const float* __restrict__ lnb,
    __nv_bfloat16* __restrict__ hnh, __nv_bfloat16* __restrict__ hnl,
    __nv_bfloat16* __restrict__ hsh, __nv_bfloat16* __restrict__ hsl) {
    int v = (int)((blockIdx.x * blockDim.x + threadIdx.x) >> 5);
    if (v >= NN) return;
    int lane = threadIdx.x & 31;

    const float4* att4 = (const float4*)att;
    float4 a0 = __ldg(&att4[2 * lane]);
    float4 a1 = __ldg(&att4[2 * lane + 1]);
    const float4* xr4 = (const float4*)(xr + (size_t)v * DD);
    float4 r0 = __ldg(&xr4[2 * lane]);
    float4 r1 = __ldg(&xr4[2 * lane + 1]);

    float m = -1e30f;
    float den = 0.f;
    float acc[8];
#pragma unroll
    for (int j = 0; j < 8; j++) acc[j] = 0.f;

    int e1 = __ldg(&rowptr[v + 1]);
    for (int e = __ldg(&rowptr[v]); e < e1; e++) {
        int s = __ldg(&csrsrc[e]);
        uint4 raw = __ldg((const uint4*)(xl + (size_t)s * DD) + lane);
        const __half2* hp = (const __half2*)&raw;
        float2 f0 = __half22float2(hp[0]);
        float2 f1 = __half22float2(hp[1]);
        float2 f2 = __half22float2(hp[2]);
        float2 f3 = __half22float2(hp[3]);
        float p = 0.f;
        p = fmaf(lrelu(f0.x + r0.x, 0.2f), a0.x, p);
        p = fmaf(lrelu(f0.y + r0.y, 0.2f), a0.y, p);
        p = fmaf(lrelu(f1.x + r0.z, 0.2f), a0.z, p);
        p = fmaf(lrelu(f1.y + r0.w, 0.2f), a0.w, p);
        p = fmaf(lrelu(f2.x + r1.x, 0.2f), a1.x, p);
        p = fmaf(lrelu(f2.y + r1.y, 0.2f), a1.y, p);
        p = fmaf(lrelu(f3.x + r1.z, 0.2f), a1.z, p);
        p = fmaf(lrelu(f3.y + r1.w, 0.2f), a1.w, p);
        p += __shfl_xor_sync(0xffffffffu, p, 1);
        p += __shfl_xor_sync(0xffffffffu, p, 2);
        float nm = fmaxf(m, p);
        float sc = __expf(m - nm);
        float ep = __expf(p - nm);
        den = den * sc + ep;
        acc[0] = acc[0] * sc + f0.x * ep;
        acc[1] = acc[1] * sc + f0.y * ep;
        acc[2] = acc[2] * sc + f1.x * ep;
        acc[3] = acc[3] * sc + f1.y * ep;
        acc[4] = acc[4] * sc + f2.x * ep;
        acc[5] = acc[5] * sc + f2.y * ep;
        acc[6] = acc[6] * sc + f3.x * ep;
        acc[7] = acc[7] * sc + f3.y * ep;
        m = nm;
    }

    const float4* cb4 = (const float4*)convb;
    float4 cb0 = __ldg(&cb4[2 * lane]);
    float4 cb1 = __ldg(&cb4[2 * lane + 1]);
    float sci = __ldg(&scales[li]);
    float wi = __ldg(&wvec[li]);
    float4* h4 = (float4*)(h + (size_t)v * DD);
    float4 res0 = h4[2 * lane];
    float4 res1 = h4[2 * lane + 1];
    float id = 1.0f / den;
    float nh[8];
    nh[0] = res0.x + sci * lrelu(acc[0] * id + cb0.x, 0.1f);
    nh[1] = res0.y + sci * lrelu(acc[1] * id + cb0.y, 0.1f);
    nh[2] = res0.z + sci * lrelu(acc[2] * id + cb0.z, 0.1f);
    nh[3] = res0.w + sci * lrelu(acc[3] * id + cb0.w, 0.1f);
    nh[4] = res1.x + sci * lrelu(acc[4] * id + cb1.x, 0.1f);
    nh[5] = res1.y + sci * lrelu(acc[5] * id + cb1.y, 0.1f);
    nh[6] = res1.z + sci * lrelu(acc[6] * id + cb1.z, 0.1f);
    nh[7] = res1.w + sci * lrelu(acc[7] * id + cb1.w, 0.1f);
    h4[2 * lane] = make_float4(nh[0], nh[1], nh[2], nh[3]);
    h4[2 * lane + 1] = make_float4(nh[4], nh[5], nh[6], nh[7]);

    float4* hs4 = (float4*)(hsum + (size_t)v * DD);
    float4 sa, sb;
    if (li == 0) {
        sa = make_float4(0.f, 0.f, 0.f, 0.f);
        sb = make_float4(0.f, 0.f, 0.f, 0.f);
    } else {
        sa = hs4[2 * lane];
        sb = hs4[2 * lane + 1];
    }
    sa.x += wi * nh[0]; sa.y += wi * nh[1]; sa.z += wi * nh[2]; sa.w += wi * nh[3];
    sb.x += wi * nh[4]; sb.y += wi * nh[5]; sb.z += wi * nh[6]; sb.w += wi * nh[7];
    hs4[2 * lane] = sa;
    hs4[2 * lane + 1] = sb;

    if (li < LL - 1) {
        float s = 0.f;
        float q = 0.f;
#pragma unroll
        for (int j = 0; j < 8; j++) {
            s += nh[j];
            q += nh[j] * nh[j];
        }
        for (int d = 16; d; d >>= 1) {
            s += __shfl_xor_sync(0xffffffffu, s, d);
            q += __shfl_xor_sync(0xffffffffu, q, d);
        }
        float mu = s * (1.0f / 256.0f);
        float var = q * (1.0f / 256.0f) - mu * mu;
        float rr = rsqrtf(var + EPSF);
        const float4* g4 = (const float4*)lng;
        const float4* b4 = (const float4*)lnb;
        float4 g0 = __ldg(&g4[2 * lane]);
        float4 g1 = __ldg(&g4[2 * lane + 1]);
        float4 bb0 = __ldg(&b4[2 * lane]);
        float4 bb1 = __ldg(&b4[2 * lane + 1]);
        float o[8];
        o[0] = (nh[0] - mu) * rr * g0.x + bb0.x;
        o[1] = (nh[1] - mu) * rr * g0.y + bb0.y;
        o[2] = (nh[2] - mu) * rr * g0.z + bb0.z;
        o[3] = (nh[3] - mu) * rr * g0.w + bb0.w;
        o[4] = (nh[4] - mu) * rr * g1.x + bb1.x;
        o[5] = (nh[5] - mu) * rr * g1.y + bb1.y;
        o[6] = (nh[6] - mu) * rr * g1.z + bb1.z;
        o[7] = (nh[7] - mu) * rr * g1.w + bb1.w;
        __nv_bfloat16 ph[8];
        __nv_bfloat16 pl[8];
#pragma unroll
        for (int j = 0; j < 8; j++) {
            ph[j] = __float2bfloat16(o[j]);
            pl[j] = __float2bfloat16(o[j] - __bfloat162float(ph[j]));
        }
        *(uint4*)(hnh + (size_t)v * DD + 8 * lane) = *(uint4*)ph;
        *(uint4*)(hnl + (size_t)v * DD + 8 * lane) = *(uint4*)pl;
    } else {
        float sv[8];
        sv[0] = sa.x; sv[1] = sa.y; sv[2] = sa.z; sv[3] = sa.w;
        sv[4] = sb.x; sv[5] = sb.y; sv[6] = sb.z; sv[7] = sb.w;
        __nv_bfloat16 ph[8];
        __nv_bfloat16 pl[8];
#pragma unroll
        for (int j = 0; j < 8; j++) {
            ph[j] = __float2bfloat16(sv[j]);
            pl[j] = __float2bfloat16(sv[j] - __bfloat162float(ph[j]));
        }
        *(uint4*)(hsh + (size_t)v * DD + 8 * lane) = *(uint4*)ph;
        *(uint4*)(hsl + (size_t)v * DD + 8 * lane) = *(uint4*)pl;
    }
}

// ---------------- final projection ----------------
__global__ __launch_bounds__(256) void k_final(
    const float* __restrict__ y2, const float* __restrict__ w,
    const float* __restrict__ b, float* __restrict__ out) {
    int v = (int)((blockIdx.x * blockDim.x + threadIdx.x) >> 5);
    if (v >= NN) return;
    int lane = threadIdx.x & 31;
    const float4* y4 = (const float4*)y2;
    const float4* w4 = (const float4*)w;
    float4 a = y4[v * 32 + lane];
    float4 ww = __ldg(&w4[lane]);
    float p = a.x * ww.x + a.y * ww.y + a.z * ww.z + a.w * ww.w;
    for (int d = 16; d; d >>= 1) p += __shfl_xor_sync(0xffffffffu, p, d);
    if (lane == 0) out[v] = p + __ldg(&b[0]);
}

// ---------------- launcher ----------------
extern "C" void kernel_launch(void* const* d_in, const int* in_sizes, int n_in,
                              void* d_out, int out_size) {
    (void)in_sizes; (void)n_in; (void)out_size;
    const float* x      = (const float*)d_in[0];
    const int*   ei     = (const int*)d_in[1];
    const float* win_w  = (const float*)d_in[2];
    const float* win_b  = (const float*)d_in[3];
    const float* bn1_g  = (const float*)d_in[4];
    const float* bn1_b  = (const float*)d_in[5];
    const float* ln_g   = (const float*)d_in[6];
    const float* ln_b   = (const float*)d_in[7];
    const float* Wl     = (const float*)d_in[8];
    const float* bl     = (const float*)d_in[9];
    const float* Wr     = (const float*)d_in[10];
    const float* br     = (const float*)d_in[11];
    const float* att    = (const float*)d_in[12];
    const float* conv_b = (const float*)d_in[13];
    const float* scales = (const float*)d_in[14];
    const float* sw     = (const float*)d_in[15];
    const float* h1_w   = (const float*)d_in[16];
    const float* h1_b   = (const float*)d_in[17];
    const float* bn2_g  = (const float*)d_in[18];
    const float* bn2_b  = (const float*)d_in[19];
    const float* h2_w   = (const float*)d_in[20];
    const float* h2_b   = (const float*)d_in[21];
    const float* h3_w   = (const float*)d_in[22];
    const float* h3_b   = (const float*)d_in[23];
    float* out = (float*)d_out;

    float *p_h, *p_xr, *p_hsum, *p_y2, *p_w;
    __half* p_xl;
    __nv_bfloat16 *p_xh, *p_xlo, *p_hnh, *p_hnl, *p_hsh, *p_hsl, *p_y1h, *p_y1l;
    __nv_bfloat16 *p_wbh, *p_wbl;
    int *p_rowptr, *p_deg, *p_bsum, *p_cursor, *p_csr;
    cudaGetSymbolAddress((void**)&p_h, d_h);
    cudaGetSymbolAddress((void**)&p_xh, d_xh);
    cudaGetSymbolAddress((void**)&p_xlo, d_xlo);
    cudaGetSymbolAddress((void**)&p_hnh, d_hnh);
    cudaGetSymbolAddress((void**)&p_hnl, d_hnl);
    cudaGetSymbolAddress((void**)&p_xl, d_xl);
    cudaGetSymbolAddress((void**)&p_xr, d_xr);
    cudaGetSymbolAddress((void**)&p_hsum, d_hsum);
    cudaGetSymbolAddress((void**)&p_hsh, d_hsh);
    cudaGetSymbolAddress((void**)&p_hsl, d_hsl);
    cudaGetSymbolAddress((void**)&p_y1h, d_y1h);
    cudaGetSymbolAddress((void**)&p_y1l, d_y1l);
    cudaGetSymbolAddress((void**)&p_y2, d_y2);
    cudaGetSymbolAddress((void**)&p_wbh, d_wbh);
    cudaGetSymbolAddress((void**)&p_wbl, d_wbl);
    cudaGetSymbolAddress((void**)&p_w, d_w);
    cudaGetSymbolAddress((void**)&p_rowptr, d_rowptr);
    cudaGetSymbolAddress((void**)&p_deg, d_deg);
    cudaGetSymbolAddress((void**)&p_bsum, d_bsum);
    cudaGetSymbolAddress((void**)&p_cursor, d_cursor);
    cudaGetSymbolAddress((void**)&p_csr, d_csrsrc);

    cudaFuncSetAttribute(k_gemm_tc<0>, cudaFuncAttributeMaxDynamicSharedMemorySize, SMEM_TOTAL);
    cudaFuncSetAttribute(k_gemm_tc<1>, cudaFuncAttributeMaxDynamicSharedMemorySize, SMEM_TOTAL);
    cudaFuncSetAttribute(k_gemm_tc<2>, cudaFuncAttributeMaxDynamicSharedMemorySize, SMEM_TOTAL);
    cudaFuncSetAttribute(k_gemm_tc<3>, cudaFuncAttributeMaxDynamicSharedMemorySize, SMEM_TOTAL);

    const int* e_src = ei;
    const int* e_dst = ei + EE;
    const int warpBlocks = (NN * 32 + 255) / 256;

    // 0-4: setup so launch #5 (ncu -s 5) is the input-proj GEMM
    k_softmax_w<<<1, 32>>>(sw, p_w);
    {
        int n4 = NN * IND / 4;
        k_split<<<(n4 + 255) / 256, 256>>>(x, p_xh, p_xlo, n4);
    }
    {
        int n4 = IND * DD / 4;
        k_split<<<(n4 + 255) / 256, 256>>>(win_w, p_wbh + W_WIN, p_wbl + W_WIN, n4);
    }
    k_deg_init<<<(NN + 255) / 256, 256>>>(p_deg);
    k_deg_count<<<(EE + 255) / 256, 256>>>(e_dst, p_deg);

    {
        dim3 g(2, (NN + 127) / 128);   // launch #5: input projection
        k_gemm_tc<1><<<g, 256, SMEM_TOTAL>>>(
            p_xh, p_xlo, p_wbh + W_WIN, p_wbl + W_WIN, p_wbh + W_WIN, p_wbl + W_WIN,
            win_b, win_b, bn1_g, bn1_b, p_h, NULL, NULL, NULL, NULL,
            NN, IND, DD, DD);
    }

    {
        int n4 = LL * DD * DD / 4;
        k_split<<<(n4 + 255) / 256, 256>>>(Wl, p_wbh + W_WL, p_wbl + W_WL, n4);
        k_split<<<(n4 + 255) / 256, 256>>>(Wr, p_wbh + W_WR, p_wbl + W_WR, n4);
    }
    {
        int n4 = DD * DD / 4;
        k_split<<<(n4 + 255) / 256, 256>>>(h1_w, p_wbh + W_H1, p_wbl + W_H1, n4);
    }
    {
        int n4 = DD * (DD / 2) / 4;
        k_split<<<(n4 + 255) / 256, 256>>>(h2_w, p_wbh + W_H2, p_wbl + W_H2, n4);
    }

    k_layernorm<<<warpBlocks, 256>>>(p_h, ln_g, ln_b, p_hnh, p_hnl);

    k_blocksum<<<NB, 256>>>(p_deg, p_bsum);
    k_bscan<<<1, 256>>>(p_bsum);
    k_scanout<<<NB, 256>>>(p_deg, p_bsum, p_rowptr);
    k_selfloop<<<(NN + 255) / 256, 256>>>(p_rowptr, p_cursor, p_csr);
    k_scatter<<<(EE + 255) / 256, 256>>>(e_src, e_dst, p_cursor, p_csr);

    for (int i = 0; i < LL; i++) {
        dim3 g(4, (NN + 127) / 128);
        k_gemm_tc<0><<<g, 256, SMEM_TOTAL>>>(
            p_hnh, p_hnl,
            p_wbh + W_WL + (size_t)i * DD * DD, p_wbl + W_WL + (size_t)i * DD * DD,
            p_wbh + W_WR + (size_t)i * DD * DD, p_wbl + W_WR + (size_t)i * DD * DD,
            bl + i * DD, br + i * DD, NULL, NULL,
            NULL, p_xl, p_xr, NULL, NULL, NN, DD, DD, 0);
        k_gat<<<warpBlocks, 256>>>(p_xl, p_xr, p_rowptr, p_csr, att + i * DD,
                                   conv_b + i * DD, scales, p_w, i, p_h, p_hsum,
                                   ln_g + (i + 1 < LL ? (i + 1) * DD : 0),
                                   ln_b + (i + 1 < LL ? (i + 1) * DD : 0),
                                   p_hnh, p_hnl, p_hsh, p_hsl);
    }

    {
        dim3 g(2, (NN + 127) / 128);
        k_gemm_tc<3><<<g, 256, SMEM_TOTAL>>>(
            p_hsh, p_hsl, p_wbh + W_H1, p_wbl + W_H1, p_wbh + W_H1, p_wbl + W_H1,
            h1_b, h1_b, bn2_g, bn2_b, NULL, NULL, NULL, p_y1h, p_y1l,
            NN, DD, DD, DD);
        dim3 g2(1, (NN + 127) / 128);
        k_gemm_tc<2><<<g2, 256, SMEM_TOTAL>>>(
            p_y1h, p_y1l, p_wbh + W_H2, p_wbl + W_H2, p_wbh + W_H2, p_wbl + W_H2,
            h2_b, h2_b, NULL, NULL, p_y2, NULL, NULL, NULL, NULL,
            NN, DD, DD / 2, DD / 2);
    }
    k_final<<<warpBlocks, 256>>>(p_y2, h3_w, h3_b, out);
}

// round 7
// speedup vs baseline: 2.7146x; 1.1014x over previous
#include <cuda_runtime.h>
#include <cuda_bf16.h>
#include <cuda_fp16.h>
#include <stdint.h>
#include <math.h>

#define NN 50000
#define EE 800000
#define IND 128
#define DD 256
#define LL 6
#define EPSF 1e-5f
#define NB 196

// smem stage layout (bytes); A: 128 rows x 40 b16 stride; B: 32 rows x 136 b16 stride
#define AH_OFF 0
#define AL_OFF 10240
#define BH_OFF 20480
#define BL_OFF 29184
#define STAGE_BYTES 37888
#define NSTAGE 3
#define SMEM_TOTAL (NSTAGE * STAGE_BYTES)

// bf16 weight-split pool offsets (elements): win | h1 | h2
#define W_WIN 0
#define W_H1 32768
#define W_H2 98304
#define W_TOT 131072

// ---------------- scratch ----------------
__device__ __align__(16) float  d_h[(size_t)NN * DD];
__device__ __align__(16) __nv_bfloat16 d_xh[(size_t)NN * IND];
__device__ __align__(16) __nv_bfloat16 d_xlo[(size_t)NN * IND];
__device__ __align__(16) __half d_hnh[(size_t)NN * DD];
__device__ __align__(16) __half d_hnl[(size_t)NN * DD];
__device__ __align__(16) __half d_xl[(size_t)NN * DD];
__device__ __align__(16) float  d_xr[(size_t)NN * DD];
__device__ __align__(16) float  d_hsum[(size_t)NN * DD];
__device__ __align__(16) __nv_bfloat16 d_hsh[(size_t)NN * DD];
__device__ __align__(16) __nv_bfloat16 d_hsl[(size_t)NN * DD];
__device__ __align__(16) __nv_bfloat16 d_y1h[(size_t)NN * DD];
__device__ __align__(16) __nv_bfloat16 d_y1l[(size_t)NN * DD];
__device__ __align__(16) float  d_y2[(size_t)NN * (DD / 2)];
__device__ __align__(16) __nv_bfloat16 d_wbh[W_TOT];
__device__ __align__(16) __nv_bfloat16 d_wbl[W_TOT];
__device__ __align__(16) __half d_wlh[(size_t)LL * DD * DD];
__device__ __align__(16) __half d_wll[(size_t)LL * DD * DD];
__device__ __align__(16) __half d_wrh[(size_t)LL * DD * DD];
__device__ __align__(16) __half d_wrl[(size_t)LL * DD * DD];
__device__ int   d_rowptr[NN + 1];
__device__ int   d_deg[NN];
__device__ int   d_bsum[NB];
__device__ int   d_cursor[NN];
__device__ int   d_csrsrc[EE + NN];
__device__ float d_w[LL];

__device__ __forceinline__ float lrelu(float x, float a) { return x > 0.f ? x : a * x; }

// ---------------- tiny kernels ----------------
__global__ void k_softmax_w(const float* __restrict__ sw, float* __restrict__ w) {
    if (threadIdx.x == 0 && blockIdx.x == 0) {
        float m = -1e30f;
        for (int i = 0; i < LL; i++) m = fmaxf(m, sw[i]);
        float e[LL];
        float s = 0.f;
        for (int i = 0; i < LL; i++) { e[i] = __expf(sw[i] - m); s += e[i]; }
        for (int i = 0; i < LL; i++) w[i] = e[i] / s;
    }
}

// split fp32 -> bf16 hi/lo
__global__ void k_split(const float* __restrict__ in, __nv_bfloat16* __restrict__ hi,
                        __nv_bfloat16* __restrict__ lo, int n4) {
    int i = blockIdx.x * blockDim.x + threadIdx.x;
    if (i >= n4) return;
    float4 v = ((const float4*)in)[i];
    __nv_bfloat16 h[4];
    __nv_bfloat16 l[4];
    h[0] = __float2bfloat16(v.x); l[0] = __float2bfloat16(v.x - __bfloat162float(h[0]));
    h[1] = __float2bfloat16(v.y); l[1] = __float2bfloat16(v.y - __bfloat162float(h[1]));
    h[2] = __float2bfloat16(v.z); l[2] = __float2bfloat16(v.z - __bfloat162float(h[2]));
    h[3] = __float2bfloat16(v.w); l[3] = __float2bfloat16(v.w - __bfloat162float(h[3]));
    ((uint2*)hi)[i] = *(uint2*)h;
    ((uint2*)lo)[i] = *(uint2*)l;
}

// split two fp32 arrays -> fp16 hi/lo (Wl and Wr fused), n4each per array
__global__ void k_split2_h(const float* __restrict__ a, const float* __restrict__ b,
                           __half* __restrict__ ah, __half* __restrict__ al,
                           __half* __restrict__ bh, __half* __restrict__ bl, int n4each) {
    int i = blockIdx.x * blockDim.x + threadIdx.x;
    if (i >= 2 * n4each) return;
    const float* src = (i < n4each) ? a : b;
    __half* dh = (i < n4each) ? ah : bh;
    __half* dl = (i < n4each) ? al : bl;
    int j = (i < n4each) ? i : i - n4each;
    float4 v = ((const float4*)src)[j];
    __half h[4];
    __half l[4];
    h[0] = __float2half(v.x); l[0] = __float2half(v.x - __half2float(h[0]));
    h[1] = __float2half(v.y); l[1] = __float2half(v.y - __half2float(h[1]));
    h[2] = __float2half(v.z); l[2] = __float2half(v.z - __half2float(h[2]));
    h[3] = __float2half(v.w); l[3] = __float2half(v.w - __half2float(h[3]));
    ((uint2*)dh)[j] = *(uint2*)h;
    ((uint2*)dl)[j] = *(uint2*)l;
}

__global__ void k_deg_init(int* __restrict__ deg) {
    int i = blockIdx.x * blockDim.x + threadIdx.x;
    if (i < NN) deg[i] = 1;
}

__global__ void k_deg_count(const int* __restrict__ dst, int* __restrict__ deg) {
    int i = blockIdx.x * blockDim.x + threadIdx.x;
    if (i < EE) atomicAdd(&deg[dst[i]], 1);
}

__global__ void k_blocksum(const int* __restrict__ deg, int* __restrict__ bsum) {
    int i = blockIdx.x * 256 + threadIdx.x;
    int v = (i < NN) ? deg[i] : 0;
    int lane = threadIdx.x & 31;
    int wid = threadIdx.x >> 5;
    for (int d = 16; d; d >>= 1) v += __shfl_xor_sync(0xffffffffu, v, d);
    __shared__ int ws[8];
    if (lane == 0) ws[wid] = v;
    __syncthreads();
    if (threadIdx.x == 0) {
        int s = 0;
        for (int k = 0; k < 8; k++) s += ws[k];
        bsum[blockIdx.x] = s;
    }
}

__global__ void k_bscan(int* __restrict__ bsum) {
    int t = threadIdx.x;
    int v = (t < NB) ? bsum[t] : 0;
    int lane = t & 31;
    int wid = t >> 5;
    int x = v;
    for (int d = 1; d < 32; d <<= 1) {
        int u = __shfl_up_sync(0xffffffffu, x, d);
        if (lane >= d) x += u;
    }
    __shared__ int ws[8];
    if (lane == 31) ws[wid] = x;
    __syncthreads();
    if (wid == 0 && lane < 8) {
        int y = ws[lane];
        for (int d = 1; d < 8; d <<= 1) {
            int u = __shfl_up_sync(0xffu, y, d);
            if (lane >= d) y += u;
        }
        ws[lane] = y;
    }
    __syncthreads();
    int incl = x + (wid > 0 ? ws[wid - 1] : 0);
    if (t < NB) bsum[t] = incl - v;
}

// scan-out + self-loop + cursor init fused
__global__ void k_scanout(const int* __restrict__ deg, const int* __restrict__ boff,
                          int* __restrict__ rowptr, int* __restrict__ cursor,
                          int* __restrict__ csrsrc) {
    int t = threadIdx.x;
    int i = blockIdx.x * 256 + t;
    int v = (i < NN) ? deg[i] : 0;
    int lane = t & 31;
    int wid = t >> 5;
    int x = v;
    for (int d = 1; d < 32; d <<= 1) {
        int u = __shfl_up_sync(0xffffffffu, x, d);
        if (lane >= d) x += u;
    }
    __shared__ int ws[8];
    if (lane == 31) ws[wid] = x;
    __syncthreads();
    if (wid == 0 && lane < 8) {
        int y = ws[lane];
        for (int d = 1; d < 8; d <<= 1) {
            int u = __shfl_up_sync(0xffu, y, d);
            if (lane >= d) y += u;
        }
        ws[lane] = y;
    }
    __syncthreads();
    int excl = x - v + (wid > 0 ? ws[wid - 1] : 0) + boff[blockIdx.x];
    if (i < NN) {
        rowptr[i] = excl;
        csrsrc[excl] = i;      // self loop first
        cursor[i] = excl + 1;
    }
    if (i == 0) rowptr[NN] = EE + NN;
}

__global__ void k_scatter(const int* __restrict__ src, const int* __restrict__ dst,
                          int* __restrict__ cursor, int* __restrict__ csrsrc) {
    int i = blockIdx.x * blockDim.x + threadIdx.x;
    if (i < EE) {
        int p = atomicAdd(&cursor[dst[i]], 1);
        csrsrc[p] = src[i];
    }
}

// ---------------- layernorm (layer 0 only): fp32 in -> split fp16 out ----------------
__global__ __launch_bounds__(256) void k_layernorm(
    const float* __restrict__ h, const float* __restrict__ g,
    const float* __restrict__ b, __half* __restrict__ hnh,
    __half* __restrict__ hnl) {
    int v = (int)((blockIdx.x * blockDim.x + threadIdx.x) >> 5);
    if (v >= NN) return;
    int lane = threadIdx.x & 31;
    const float4* h4 = (const float4*)(h + (size_t)v * DD);
    float4 x0 = h4[2 * lane];
    float4 x1 = h4[2 * lane + 1];
    float s = x0.x + x0.y + x0.z + x0.w + x1.x + x1.y + x1.z + x1.w;
    float q = x0.x * x0.x + x0.y * x0.y + x0.z * x0.z + x0.w * x0.w
            + x1.x * x1.x + x1.y * x1.y + x1.z * x1.z + x1.w * x1.w;
    for (int d = 16; d; d >>= 1) {
        s += __shfl_xor_sync(0xffffffffu, s, d);
        q += __shfl_xor_sync(0xffffffffu, q, d);
    }
    float mu = s * (1.0f / 256.0f);
    float var = q * (1.0f / 256.0f) - mu * mu;
    float r = rsqrtf(var + EPSF);
    const float4* g4 = (const float4*)g;
    const float4* b4 = (const float4*)b;
    float4 g0 = __ldg(&g4[2 * lane]);
    float4 g1 = __ldg(&g4[2 * lane + 1]);
    float4 b0 = __ldg(&b4[2 * lane]);
    float4 b1 = __ldg(&b4[2 * lane + 1]);
    float o[8];
    o[0] = (x0.x - mu) * r * g0.x + b0.x;
    o[1] = (x0.y - mu) * r * g0.y + b0.y;
    o[2] = (x0.z - mu) * r * g0.z + b0.z;
    o[3] = (x0.w - mu) * r * g0.w + b0.w;
    o[4] = (x1.x - mu) * r * g1.x + b1.x;
    o[5] = (x1.y - mu) * r * g1.y + b1.y;
    o[6] = (x1.z - mu) * r * g1.z + b1.z;
    o[7] = (x1.w - mu) * r * g1.w + b1.w;
    __half ph[8];
    __half pl[8];
#pragma unroll
    for (int j = 0; j < 8; j++) {
        ph[j] = __float2half(o[j]);
        pl[j] = __float2half(o[j] - __half2float(ph[j]));
    }
    *(uint4*)(hnh + (size_t)v * DD + 8 * lane) = *(uint4*)ph;
    *(uint4*)(hnl + (size_t)v * DD + 8 * lane) = *(uint4*)pl;
}

// ---------------- tensor-core GEMM ----------------
__device__ __forceinline__ void cp16(unsigned int dst, const void* src, int srcsize) {
    asm volatile("cp.async.cg.shared.global [%0], [%1], 16, %2;"
                 :: "r"(dst), "l"(src), "r"(srcsize));
}

__device__ __forceinline__ void ldsm_x4(unsigned int* r, unsigned int addr) {
    asm volatile("ldmatrix.sync.aligned.m8n8.x4.shared.b16 {%0,%1,%2,%3}, [%4];"
                 : "=r"(r[0]), "=r"(r[1]), "=r"(r[2]), "=r"(r[3]) : "r"(addr));
}

__device__ __forceinline__ void ldsm_x4t(unsigned int* r, unsigned int addr) {
    asm volatile("ldmatrix.sync.aligned.m8n8.x4.trans.shared.b16 {%0,%1,%2,%3}, [%4];"
                 : "=r"(r[0]), "=r"(r[1]), "=r"(r[2]), "=r"(r[3]) : "r"(addr));
}

template <int FP16>
__device__ __forceinline__ void mma16(float* c, const unsigned int* a,
                                      const unsigned int* b) {
    if (FP16) {
        asm volatile(
            "mma.sync.aligned.m16n8k16.row.col.f32.f16.f16.f32 "
            "{%0,%1,%2,%3}, {%4,%5,%6,%7}, {%8,%9}, {%0,%1,%2,%3};"
            : "+f"(c[0]), "+f"(c[1]), "+f"(c[2]), "+f"(c[3])
            : "r"(a[0]), "r"(a[1]), "r"(a[2]), "r"(a[3]), "r"(b[0]), "r"(b[1]));
    } else {
        asm volatile(
            "mma.sync.aligned.m16n8k16.row.col.f32.bf16.bf16.f32 "
            "{%0,%1,%2,%3}, {%4,%5,%6,%7}, {%8,%9}, {%0,%1,%2,%3};"
            : "+f"(c[0]), "+f"(c[1]), "+f"(c[2]), "+f"(c[3])
            : "r"(a[0]), "r"(a[1]), "r"(a[2]), "r"(a[3]), "r"(b[0]), "r"(b[1]));
    }
}

template <int LOADBL>
__device__ __forceinline__ void issue_stage(
    const __nv_bfloat16* __restrict__ Ah, const __nv_bfloat16* __restrict__ Al,
    const __nv_bfloat16* __restrict__ Bh, const __nv_bfloat16* __restrict__ Bl,
    unsigned int sdst, int bm, int bn_l, int M, int K, int ldb, int tid, int kk) {
#pragma unroll
    for (int u = 0; u < 2; u++) {
        int c = tid + u * 256;
        int row = c >> 2;
        int seg = c & 3;
        int gr = bm + row;
        size_t go = (size_t)gr * K + kk + seg * 8;
        unsigned int dd = sdst + AH_OFF + row * 80 + seg * 16;
        int p = (gr < M) ? 16 : 0;
        cp16(dd, Ah + go, p);
        cp16(dd + (AL_OFF - AH_OFF), Al + go, p);
    }
#pragma unroll
    for (int u = 0; u < 2; u++) {
        int c = tid + u * 256;
        int row = c >> 4;
        int seg = c & 15;
        size_t go = (size_t)(kk + row) * ldb + bn_l + seg * 8;
        unsigned int dd = sdst + BH_OFF + row * 272 + seg * 16;
        cp16(dd, Bh + go, 16);
        if (LOADBL) cp16(dd + (BL_OFF - BH_OFF), Bl + go, 16);
    }
}

template <int FP16, int NT>
__device__ __forceinline__ void tile_mma(unsigned int stg, int wm0, int wn0,
                                         int aRow, int aKof, int bRow, int bNof,
                                         float acc[4][4][4]) {
#pragma unroll
    for (int ks = 0; ks < 32; ks += 16) {
        unsigned int ah[4][4];
        unsigned int al[4][4];
        unsigned int bh[4][2];
        unsigned int bl[4][2];
#pragma unroll
        for (int mi = 0; mi < 4; mi++) {
            unsigned int ad = stg + AH_OFF
                + (unsigned int)((wm0 + mi * 16 + aRow) * 40 + ks + aKof) * 2u;
            ldsm_x4(ah[mi], ad);
            ldsm_x4(al[mi], ad + (AL_OFF - AH_OFF));
        }
#pragma unroll
        for (int np = 0; np < 2; np++) {
            unsigned int bd = stg + BH_OFF
                + (unsigned int)((ks + bRow) * 136 + wn0 + np * 16 + bNof) * 2u;
            unsigned int tb[4];
            ldsm_x4t(tb, bd);
            bh[np * 2][0] = tb[0];
            bh[np * 2][1] = tb[1];
            bh[np * 2 + 1][0] = tb[2];
            bh[np * 2 + 1][1] = tb[3];
            if (NT == 3) {
                ldsm_x4t(tb, bd + (BL_OFF - BH_OFF));
                bl[np * 2][0] = tb[0];
                bl[np * 2][1] = tb[1];
                bl[np * 2 + 1][0] = tb[2];
                bl[np * 2 + 1][1] = tb[3];
            }
        }
#pragma unroll
        for (int mi = 0; mi < 4; mi++) {
#pragma unroll
            for (int ni = 0; ni < 4; ni++) {
                mma16<FP16>(acc[mi][ni], ah[mi], bh[ni]);
                mma16<FP16>(acc[mi][ni], al[mi], bh[ni]);
                if (NT == 3) mma16<FP16>(acc[mi][ni], ah[mi], bl[ni]);
            }
        }
    }
}

// EPI 0: layer -> xl(half,<256)/xr(float,>=256). EPI 1: bn+lrelu -> C fp32.
// EPI 2: lrelu -> C fp32. EPI 3: bn+lrelu -> split bf16 (Coh/Col).
template <int EPI, int FP16, int NT>
__global__ __launch_bounds__(256, 2) void k_gemm_tc(
    const __nv_bfloat16* __restrict__ Ah, const __nv_bfloat16* __restrict__ Al,
    const __nv_bfloat16* __restrict__ B0h, const __nv_bfloat16* __restrict__ B0l,
    const __nv_bfloat16* __restrict__ B1h, const __nv_bfloat16* __restrict__ B1l,
    const float* __restrict__ bias0, const float* __restrict__ bias1,
    const float* __restrict__ bng, const float* __restrict__ bnb,
    float* __restrict__ C, __half* __restrict__ Cxl, float* __restrict__ Cxr,
    __nv_bfloat16* __restrict__ Coh, __nv_bfloat16* __restrict__ Col,
    int M, int K, int ldb, int ldc) {
    extern __shared__ char smem[];
    const int tid = threadIdx.x;
    const int lane = tid & 31;
    const int wid = tid >> 5;
    const int bm = blockIdx.y * 128;
    const int bn = blockIdx.x * 128;
    const __nv_bfloat16* Bh = (bn < 256) ? B0h : B1h;
    const __nv_bfloat16* Bl = (bn < 256) ? B0l : B1l;
    const float* biasp = (bn < 256) ? bias0 : bias1;
    const int bn_l = bn & 255;
    const int wm0 = (wid & 1) * 64;
    const int wn0 = (wid >> 1) * 32;
    unsigned int sbase = (unsigned int)__cvta_generic_to_shared(smem);

    float acc[4][4][4];
#pragma unroll
    for (int i = 0; i < 4; i++) {
#pragma unroll
        for (int j = 0; j < 4; j++) {
#pragma unroll
            for (int k = 0; k < 4; k++) acc[i][j][k] = 0.f;
        }
    }

    const int grp = lane & 7;
    const int seg = lane >> 3;
    const int aRow = (seg & 1) * 8 + grp;
    const int aKof = (seg >> 1) * 8;
    const int bRow = (seg & 1) * 8 + grp;
    const int bNof = (seg >> 1) * 8;

    int nk = K / 32;
    issue_stage<NT == 3>(Ah, Al, Bh, Bl, sbase, bm, bn_l, M, K, ldb, tid, 0);
    asm volatile("cp.async.commit_group;");
    issue_stage<NT == 3>(Ah, Al, Bh, Bl, sbase + STAGE_BYTES, bm, bn_l, M, K, ldb, tid, 32);
    asm volatile("cp.async.commit_group;");

    for (int t = 0; t < nk; t++) {
        asm volatile("cp.async.wait_group 1;");
        __syncthreads();
        int sidx = t % NSTAGE;
        tile_mma<FP16, NT>(sbase + (unsigned int)sidx * STAGE_BYTES,
                           wm0, wn0, aRow, aKof, bRow, bNof, acc);
        if (t + 2 < nk) {
            issue_stage<NT == 3>(Ah, Al, Bh, Bl,
                                 sbase + (unsigned int)((t + 2) % NSTAGE) * STAGE_BYTES,
                                 bm, bn_l, M, K, ldb, tid, (t + 2) * 32);
        }
        asm volatile("cp.async.commit_group;");
    }

    const float rsb = rsqrtf(1.0f + EPSF);
    const int cg = lane >> 2;
    const int cc = lane & 3;
#pragma unroll
    for (int mi = 0; mi < 4; mi++) {
        int r0 = bm + wm0 + mi * 16 + cg;
#pragma unroll
        for (int ni = 0; ni < 4; ni++) {
            int colL = wn0 + ni * 8 + 2 * cc;
            int colB = bn_l + colL;
            float b0v = __ldg(&biasp[colB]);
            float b1v = __ldg(&biasp[colB + 1]);
            float v0 = acc[mi][ni][0] + b0v;
            float v1 = acc[mi][ni][1] + b1v;
            float v2 = acc[mi][ni][2] + b0v;
            float v3 = acc[mi][ni][3] + b1v;
            if (EPI == 0) {
                if (bn < 256) {
                    if (r0 < M)
                        *(__half2*)(Cxl + (size_t)r0 * DD + colB) = __floats2half2_rn(v0, v1);
                    if (r0 + 8 < M)
                        *(__half2*)(Cxl + (size_t)(r0 + 8) * DD + colB) = __floats2half2_rn(v2, v3);
                } else {
                    if (r0 < M)
                        *(float2*)(Cxr + (size_t)r0 * DD + colB) = make_float2(v0, v1);
                    if (r0 + 8 < M)
                        *(float2*)(Cxr + (size_t)(r0 + 8) * DD + colB) = make_float2(v2, v3);
                }
            } else {
                if (EPI == 1 || EPI == 3) {
                    float g0 = __ldg(&bng[colB]);
                    float g1 = __ldg(&bng[colB + 1]);
                    float q0 = __ldg(&bnb[colB]);
                    float q1 = __ldg(&bnb[colB + 1]);
                    v0 = lrelu(v0 * rsb * g0 + q0, 0.1f);
                    v1 = lrelu(v1 * rsb * g1 + q1, 0.1f);
                    v2 = lrelu(v2 * rsb * g0 + q0, 0.1f);
                    v3 = lrelu(v3 * rsb * g1 + q1, 0.1f);
                }
                if (EPI == 2) {
                    v0 = lrelu(v0, 0.1f);
                    v1 = lrelu(v1, 0.1f);
                    v2 = lrelu(v2, 0.1f);
                    v3 = lrelu(v3, 0.1f);
                }
                int col = bn + colL;
                if (EPI == 3) {
                    __nv_bfloat16 h0 = __float2bfloat16(v0);
                    __nv_bfloat16 h1 = __float2bfloat16(v1);
                    __nv_bfloat16 h2 = __float2bfloat16(v2);
                    __nv_bfloat16 h3 = __float2bfloat16(v3);
                    __nv_bfloat16 l0 = __float2bfloat16(v0 - __bfloat162float(h0));
                    __nv_bfloat16 l1 = __float2bfloat16(v1 - __bfloat162float(h1));
                    __nv_bfloat16 l2 = __float2bfloat16(v2 - __bfloat162float(h2));
                    __nv_bfloat16 l3 = __float2bfloat16(v3 - __bfloat162float(h3));
                    if (r0 < M) {
                        __nv_bfloat16 th[2] = {h0, h1};
                        __nv_bfloat16 tl[2] = {l0, l1};
                        *(unsigned int*)(Coh + (size_t)r0 * ldc + col) = *(unsigned int*)th;
                        *(unsigned int*)(Col + (size_t)r0 * ldc + col) = *(unsigned int*)tl;
                    }
                    if (r0 + 8 < M) {
                        __nv_bfloat16 th[2] = {h2, h3};
                        __nv_bfloat16 tl[2] = {l2, l3};
                        *(unsigned int*)(Coh + (size_t)(r0 + 8) * ldc + col) = *(unsigned int*)th;
                        *(unsigned int*)(Col + (size_t)(r0 + 8) * ldc + col) = *(unsigned int*)tl;
                    }
                } else {
                    if (r0 < M)
                        *(float2*)(C + (size_t)r0 * ldc + col) = make_float2(v0, v1);
                    if (r0 + 8 < M)
                        *(float2*)(C + (size_t)(r0 + 8) * ldc + col) = make_float2(v2, v3);
                }
            }
        }
    }
}

// ---------------- GATv2 aggregation + residual + fused next-layer LN (fp16 split out) ----------------
__global__ __launch_bounds__(256) void k_gat(
    const __half* __restrict__ xl, const float* __restrict__ xr,
    const int* __restrict__ rowptr, const int* __restrict__ csrsrc,
    const float* __restrict__ att, const float* __restrict__ convb,
    const float* __restrict__ scales, const float* __restrict__ wvec, int li,
    float* __restrict__ h, float* __restrict__ hsum,
    const float* __restrict__ lng, const float* __restrict__ lnb,
    __half* __restrict__ hnh, __half* __restrict__ hnl,
    __nv_bfloat16* __restrict__ hsh, __nv_bfloat16* __restrict__ hsl) {
    int v = (int)((blockIdx.x * blockDim.x + threadIdx.x) >> 5);
    if (v >= NN) return;
    int lane = threadIdx.x & 31;

    const float4* att4 = (const float4*)att;
    float4 a0 = __ldg(&att4[2 * lane]);
    float4 a1 = __ldg(&att4[2 * lane + 1]);
    const float4* xr4 = (const float4*)(xr + (size_t)v * DD);
    float4 r0 = __ldg(&xr4[2 * lane]);
    float4 r1 = __ldg(&xr4[2 * lane + 1]);

    float m = -1e30f;
    float den = 0.f;
    float acc[8];
#pragma unroll
    for (int j = 0; j < 8; j++) acc[j] = 0.f;

    int e1 = __ldg(&rowptr[v + 1]);
    for (int e = __ldg(&rowptr[v]); e < e1; e++) {
        int s = __ldg(&csrsrc[e]);
        uint4 raw = __ldg((const uint4*)(xl + (size_t)s * DD) + lane);
        const __half2* hp = (const __half2*)&raw;
        float2 f0 = __half22float2(hp[0]);
        float2 f1 = __half22float2(hp[1]);
        float2 f2 = __half22float2(hp[2]);
        float2 f3 = __half22float2(hp[3]);
        float p = 0.f;
        p = fmaf(lrelu(f0.x + r0.x, 0.2f), a0.x, p);
        p = fmaf(lrelu(f0.y + r0.y, 0.2f), a0.y, p);
        p = fmaf(lrelu(f1.x + r0.z, 0.2f), a0.z, p);
        p = fmaf(lrelu(f1.y + r0.w, 0.2f), a0.w, p);
        p = fmaf(lrelu(f2.x + r1.x, 0.2f), a1.x, p);
        p = fmaf(lrelu(f2.y + r1.y, 0.2f), a1.y, p);
        p = fmaf(lrelu(f3.x + r1.z, 0.2f), a1.z, p);
        p = fmaf(lrelu(f3.y + r1.w, 0.2f), a1.w, p);
        p += __shfl_xor_sync(0xffffffffu, p, 1);
        p += __shfl_xor_sync(0xffffffffu, p, 2);
        float nm = fmaxf(m, p);
        float sc = __expf(m - nm);
        float ep = __expf(p - nm);
        den = den * sc + ep;
        acc[0] = acc[0] * sc + f0.x * ep;
        acc[1] = acc[1] * sc + f0.y * ep;
        acc[2] = acc[2] * sc + f1.x * ep;
        acc[3] = acc[3] * sc + f1.y * ep;
        acc[4] = acc[4] * sc + f2.x * ep;
        acc[5] = acc[5] * sc + f2.y * ep;
        acc[6] = acc[6] * sc + f3.x * ep;
        acc[7] = acc[7] * sc + f3.y * ep;
        m = nm;
    }

    const float4* cb4 = (const float4*)convb;
    float4 cb0 = __ldg(&cb4[2 * lane]);
    float4 cb1 = __ldg(&cb4[2 * lane + 1]);
    float sci = __ldg(&scales[li]);
    float wi = __ldg(&wvec[li]);
    float4* h4 = (float4*)(h + (size_t)v * DD);
    float4 res0 = h4[2 * lane];
    float4 res1 = h4[2 * lane + 1];
    float id = 1.0f / den;
    float nh[8];
    nh[0] = res0.x + sci * lrelu(acc[0] * id + cb0.x, 0.1f);
    nh[1] = res0.y + sci * lrelu(acc[1] * id + cb0.y, 0.1f);
    nh[2] = res0.z + sci * lrelu(acc[2] * id + cb0.z, 0.1f);
    nh[3] = res0.w + sci * lrelu(acc[3] * id + cb0.w, 0.1f);
    nh[4] = res1.x + sci * lrelu(acc[4] * id + cb1.x, 0.1f);
    nh[5] = res1.y + sci * lrelu(acc[5] * id + cb1.y, 0.1f);
    nh[6] = res1.z + sci * lrelu(acc[6] * id + cb1.z, 0.1f);
    nh[7] = res1.w + sci * lrelu(acc[7] * id + cb1.w, 0.1f);
    h4[2 * lane] = make_float4(nh[0], nh[1], nh[2], nh[3]);
    h4[2 * lane + 1] = make_float4(nh[4], nh[5], nh[6], nh[7]);

    float4* hs4 = (float4*)(hsum + (size_t)v * DD);
    float4 sa, sb;
    if (li == 0) {
        sa = make_float4(0.f, 0.f, 0.f, 0.f);
        sb = make_float4(0.f, 0.f, 0.f, 0.f);
    } else {
        sa = hs4[2 * lane];
        sb = hs4[2 * lane + 1];
    }
    sa.x += wi * nh[0]; sa.y += wi * nh[1]; sa.z += wi * nh[2]; sa.w += wi * nh[3];
    sb.x += wi * nh[4]; sb.y += wi * nh[5]; sb.z += wi * nh[6]; sb.w += wi * nh[7];
    hs4[2 * lane] = sa;
    hs4[2 * lane + 1] = sb;

    if (li < LL - 1) {
        float s = 0.f;
        float q = 0.f;
#pragma unroll
        for (int j = 0; j < 8; j++) {
            s += nh[j];
            q += nh[j] * nh[j];
        }
        for (int d = 16; d; d >>= 1) {
            s += __shfl_xor_sync(0xffffffffu, s, d);
            q += __shfl_xor_sync(0xffffffffu, q, d);
        }
        float mu = s * (1.0f / 256.0f);
        float var = q * (1.0f / 256.0f) - mu * mu;
        float rr = rsqrtf(var + EPSF);
        const float4* g4 = (const float4*)lng;
        const float4* b4 = (const float4*)lnb;
        float4 g0 = __ldg(&g4[2 * lane]);
        float4 g1 = __ldg(&g4[2 * lane + 1]);
        float4 bb0 = __ldg(&b4[2 * lane]);
        float4 bb1 = __ldg(&b4[2 * lane + 1]);
        float o[8];
        o[0] = (nh[0] - mu) * rr * g0.x + bb0.x;
        o[1] = (nh[1] - mu) * rr * g0.y + bb0.y;
        o[2] = (nh[2] - mu) * rr * g0.z + bb0.z;
        o[3] = (nh[3] - mu) * rr * g0.w + bb0.w;
        o[4] = (nh[4] - mu) * rr * g1.x + bb1.x;
        o[5] = (nh[5] - mu) * rr * g1.y + bb1.y;
        o[6] = (nh[6] - mu) * rr * g1.z + bb1.z;
        o[7] = (nh[7] - mu) * rr * g1.w + bb1.w;
        __half ph[8];
        __half pl[8];
#pragma unroll
        for (int j = 0; j < 8; j++) {
            ph[j] = __float2half(o[j]);
            pl[j] = __float2half(o[j] - __half2float(ph[j]));
        }
        *(uint4*)(hnh + (size_t)v * DD + 8 * lane) = *(uint4*)ph;
        *(uint4*)(hnl + (size_t)v * DD + 8 * lane) = *(uint4*)pl;
    } else {
        float sv[8];
        sv[0] = sa.x; sv[1] = sa.y; sv[2] = sa.z; sv[3] = sa.w;
        sv[4] = sb.x; sv[5] = sb.y; sv[6] = sb.z; sv[7] = sb.w;
        __nv_bfloat16 ph[8];
        __nv_bfloat16 pl[8];
#pragma unroll
        for (int j = 0; j < 8; j++) {
            ph[j] = __float2bfloat16(sv[j]);
            pl[j] = __float2bfloat16(sv[j] - __bfloat162float(ph[j]));
        }
        *(uint4*)(hsh + (size_t)v * DD + 8 * lane) = *(uint4*)ph;
        *(uint4*)(hsl + (size_t)v * DD + 8 * lane) = *(uint4*)pl;
    }
}

// ---------------- final projection ----------------
__global__ __launch_bounds__(256) void k_final(
    const float* __restrict__ y2, const float* __restrict__ w,
    const float* __restrict__ b, float* __restrict__ out) {
    int v = (int)((blockIdx.x * blockDim.x + threadIdx.x) >> 5);
    if (v >= NN) return;
    int lane = threadIdx.x & 31;
    const float4* y4 = (const float4*)y2;
    const float4* w4 = (const float4*)w;
    float4 a = y4[v * 32 + lane];
    float4 ww = __ldg(&w4[lane]);
    float p = a.x * ww.x + a.y * ww.y + a.z * ww.z + a.w * ww.w;
    for (int d = 16; d; d >>= 1) p += __shfl_xor_sync(0xffffffffu, p, d);
    if (lane == 0) out[v] = p + __ldg(&b[0]);
}

// ---------------- launcher ----------------
extern "C" void kernel_launch(void* const* d_in, const int* in_sizes, int n_in,
                              void* d_out, int out_size) {
    (void)in_sizes; (void)n_in; (void)out_size;
    const float* x      = (const float*)d_in[0];
    const int*   ei     = (const int*)d_in[1];
    const float* win_w  = (const float*)d_in[2];
    const float* win_b  = (const float*)d_in[3];
    const float* bn1_g  = (const float*)d_in[4];
    const float* bn1_b  = (const float*)d_in[5];
    const float* ln_g   = (const float*)d_in[6];
    const float* ln_b   = (const float*)d_in[7];
    const float* Wl     = (const float*)d_in[8];
    const float* bl     = (const float*)d_in[9];
    const float* Wr     = (const float*)d_in[10];
    const float* br     = (const float*)d_in[11];
    const float* att    = (const float*)d_in[12];
    const float* conv_b = (const float*)d_in[13];
    const float* scales = (const float*)d_in[14];
    const float* sw     = (const float*)d_in[15];
    const float* h1_w   = (const float*)d_in[16];
    const float* h1_b   = (const float*)d_in[17];
    const float* bn2_g  = (const float*)d_in[18];
    const float* bn2_b  = (const float*)d_in[19];
    const float* h2_w   = (const float*)d_in[20];
    const float* h2_b   = (const float*)d_in[21];
    const float* h3_w   = (const float*)d_in[22];
    const float* h3_b   = (const float*)d_in[23];
    float* out = (float*)d_out;

    float *p_h, *p_xr, *p_hsum, *p_y2, *p_w;
    __half *p_xl, *p_hnh, *p_hnl, *p_wlh, *p_wll, *p_wrh, *p_wrl;
    __nv_bfloat16 *p_xh, *p_xlo, *p_hsh, *p_hsl, *p_y1h, *p_y1l, *p_wbh, *p_wbl;
    int *p_rowptr, *p_deg, *p_bsum, *p_cursor, *p_csr;
    cudaGetSymbolAddress((void**)&p_h, d_h);
    cudaGetSymbolAddress((void**)&p_xh, d_xh);
    cudaGetSymbolAddress((void**)&p_xlo, d_xlo);
    cudaGetSymbolAddress((void**)&p_hnh, d_hnh);
    cudaGetSymbolAddress((void**)&p_hnl, d_hnl);
    cudaGetSymbolAddress((void**)&p_xl, d_xl);
    cudaGetSymbolAddress((void**)&p_xr, d_xr);
    cudaGetSymbolAddress((void**)&p_hsum, d_hsum);
    cudaGetSymbolAddress((void**)&p_hsh, d_hsh);
    cudaGetSymbolAddress((void**)&p_hsl, d_hsl);
    cudaGetSymbolAddress((void**)&p_y1h, d_y1h);
    cudaGetSymbolAddress((void**)&p_y1l, d_y1l);
    cudaGetSymbolAddress((void**)&p_y2, d_y2);
    cudaGetSymbolAddress((void**)&p_wbh, d_wbh);
    cudaGetSymbolAddress((void**)&p_wbl, d_wbl);
    cudaGetSymbolAddress((void**)&p_wlh, d_wlh);
    cudaGetSymbolAddress((void**)&p_wll, d_wll);
    cudaGetSymbolAddress((void**)&p_wrh, d_wrh);
    cudaGetSymbolAddress((void**)&p_wrl, d_wrl);
    cudaGetSymbolAddress((void**)&p_w, d_w);
    cudaGetSymbolAddress((void**)&p_rowptr, d_rowptr);
    cudaGetSymbolAddress((void**)&p_deg, d_deg);
    cudaGetSymbolAddress((void**)&p_bsum, d_bsum);
    cudaGetSymbolAddress((void**)&p_cursor, d_cursor);
    cudaGetSymbolAddress((void**)&p_csr, d_csrsrc);

    cudaFuncSetAttribute(k_gemm_tc<0, 1, 2>, cudaFuncAttributeMaxDynamicSharedMemorySize, SMEM_TOTAL);
    cudaFuncSetAttribute(k_gemm_tc<1, 0, 3>, cudaFuncAttributeMaxDynamicSharedMemorySize, SMEM_TOTAL);
    cudaFuncSetAttribute(k_gemm_tc<2, 0, 3>, cudaFuncAttributeMaxDynamicSharedMemorySize, SMEM_TOTAL);
    cudaFuncSetAttribute(k_gemm_tc<3, 0, 3>, cudaFuncAttributeMaxDynamicSharedMemorySize, SMEM_TOTAL);

    const int* e_src = ei;
    const int* e_dst = ei + EE;
    const int warpBlocks = (NN * 32 + 255) / 256;

    // launches 0-3: the 4th launch (idx 3) is what ncu profiles
    {
        int n4 = NN * IND / 4;
        k_split<<<(n4 + 255) / 256, 256>>>(x, p_xh, p_xlo, n4);            // 0
    }
    {
        int n4 = IND * DD / 4;
        k_split<<<(n4 + 255) / 256, 256>>>(win_w, p_wbh + W_WIN, p_wbl + W_WIN, n4);  // 1
    }
    {
        int n4e = LL * DD * DD / 4;
        k_split2_h<<<(2 * n4e + 255) / 256, 256>>>(Wl, Wr, p_wlh, p_wll,
                                                   p_wrh, p_wrl, n4e);     // 2
    }
    {
        dim3 g(2, (NN + 127) / 128);                                       // 3: PROFILED
        k_gemm_tc<1, 0, 3><<<g, 256, SMEM_TOTAL>>>(
            p_xh, p_xlo, p_wbh + W_WIN, p_wbl + W_WIN, p_wbh + W_WIN, p_wbl + W_WIN,
            win_b, win_b, bn1_g, bn1_b, p_h, NULL, NULL, NULL, NULL,
            NN, IND, DD, DD);
    }
    {
        int n4 = DD * DD / 4;
        k_split<<<(n4 + 255) / 256, 256>>>(h1_w, p_wbh + W_H1, p_wbl + W_H1, n4);
    }
    {
        int n4 = DD * (DD / 2) / 4;
        k_split<<<(n4 + 255) / 256, 256>>>(h2_w, p_wbh + W_H2, p_wbl + W_H2, n4);
    }
    k_softmax_w<<<1, 32>>>(sw, p_w);
    k_layernorm<<<warpBlocks, 256>>>(p_h, ln_g, ln_b, p_hnh, p_hnl);

    k_deg_init<<<(NN + 255) / 256, 256>>>(p_deg);
    k_deg_count<<<(EE + 255) / 256, 256>>>(e_dst, p_deg);
    k_blocksum<<<NB, 256>>>(p_deg, p_bsum);
    k_bscan<<<1, 256>>>(p_bsum);
    k_scanout<<<NB, 256>>>(p_deg, p_bsum, p_rowptr, p_cursor, p_csr);
    k_scatter<<<(EE + 255) / 256, 256>>>(e_src, e_dst, p_cursor, p_csr);

    for (int i = 0; i < LL; i++) {
        dim3 g(4, (NN + 127) / 128);
        k_gemm_tc<0, 1, 2><<<g, 256, SMEM_TOTAL>>>(
            (const __nv_bfloat16*)p_hnh, (const __nv_bfloat16*)p_hnl,
            (const __nv_bfloat16*)(p_wlh + (size_t)i * DD * DD), NULL,
            (const __nv_bfloat16*)(p_wrh + (size_t)i * DD * DD), NULL,
            bl + i * DD, br + i * DD, NULL, NULL,
            NULL, p_xl, p_xr, NULL, NULL, NN, DD, DD, 0);
        k_gat<<<warpBlocks, 256>>>(p_xl, p_xr, p_rowptr, p_csr, att + i * DD,
                                   conv_b + i * DD, scales, p_w, i, p_h, p_hsum,
                                   ln_g + (i + 1 < LL ? (i + 1) * DD : 0),
                                   ln_b + (i + 1 < LL ? (i + 1) * DD : 0),
                                   p_hnh, p_hnl, p_hsh, p_hsl);
    }

    {
        dim3 g(2, (NN + 127) / 128);
        k_gemm_tc<3, 0, 3><<<g, 256, SMEM_TOTAL>>>(
            p_hsh, p_hsl, p_wbh + W_H1, p_wbl + W_H1, p_wbh + W_H1, p_wbl + W_H1,
            h1_b, h1_b, bn2_g, bn2_b, NULL, NULL, NULL, p_y1h, p_y1l,
            NN, DD, DD, DD);
        dim3 g2(1, (NN + 127) / 128);
        k_gemm_tc<2, 0, 3><<<g2, 256, SMEM_TOTAL>>>(
            p_y1h, p_y1l, p_wbh + W_H2, p_wbl + W_H2, p_wbh + W_H2, p_wbl + W_H2,
            h2_b, h2_b, NULL, NULL, p_y2, NULL, NULL, NULL, NULL,
            NN, DD, DD / 2, DD / 2);
    }
    k_final<<<warpBlocks, 256>>>(p_y2, h3_w, h3_b, out);
}

// round 8
// speedup vs baseline: 3.0959x; 1.1404x over previous
#include <cuda_runtime.h>
#include <cuda_bf16.h>
#include <cuda_fp16.h>
#include <stdint.h>
#include <math.h>

#define NN 50000
#define EE 800000
#define IND 128
#define DD 256
#define LL 6
#define EPSF 1e-5f
#define NB 196

// smem stage layout (bytes); A: 128 rows x 40 b16 stride; B: 32 rows x 136 b16 stride
#define AH_OFF 0
#define AL_OFF 10240
#define BH_OFF 20480
#define BL_OFF 29184
#define STAGE_BYTES 37888
#define NSTAGE 3
#define SMEM_TOTAL (NSTAGE * STAGE_BYTES)

// bf16 weight-split pool offsets (elements): win | h1 | h2
#define W_WIN 0
#define W_H1 32768
#define W_H2 98304
#define W_TOT 131072

// ---------------- scratch ----------------
__device__ __align__(16) float  d_h[(size_t)NN * DD];
__device__ __align__(16) __nv_bfloat16 d_xh[(size_t)NN * IND];
__device__ __align__(16) __nv_bfloat16 d_xlo[(size_t)NN * IND];
__device__ __align__(16) __half d_hnh[(size_t)NN * DD];
__device__ __align__(16) __half d_xl[(size_t)NN * DD];
__device__ __align__(16) float  d_xr[(size_t)NN * DD];
__device__ __align__(16) float  d_hsum[(size_t)NN * DD];
__device__ __align__(16) __nv_bfloat16 d_hsh[(size_t)NN * DD];
__device__ __align__(16) __nv_bfloat16 d_hsl[(size_t)NN * DD];
__device__ __align__(16) __nv_bfloat16 d_y1h[(size_t)NN * DD];
__device__ __align__(16) __nv_bfloat16 d_y1l[(size_t)NN * DD];
__device__ __align__(16) float  d_y2[(size_t)NN * (DD / 2)];
__device__ __align__(16) __nv_bfloat16 d_wbh[W_TOT];
__device__ __align__(16) __nv_bfloat16 d_wbl[W_TOT];
__device__ __align__(16) __half d_wlh[(size_t)LL * DD * DD];
__device__ __align__(16) __half d_wrh[(size_t)LL * DD * DD];
__device__ int   d_rowptr[NN + 1];
__device__ int   d_deg[NN];
__device__ int   d_bsum[NB];
__device__ int   d_cursor[NN];
__device__ int   d_csrsrc[EE + NN];
__device__ float d_w[LL];

__device__ __forceinline__ float lrelu(float x, float a) { return x > 0.f ? x : a * x; }

// ---------------- tiny kernels ----------------
__global__ void k_softmax_w(const float* __restrict__ sw, float* __restrict__ w) {
    if (threadIdx.x == 0 && blockIdx.x == 0) {
        float m = -1e30f;
        for (int i = 0; i < LL; i++) m = fmaxf(m, sw[i]);
        float e[LL];
        float s = 0.f;
        for (int i = 0; i < LL; i++) { e[i] = __expf(sw[i] - m); s += e[i]; }
        for (int i = 0; i < LL; i++) w[i] = e[i] / s;
    }
}

// split fp32 -> bf16 hi/lo
__global__ void k_split(const float* __restrict__ in, __nv_bfloat16* __restrict__ hi,
                        __nv_bfloat16* __restrict__ lo, int n4) {
    int i = blockIdx.x * blockDim.x + threadIdx.x;
    if (i >= n4) return;
    float4 v = ((const float4*)in)[i];
    __nv_bfloat16 h[4];
    __nv_bfloat16 l[4];
    h[0] = __float2bfloat16(v.x); l[0] = __float2bfloat16(v.x - __bfloat162float(h[0]));
    h[1] = __float2bfloat16(v.y); l[1] = __float2bfloat16(v.y - __bfloat162float(h[1]));
    h[2] = __float2bfloat16(v.z); l[2] = __float2bfloat16(v.z - __bfloat162float(h[2]));
    h[3] = __float2bfloat16(v.w); l[3] = __float2bfloat16(v.w - __bfloat162float(h[3]));
    ((uint2*)hi)[i] = *(uint2*)h;
    ((uint2*)lo)[i] = *(uint2*)l;
}

// convert two fp32 arrays -> fp16 (hi only; Wl and Wr fused)
__global__ void k_cvt2_h(const float* __restrict__ a, const float* __restrict__ b,
                         __half* __restrict__ ah, __half* __restrict__ bh, int n4each) {
    int i = blockIdx.x * blockDim.x + threadIdx.x;
    if (i >= 2 * n4each) return;
    const float* src = (i < n4each) ? a : b;
    __half* dh = (i < n4each) ? ah : bh;
    int j = (i < n4each) ? i : i - n4each;
    float4 v = ((const float4*)src)[j];
    __half h[4];
    h[0] = __float2half(v.x);
    h[1] = __float2half(v.y);
    h[2] = __float2half(v.z);
    h[3] = __float2half(v.w);
    ((uint2*)dh)[j] = *(uint2*)h;
}

__global__ void k_deg_init(int* __restrict__ deg) {
    int i = blockIdx.x * blockDim.x + threadIdx.x;
    if (i < NN) deg[i] = 1;
}

__global__ void k_deg_count(const int* __restrict__ dst, int* __restrict__ deg) {
    int i = blockIdx.x * blockDim.x + threadIdx.x;
    if (i < EE) atomicAdd(&deg[dst[i]], 1);
}

__global__ void k_blocksum(const int* __restrict__ deg, int* __restrict__ bsum) {
    int i = blockIdx.x * 256 + threadIdx.x;
    int v = (i < NN) ? deg[i] : 0;
    int lane = threadIdx.x & 31;
    int wid = threadIdx.x >> 5;
    for (int d = 16; d; d >>= 1) v += __shfl_xor_sync(0xffffffffu, v, d);
    __shared__ int ws[8];
    if (lane == 0) ws[wid] = v;
    __syncthreads();
    if (threadIdx.x == 0) {
        int s = 0;
        for (int k = 0; k < 8; k++) s += ws[k];
        bsum[blockIdx.x] = s;
    }
}

__global__ void k_bscan(int* __restrict__ bsum) {
    int t = threadIdx.x;
    int v = (t < NB) ? bsum[t] : 0;
    int lane = t & 31;
    int wid = t >> 5;
    int x = v;
    for (int d = 1; d < 32; d <<= 1) {
        int u = __shfl_up_sync(0xffffffffu, x, d);
        if (lane >= d) x += u;
    }
    __shared__ int ws[8];
    if (lane == 31) ws[wid] = x;
    __syncthreads();
    if (wid == 0 && lane < 8) {
        int y = ws[lane];
        for (int d = 1; d < 8; d <<= 1) {
            int u = __shfl_up_sync(0xffu, y, d);
            if (lane >= d) y += u;
        }
        ws[lane] = y;
    }
    __syncthreads();
    int incl = x + (wid > 0 ? ws[wid - 1] : 0);
    if (t < NB) bsum[t] = incl - v;
}

// scan-out + self-loop + cursor init fused
__global__ void k_scanout(const int* __restrict__ deg, const int* __restrict__ boff,
                          int* __restrict__ rowptr, int* __restrict__ cursor,
                          int* __restrict__ csrsrc) {
    int t = threadIdx.x;
    int i = blockIdx.x * 256 + t;
    int v = (i < NN) ? deg[i] : 0;
    int lane = t & 31;
    int wid = t >> 5;
    int x = v;
    for (int d = 1; d < 32; d <<= 1) {
        int u = __shfl_up_sync(0xffffffffu, x, d);
        if (lane >= d) x += u;
    }
    __shared__ int ws[8];
    if (lane == 31) ws[wid] = x;
    __syncthreads();
    if (wid == 0 && lane < 8) {
        int y = ws[lane];
        for (int d = 1; d < 8; d <<= 1) {
            int u = __shfl_up_sync(0xffu, y, d);
            if (lane >= d) y += u;
        }
        ws[lane] = y;
    }
    __syncthreads();
    int excl = x - v + (wid > 0 ? ws[wid - 1] : 0) + boff[blockIdx.x];
    if (i < NN) {
        rowptr[i] = excl;
        csrsrc[excl] = i;      // self loop first
        cursor[i] = excl + 1;
    }
    if (i == 0) rowptr[NN] = EE + NN;
}

__global__ void k_scatter(const int* __restrict__ src, const int* __restrict__ dst,
                          int* __restrict__ cursor, int* __restrict__ csrsrc) {
    int i = blockIdx.x * blockDim.x + threadIdx.x;
    if (i < EE) {
        int p = atomicAdd(&cursor[dst[i]], 1);
        csrsrc[p] = src[i];
    }
}

// ---------------- layernorm (layer 0 only): fp32 in -> fp16 out ----------------
__global__ __launch_bounds__(256) void k_layernorm(
    const float* __restrict__ h, const float* __restrict__ g,
    const float* __restrict__ b, __half* __restrict__ hnh) {
    int v = (int)((blockIdx.x * blockDim.x + threadIdx.x) >> 5);
    if (v >= NN) return;
    int lane = threadIdx.x & 31;
    const float4* h4 = (const float4*)(h + (size_t)v * DD);
    float4 x0 = h4[2 * lane];
    float4 x1 = h4[2 * lane + 1];
    float s = x0.x + x0.y + x0.z + x0.w + x1.x + x1.y + x1.z + x1.w;
    float q = x0.x * x0.x + x0.y * x0.y + x0.z * x0.z + x0.w * x0.w
            + x1.x * x1.x + x1.y * x1.y + x1.z * x1.z + x1.w * x1.w;
    for (int d = 16; d; d >>= 1) {
        s += __shfl_xor_sync(0xffffffffu, s, d);
        q += __shfl_xor_sync(0xffffffffu, q, d);
    }
    float mu = s * (1.0f / 256.0f);
    float var = q * (1.0f / 256.0f) - mu * mu;
    float r = rsqrtf(var + EPSF);
    const float4* g4 = (const float4*)g;
    const float4* b4 = (const float4*)b;
    float4 g0 = __ldg(&g4[2 * lane]);
    float4 g1 = __ldg(&g4[2 * lane + 1]);
    float4 b0 = __ldg(&b4[2 * lane]);
    float4 b1 = __ldg(&b4[2 * lane + 1]);
    float o[8];
    o[0] = (x0.x - mu) * r * g0.x + b0.x;
    o[1] = (x0.y - mu) * r * g0.y + b0.y;
    o[2] = (x0.z - mu) * r * g0.z + b0.z;
    o[3] = (x0.w - mu) * r * g0.w + b0.w;
    o[4] = (x1.x - mu) * r * g1.x + b1.x;
    o[5] = (x1.y - mu) * r * g1.y + b1.y;
    o[6] = (x1.z - mu) * r * g1.z + b1.z;
    o[7] = (x1.w - mu) * r * g1.w + b1.w;
    __half ph[8];
#pragma unroll
    for (int j = 0; j < 8; j++) ph[j] = __float2half(o[j]);
    *(uint4*)(hnh + (size_t)v * DD + 8 * lane) = *(uint4*)ph;
}

// ---------------- tensor-core GEMM ----------------
__device__ __forceinline__ void cp16(unsigned int dst, const void* src, int srcsize) {
    asm volatile("cp.async.cg.shared.global [%0], [%1], 16, %2;"
                 :: "r"(dst), "l"(src), "r"(srcsize));
}

__device__ __forceinline__ void ldsm_x4(unsigned int* r, unsigned int addr) {
    asm volatile("ldmatrix.sync.aligned.m8n8.x4.shared.b16 {%0,%1,%2,%3}, [%4];"
                 : "=r"(r[0]), "=r"(r[1]), "=r"(r[2]), "=r"(r[3]) : "r"(addr));
}

__device__ __forceinline__ void ldsm_x4t(unsigned int* r, unsigned int addr) {
    asm volatile("ldmatrix.sync.aligned.m8n8.x4.trans.shared.b16 {%0,%1,%2,%3}, [%4];"
                 : "=r"(r[0]), "=r"(r[1]), "=r"(r[2]), "=r"(r[3]) : "r"(addr));
}

template <int FP16>
__device__ __forceinline__ void mma16(float* c, const unsigned int* a,
                                      const unsigned int* b) {
    if (FP16) {
        asm volatile(
            "mma.sync.aligned.m16n8k16.row.col.f32.f16.f16.f32 "
            "{%0,%1,%2,%3}, {%4,%5,%6,%7}, {%8,%9}, {%0,%1,%2,%3};"
            : "+f"(c[0]), "+f"(c[1]), "+f"(c[2]), "+f"(c[3])
            : "r"(a[0]), "r"(a[1]), "r"(a[2]), "r"(a[3]), "r"(b[0]), "r"(b[1]));
    } else {
        asm volatile(
            "mma.sync.aligned.m16n8k16.row.col.f32.bf16.bf16.f32 "
            "{%0,%1,%2,%3}, {%4,%5,%6,%7}, {%8,%9}, {%0,%1,%2,%3};"
            : "+f"(c[0]), "+f"(c[1]), "+f"(c[2]), "+f"(c[3])
            : "r"(a[0]), "r"(a[1]), "r"(a[2]), "r"(a[3]), "r"(b[0]), "r"(b[1]));
    }
}

template <int LOADAL, int LOADBL>
__device__ __forceinline__ void issue_stage(
    const __nv_bfloat16* __restrict__ Ah, const __nv_bfloat16* __restrict__ Al,
    const __nv_bfloat16* __restrict__ Bh, const __nv_bfloat16* __restrict__ Bl,
    unsigned int sdst, int bm, int bn_l, int M, int K, int ldb, int tid, int kk) {
#pragma unroll
    for (int u = 0; u < 2; u++) {
        int c = tid + u * 256;
        int row = c >> 2;
        int seg = c & 3;
        int gr = bm + row;
        size_t go = (size_t)gr * K + kk + seg * 8;
        unsigned int dd = sdst + AH_OFF + row * 80 + seg * 16;
        int p = (gr < M) ? 16 : 0;
        cp16(dd, Ah + go, p);
        if (LOADAL) cp16(dd + (AL_OFF - AH_OFF), Al + go, p);
    }
#pragma unroll
    for (int u = 0; u < 2; u++) {
        int c = tid + u * 256;
        int row = c >> 4;
        int seg = c & 15;
        size_t go = (size_t)(kk + row) * ldb + bn_l + seg * 8;
        unsigned int dd = sdst + BH_OFF + row * 272 + seg * 16;
        cp16(dd, Bh + go, 16);
        if (LOADBL) cp16(dd + (BL_OFF - BH_OFF), Bl + go, 16);
    }
}

template <int FP16, int NT>
__device__ __forceinline__ void tile_mma(unsigned int stg, int wm0, int wn0,
                                         int aRow, int aKof, int bRow, int bNof,
                                         float acc[4][4][4]) {
#pragma unroll
    for (int ks = 0; ks < 32; ks += 16) {
        unsigned int ah[4][4];
        unsigned int al[4][4];
        unsigned int bh[4][2];
        unsigned int bl[4][2];
#pragma unroll
        for (int mi = 0; mi < 4; mi++) {
            unsigned int ad = stg + AH_OFF
                + (unsigned int)((wm0 + mi * 16 + aRow) * 40 + ks + aKof) * 2u;
            ldsm_x4(ah[mi], ad);
            if (NT >= 2) ldsm_x4(al[mi], ad + (AL_OFF - AH_OFF));
        }
#pragma unroll
        for (int np = 0; np < 2; np++) {
            unsigned int bd = stg + BH_OFF
                + (unsigned int)((ks + bRow) * 136 + wn0 + np * 16 + bNof) * 2u;
            unsigned int tb[4];
            ldsm_x4t(tb, bd);
            bh[np * 2][0] = tb[0];
            bh[np * 2][1] = tb[1];
            bh[np * 2 + 1][0] = tb[2];
            bh[np * 2 + 1][1] = tb[3];
            if (NT == 3) {
                ldsm_x4t(tb, bd + (BL_OFF - BH_OFF));
                bl[np * 2][0] = tb[0];
                bl[np * 2][1] = tb[1];
                bl[np * 2 + 1][0] = tb[2];
                bl[np * 2 + 1][1] = tb[3];
            }
        }
#pragma unroll
        for (int mi = 0; mi < 4; mi++) {
#pragma unroll
            for (int ni = 0; ni < 4; ni++) {
                mma16<FP16>(acc[mi][ni], ah[mi], bh[ni]);
                if (NT >= 2) mma16<FP16>(acc[mi][ni], al[mi], bh[ni]);
                if (NT == 3) mma16<FP16>(acc[mi][ni], ah[mi], bl[ni]);
            }
        }
    }
}

// EPI 0: layer -> xl(half,<256)/xr(float,>=256). EPI 1: bn+lrelu -> C fp32.
// EPI 2: lrelu -> C fp32. EPI 3: bn+lrelu -> split bf16 (Coh/Col).
template <int EPI, int FP16, int NT>
__global__ __launch_bounds__(256, 2) void k_gemm_tc(
    const __nv_bfloat16* __restrict__ Ah, const __nv_bfloat16* __restrict__ Al,
    const __nv_bfloat16* __restrict__ B0h, const __nv_bfloat16* __restrict__ B0l,
    const __nv_bfloat16* __restrict__ B1h, const __nv_bfloat16* __restrict__ B1l,
    const float* __restrict__ bias0, const float* __restrict__ bias1,
    const float* __restrict__ bng, const float* __restrict__ bnb,
    float* __restrict__ C, __half* __restrict__ Cxl, float* __restrict__ Cxr,
    __nv_bfloat16* __restrict__ Coh, __nv_bfloat16* __restrict__ Col,
    int M, int K, int ldb, int ldc) {
    extern __shared__ char smem[];
    const int tid = threadIdx.x;
    const int lane = tid & 31;
    const int wid = tid >> 5;
    const int bm = blockIdx.y * 128;
    const int bn = blockIdx.x * 128;
    const __nv_bfloat16* Bh = (bn < 256) ? B0h : B1h;
    const __nv_bfloat16* Bl = (bn < 256) ? B0l : B1l;
    const float* biasp = (bn < 256) ? bias0 : bias1;
    const int bn_l = bn & 255;
    const int wm0 = (wid & 1) * 64;
    const int wn0 = (wid >> 1) * 32;
    unsigned int sbase = (unsigned int)__cvta_generic_to_shared(smem);

    float acc[4][4][4];
#pragma unroll
    for (int i = 0; i < 4; i++) {
#pragma unroll
        for (int j = 0; j < 4; j++) {
#pragma unroll
            for (int k = 0; k < 4; k++) acc[i][j][k] = 0.f;
        }
    }

    const int grp = lane & 7;
    const int seg = lane >> 3;
    const int aRow = (seg & 1) * 8 + grp;
    const int aKof = (seg >> 1) * 8;
    const int bRow = (seg & 1) * 8 + grp;
    const int bNof = (seg >> 1) * 8;

    int nk = K / 32;
    issue_stage<(NT >= 2), (NT == 3)>(Ah, Al, Bh, Bl, sbase, bm, bn_l, M, K, ldb, tid, 0);
    asm volatile("cp.async.commit_group;");
    issue_stage<(NT >= 2), (NT == 3)>(Ah, Al, Bh, Bl, sbase + STAGE_BYTES, bm, bn_l, M, K, ldb, tid, 32);
    asm volatile("cp.async.commit_group;");

    for (int t = 0; t < nk; t++) {
        asm volatile("cp.async.wait_group 1;");
        __syncthreads();
        int sidx = t % NSTAGE;
        tile_mma<FP16, NT>(sbase + (unsigned int)sidx * STAGE_BYTES,
                           wm0, wn0, aRow, aKof, bRow, bNof, acc);
        if (t + 2 < nk) {
            issue_stage<(NT >= 2), (NT == 3)>(Ah, Al, Bh, Bl,
                                 sbase + (unsigned int)((t + 2) % NSTAGE) * STAGE_BYTES,
                                 bm, bn_l, M, K, ldb, tid, (t + 2) * 32);
        }
        asm volatile("cp.async.commit_group;");
    }

    const float rsb = rsqrtf(1.0f + EPSF);
    const int cg = lane >> 2;
    const int cc = lane & 3;
#pragma unroll
    for (int mi = 0; mi < 4; mi++) {
        int r0 = bm + wm0 + mi * 16 + cg;
#pragma unroll
        for (int ni = 0; ni < 4; ni++) {
            int colL = wn0 + ni * 8 + 2 * cc;
            int colB = bn_l + colL;
            float b0v = __ldg(&biasp[colB]);
            float b1v = __ldg(&biasp[colB + 1]);
            float v0 = acc[mi][ni][0] + b0v;
            float v1 = acc[mi][ni][1] + b1v;
            float v2 = acc[mi][ni][2] + b0v;
            float v3 = acc[mi][ni][3] + b1v;
            if (EPI == 0) {
                if (bn < 256) {
                    if (r0 < M)
                        *(__half2*)(Cxl + (size_t)r0 * DD + colB) = __floats2half2_rn(v0, v1);
                    if (r0 + 8 < M)
                        *(__half2*)(Cxl + (size_t)(r0 + 8) * DD + colB) = __floats2half2_rn(v2, v3);
                } else {
                    if (r0 < M)
                        *(float2*)(Cxr + (size_t)r0 * DD + colB) = make_float2(v0, v1);
                    if (r0 + 8 < M)
                        *(float2*)(Cxr + (size_t)(r0 + 8) * DD + colB) = make_float2(v2, v3);
                }
            } else {
                if (EPI == 1 || EPI == 3) {
                    float g0 = __ldg(&bng[colB]);
                    float g1 = __ldg(&bng[colB + 1]);
                    float q0 = __ldg(&bnb[colB]);
                    float q1 = __ldg(&bnb[colB + 1]);
                    v0 = lrelu(v0 * rsb * g0 + q0, 0.1f);
                    v1 = lrelu(v1 * rsb * g1 + q1, 0.1f);
                    v2 = lrelu(v2 * rsb * g0 + q0, 0.1f);
                    v3 = lrelu(v3 * rsb * g1 + q1, 0.1f);
                }
                if (EPI == 2) {
                    v0 = lrelu(v0, 0.1f);
                    v1 = lrelu(v1, 0.1f);
                    v2 = lrelu(v2, 0.1f);
                    v3 = lrelu(v3, 0.1f);
                }
                int col = bn + colL;
                if (EPI == 3) {
                    __nv_bfloat16 h0 = __float2bfloat16(v0);
                    __nv_bfloat16 h1 = __float2bfloat16(v1);
                    __nv_bfloat16 h2 = __float2bfloat16(v2);
                    __nv_bfloat16 h3 = __float2bfloat16(v3);
                    __nv_bfloat16 l0 = __float2bfloat16(v0 - __bfloat162float(h0));
                    __nv_bfloat16 l1 = __float2bfloat16(v1 - __bfloat162float(h1));
                    __nv_bfloat16 l2 = __float2bfloat16(v2 - __bfloat162float(h2));
                    __nv_bfloat16 l3 = __float2bfloat16(v3 - __bfloat162float(h3));
                    if (r0 < M) {
                        __nv_bfloat16 th[2] = {h0, h1};
                        __nv_bfloat16 tl[2] = {l0, l1};
                        *(unsigned int*)(Coh + (size_t)r0 * ldc + col) = *(unsigned int*)th;
                        *(unsigned int*)(Col + (size_t)r0 * ldc + col) = *(unsigned int*)tl;
                    }
                    if (r0 + 8 < M) {
                        __nv_bfloat16 th[2] = {h2, h3};
                        __nv_bfloat16 tl[2] = {l2, l3};
                        *(unsigned int*)(Coh + (size_t)(r0 + 8) * ldc + col) = *(unsigned int*)th;
                        *(unsigned int*)(Col + (size_t)(r0 + 8) * ldc + col) = *(unsigned int*)tl;
                    }
                } else {
                    if (r0 < M)
                        *(float2*)(C + (size_t)r0 * ldc + col) = make_float2(v0, v1);
                    if (r0 + 8 < M)
                        *(float2*)(C + (size_t)(r0 + 8) * ldc + col) = make_float2(v2, v3);
                }
            }
        }
    }
}

// ---------------- GATv2 aggregation + residual + fused next-layer LN (fp16 out) ----------------
__global__ __launch_bounds__(256) void k_gat(
    const __half* __restrict__ xl, const float* __restrict__ xr,
    const int* __restrict__ rowptr, const int* __restrict__ csrsrc,
    const float* __restrict__ att, const float* __restrict__ convb,
    const float* __restrict__ scales, const float* __restrict__ wvec, int li,
    float* __restrict__ h, float* __restrict__ hsum,
    const float* __restrict__ lng, const float* __restrict__ lnb,
    __half* __restrict__ hnh,
    __nv_bfloat16* __restrict__ hsh, __nv_bfloat16* __restrict__ hsl) {
    int v = (int)((blockIdx.x * blockDim.x + threadIdx.x) >> 5);
    if (v >= NN) return;
    int lane = threadIdx.x & 31;

    const float4* att4 = (const float4*)att;
    float4 a0 = __ldg(&att4[2 * lane]);
    float4 a1 = __ldg(&att4[2 * lane + 1]);
    const float4* xr4 = (const float4*)(xr + (size_t)v * DD);
    float4 r0 = __ldg(&xr4[2 * lane]);
    float4 r1 = __ldg(&xr4[2 * lane + 1]);

    float m = -1e30f;
    float den = 0.f;
    float acc[8];
#pragma unroll
    for (int j = 0; j < 8; j++) acc[j] = 0.f;

    int e1 = __ldg(&rowptr[v + 1]);
    for (int e = __ldg(&rowptr[v]); e < e1; e++) {
        int s = __ldg(&csrsrc[e]);
        uint4 raw = __ldg((const uint4*)(xl + (size_t)s * DD) + lane);
        const __half2* hp = (const __half2*)&raw;
        float2 f0 = __half22float2(hp[0]);
        float2 f1 = __half22float2(hp[1]);
        float2 f2 = __half22float2(hp[2]);
        float2 f3 = __half22float2(hp[3]);
        float p = 0.f;
        p = fmaf(lrelu(f0.x + r0.x, 0.2f), a0.x, p);
        p = fmaf(lrelu(f0.y + r0.y, 0.2f), a0.y, p);
        p = fmaf(lrelu(f1.x + r0.z, 0.2f), a0.z, p);
        p = fmaf(lrelu(f1.y + r0.w, 0.2f), a0.w, p);
        p = fmaf(lrelu(f2.x + r1.x, 0.2f), a1.x, p);
        p = fmaf(lrelu(f2.y + r1.y, 0.2f), a1.y, p);
        p = fmaf(lrelu(f3.x + r1.z, 0.2f), a1.z, p);
        p = fmaf(lrelu(f3.y + r1.w, 0.2f), a1.w, p);
        p += __shfl_xor_sync(0xffffffffu, p, 1);
        p += __shfl_xor_sync(0xffffffffu, p, 2);
        float nm = fmaxf(m, p);
        float sc = __expf(m - nm);
        float ep = __expf(p - nm);
        den = den * sc + ep;
        acc[0] = acc[0] * sc + f0.x * ep;
        acc[1] = acc[1] * sc + f0.y * ep;
        acc[2] = acc[2] * sc + f1.x * ep;
        acc[3] = acc[3] * sc + f1.y * ep;
        acc[4] = acc[4] * sc + f2.x * ep;
        acc[5] = acc[5] * sc + f2.y * ep;
        acc[6] = acc[6] * sc + f3.x * ep;
        acc[7] = acc[7] * sc + f3.y * ep;
        m = nm;
    }

    const float4* cb4 = (const float4*)convb;
    float4 cb0 = __ldg(&cb4[2 * lane]);
    float4 cb1 = __ldg(&cb4[2 * lane + 1]);
    float sci = __ldg(&scales[li]);
    float wi = __ldg(&wvec[li]);
    float4* h4 = (float4*)(h + (size_t)v * DD);
    float4 res0 = h4[2 * lane];
    float4 res1 = h4[2 * lane + 1];
    float id = 1.0f / den;
    float nh[8];
    nh[0] = res0.x + sci * lrelu(acc[0] * id + cb0.x, 0.1f);
    nh[1] = res0.y + sci * lrelu(acc[1] * id + cb0.y, 0.1f);
    nh[2] = res0.z + sci * lrelu(acc[2] * id + cb0.z, 0.1f);
    nh[3] = res0.w + sci * lrelu(acc[3] * id + cb0.w, 0.1f);
    nh[4] = res1.x + sci * lrelu(acc[4] * id + cb1.x, 0.1f);
    nh[5] = res1.y + sci * lrelu(acc[5] * id + cb1.y, 0.1f);
    nh[6] = res1.z + sci * lrelu(acc[6] * id + cb1.z, 0.1f);
    nh[7] = res1.w + sci * lrelu(acc[7] * id + cb1.w, 0.1f);
    h4[2 * lane] = make_float4(nh[0], nh[1], nh[2], nh[3]);
    h4[2 * lane + 1] = make_float4(nh[4], nh[5], nh[6], nh[7]);

    float4* hs4 = (float4*)(hsum + (size_t)v * DD);
    float4 sa, sb;
    if (li == 0) {
        sa = make_float4(0.f, 0.f, 0.f, 0.f);
        sb = make_float4(0.f, 0.f, 0.f, 0.f);
    } else {
        sa = hs4[2 * lane];
        sb = hs4[2 * lane + 1];
    }
    sa.x += wi * nh[0]; sa.y += wi * nh[1]; sa.z += wi * nh[2]; sa.w += wi * nh[3];
    sb.x += wi * nh[4]; sb.y += wi * nh[5]; sb.z += wi * nh[6]; sb.w += wi * nh[7];
    hs4[2 * lane] = sa;
    hs4[2 * lane + 1] = sb;

    if (li < LL - 1) {
        float s = 0.f;
        float q = 0.f;
#pragma unroll
        for (int j = 0; j < 8; j++) {
            s += nh[j];
            q += nh[j] * nh[j];
        }
        for (int d = 16; d; d >>= 1) {
            s += __shfl_xor_sync(0xffffffffu, s, d);
            q += __shfl_xor_sync(0xffffffffu, q, d);
        }
        float mu = s * (1.0f / 256.0f);
        float var = q * (1.0f / 256.0f) - mu * mu;
        float rr = rsqrtf(var + EPSF);
        const float4* g4 = (const float4*)lng;
        const float4* b4 = (const float4*)lnb;
        float4 g0 = __ldg(&g4[2 * lane]);
        float4 g1 = __ldg(&g4[2 * lane + 1]);
        float4 bb0 = __ldg(&b4[2 * lane]);
        float4 bb1 = __ldg(&b4[2 * lane + 1]);
        float o[8];
        o[0] = (nh[0] - mu) * rr * g0.x + bb0.x;
        o[1] = (nh[1] - mu) * rr * g0.y + bb0.y;
        o[2] = (nh[2] - mu) * rr * g0.z + bb0.z;
        o[3] = (nh[3] - mu) * rr * g0.w + bb0.w;
        o[4] = (nh[4] - mu) * rr * g1.x + bb1.x;
        o[5] = (nh[5] - mu) * rr * g1.y + bb1.y;
        o[6] = (nh[6] - mu) * rr * g1.z + bb1.z;
        o[7] = (nh[7] - mu) * rr * g1.w + bb1.w;
        __half ph[8];
#pragma unroll
        for (int j = 0; j < 8; j++) ph[j] = __float2half(o[j]);
        *(uint4*)(hnh + (size_t)v * DD + 8 * lane) = *(uint4*)ph;
    } else {
        float sv[8];
        sv[0] = sa.x; sv[1] = sa.y; sv[2] = sa.z; sv[3] = sa.w;
        sv[4] = sb.x; sv[5] = sb.y; sv[6] = sb.z; sv[7] = sb.w;
        __nv_bfloat16 ph[8];
        __nv_bfloat16 pl[8];
#pragma unroll
        for (int j = 0; j < 8; j++) {
            ph[j] = __float2bfloat16(sv[j]);
            pl[j] = __float2bfloat16(sv[j] - __bfloat162float(ph[j]));
        }
        *(uint4*)(hsh + (size_t)v * DD + 8 * lane) = *(uint4*)ph;
        *(uint4*)(hsl + (size_t)v * DD + 8 * lane) = *(uint4*)pl;
    }
}

// ---------------- final projection ----------------
__global__ __launch_bounds__(256) void k_final(
    const float* __restrict__ y2, const float* __restrict__ w,
    const float* __restrict__ b, float* __restrict__ out) {
    int v = (int)((blockIdx.x * blockDim.x + threadIdx.x) >> 5);
    if (v >= NN) return;
    int lane = threadIdx.x & 31;
    const float4* y4 = (const float4*)y2;
    const float4* w4 = (const float4*)w;
    float4 a = y4[v * 32 + lane];
    float4 ww = __ldg(&w4[lane]);
    float p = a.x * ww.x + a.y * ww.y + a.z * ww.z + a.w * ww.w;
    for (int d = 16; d; d >>= 1) p += __shfl_xor_sync(0xffffffffu, p, d);
    if (lane == 0) out[v] = p + __ldg(&b[0]);
}

// ---------------- launcher ----------------
extern "C" void kernel_launch(void* const* d_in, const int* in_sizes, int n_in,
                              void* d_out, int out_size) {
    (void)in_sizes; (void)n_in; (void)out_size;
    const float* x      = (const float*)d_in[0];
    const int*   ei     = (const int*)d_in[1];
    const float* win_w  = (const float*)d_in[2];
    const float* win_b  = (const float*)d_in[3];
    const float* bn1_g  = (const float*)d_in[4];
    const float* bn1_b  = (const float*)d_in[5];
    const float* ln_g   = (const float*)d_in[6];
    const float* ln_b   = (const float*)d_in[7];
    const float* Wl     = (const float*)d_in[8];
    const float* bl     = (const float*)d_in[9];
    const float* Wr     = (const float*)d_in[10];
    const float* br     = (const float*)d_in[11];
    const float* att    = (const float*)d_in[12];
    const float* conv_b = (const float*)d_in[13];
    const float* scales = (const float*)d_in[14];
    const float* sw     = (const float*)d_in[15];
    const float* h1_w   = (const float*)d_in[16];
    const float* h1_b   = (const float*)d_in[17];
    const float* bn2_g  = (const float*)d_in[18];
    const float* bn2_b  = (const float*)d_in[19];
    const float* h2_w   = (const float*)d_in[20];
    const float* h2_b   = (const float*)d_in[21];
    const float* h3_w   = (const float*)d_in[22];
    const float* h3_b   = (const float*)d_in[23];
    float* out = (float*)d_out;

    float *p_h, *p_xr, *p_hsum, *p_y2, *p_w;
    __half *p_xl, *p_hnh, *p_wlh, *p_wrh;
    __nv_bfloat16 *p_xh, *p_xlo, *p_hsh, *p_hsl, *p_y1h, *p_y1l, *p_wbh, *p_wbl;
    int *p_rowptr, *p_deg, *p_bsum, *p_cursor, *p_csr;
    cudaGetSymbolAddress((void**)&p_h, d_h);
    cudaGetSymbolAddress((void**)&p_xh, d_xh);
    cudaGetSymbolAddress((void**)&p_xlo, d_xlo);
    cudaGetSymbolAddress((void**)&p_hnh, d_hnh);
    cudaGetSymbolAddress((void**)&p_xl, d_xl);
    cudaGetSymbolAddress((void**)&p_xr, d_xr);
    cudaGetSymbolAddress((void**)&p_hsum, d_hsum);
    cudaGetSymbolAddress((void**)&p_hsh, d_hsh);
    cudaGetSymbolAddress((void**)&p_hsl, d_hsl);
    cudaGetSymbolAddress((void**)&p_y1h, d_y1h);
    cudaGetSymbolAddress((void**)&p_y1l, d_y1l);
    cudaGetSymbolAddress((void**)&p_y2, d_y2);
    cudaGetSymbolAddress((void**)&p_wbh, d_wbh);
    cudaGetSymbolAddress((void**)&p_wbl, d_wbl);
    cudaGetSymbolAddress((void**)&p_wlh, d_wlh);
    cudaGetSymbolAddress((void**)&p_wrh, d_wrh);
    cudaGetSymbolAddress((void**)&p_w, d_w);
    cudaGetSymbolAddress((void**)&p_rowptr, d_rowptr);
    cudaGetSymbolAddress((void**)&p_deg, d_deg);
    cudaGetSymbolAddress((void**)&p_bsum, d_bsum);
    cudaGetSymbolAddress((void**)&p_cursor, d_cursor);
    cudaGetSymbolAddress((void**)&p_csr, d_csrsrc);

    cudaFuncSetAttribute(k_gemm_tc<0, 1, 1>, cudaFuncAttributeMaxDynamicSharedMemorySize, SMEM_TOTAL);
    cudaFuncSetAttribute(k_gemm_tc<1, 0, 3>, cudaFuncAttributeMaxDynamicSharedMemorySize, SMEM_TOTAL);
    cudaFuncSetAttribute(k_gemm_tc<2, 0, 3>, cudaFuncAttributeMaxDynamicSharedMemorySize, SMEM_TOTAL);
    cudaFuncSetAttribute(k_gemm_tc<3, 0, 3>, cudaFuncAttributeMaxDynamicSharedMemorySize, SMEM_TOTAL);

    const int* e_src = ei;
    const int* e_dst = ei + EE;
    const int warpBlocks = (NN * 32 + 255) / 256;

    // launches 0-3: the 4th launch (idx 3) is what ncu profiles
    {
        int n4 = NN * IND / 4;
        k_split<<<(n4 + 255) / 256, 256>>>(x, p_xh, p_xlo, n4);            // 0
    }
    {
        int n4 = IND * DD / 4;
        k_split<<<(n4 + 255) / 256, 256>>>(win_w, p_wbh + W_WIN, p_wbl + W_WIN, n4);  // 1
    }
    {
        int n4e = LL * DD * DD / 4;
        k_cvt2_h<<<(2 * n4e + 255) / 256, 256>>>(Wl, Wr, p_wlh, p_wrh, n4e);  // 2
    }
    {
        dim3 g(2, (NN + 127) / 128);                                       // 3: PROFILED
        k_gemm_tc<1, 0, 3><<<g, 256, SMEM_TOTAL>>>(
            p_xh, p_xlo, p_wbh + W_WIN, p_wbl + W_WIN, p_wbh + W_WIN, p_wbl + W_WIN,
            win_b, win_b, bn1_g, bn1_b, p_h, NULL, NULL, NULL, NULL,
            NN, IND, DD, DD);
    }
    {
        int n4 = DD * DD / 4;
        k_split<<<(n4 + 255) / 256, 256>>>(h1_w, p_wbh + W_H1, p_wbl + W_H1, n4);
    }
    {
        int n4 = DD * (DD / 2) / 4;
        k_split<<<(n4 + 255) / 256, 256>>>(h2_w, p_wbh + W_H2, p_wbl + W_H2, n4);
    }
    k_softmax_w<<<1, 32>>>(sw, p_w);
    k_layernorm<<<warpBlocks, 256>>>(p_h, ln_g, ln_b, p_hnh);

    k_deg_init<<<(NN + 255) / 256, 256>>>(p_deg);
    k_deg_count<<<(EE + 255) / 256, 256>>>(e_dst, p_deg);
    k_blocksum<<<NB, 256>>>(p_deg, p_bsum);
    k_bscan<<<1, 256>>>(p_bsum);
    k_scanout<<<NB, 256>>>(p_deg, p_bsum, p_rowptr, p_cursor, p_csr);
    k_scatter<<<(EE + 255) / 256, 256>>>(e_src, e_dst, p_cursor, p_csr);

    for (int i = 0; i < LL; i++) {
        dim3 g(4, (NN + 127) / 128);
        k_gemm_tc<0, 1, 1><<<g, 256, SMEM_TOTAL>>>(
            (const __nv_bfloat16*)p_hnh, NULL,
            (const __nv_bfloat16*)(p_wlh + (size_t)i * DD * DD), NULL,
            (const __nv_bfloat16*)(p_wrh + (size_t)i * DD * DD), NULL,
            bl + i * DD, br + i * DD, NULL, NULL,
            NULL, p_xl, p_xr, NULL, NULL, NN, DD, DD, 0);
        k_gat<<<warpBlocks, 256>>>(p_xl, p_xr, p_rowptr, p_csr, att + i * DD,
                                   conv_b + i * DD, scales, p_w, i, p_h, p_hsum,
                                   ln_g + (i + 1 < LL ? (i + 1) * DD : 0),
                                   ln_b + (i + 1 < LL ? (i + 1) * DD : 0),
                                   p_hnh, p_hsh, p_hsl);
    }

    {
        dim3 g(2, (NN + 127) / 128);
        k_gemm_tc<3, 0, 3><<<g, 256, SMEM_TOTAL>>>(
            p_hsh, p_hsl, p_wbh + W_H1, p_wbl + W_H1, p_wbh + W_H1, p_wbl + W_H1,
            h1_b, h1_b, bn2_g, bn2_b, NULL, NULL, NULL, p_y1h, p_y1l,
            NN, DD, DD, DD);
        dim3 g2(1, (NN + 127) / 128);
        k_gemm_tc<2, 0, 3><<<g2, 256, SMEM_TOTAL>>>(
            p_y1h, p_y1l, p_wbh + W_H2, p_wbl + W_H2, p_wbh + W_H2, p_wbl + W_H2,
            h2_b, h2_b, NULL, NULL, p_y2, NULL, NULL, NULL, NULL,
            NN, DD, DD / 2, DD / 2);
    }
    k_final<<<warpBlocks, 256>>>(p_y2, h3_w, h3_b, out);
}

// round 9
// speedup vs baseline: 3.3200x; 1.0724x over previous
#include <cuda_runtime.h>
#include <cuda_bf16.h>
#include <cuda_fp16.h>
#include <stdint.h>
#include <math.h>

#define NN 50000
#define EE 800000
#define IND 128
#define DD 256
#define LL 6
#define EPSF 1e-5f
#define NB 196

// bf16 weight-split pool offsets (elements): win | h1 | h2
#define W_WIN 0
#define W_H1 32768
#define W_H2 98304
#define W_TOT 131072

// per-NT smem stage config. A: 128 rows x 40 b16 stride; B: 32 rows x 136 b16 stride
template <int NT> struct SCfg {
    static constexpr int AH = 0;
    static constexpr int AL = 10240;
    static constexpr int BH = (NT >= 2) ? 20480 : 10240;
    static constexpr int BL = 29184;
    static constexpr int BYTES = (NT == 3) ? 37888 : ((NT == 2) ? 29184 : 18944);
    static constexpr int NS = (NT == 1) ? 5 : 3;   // pipeline stages
    static constexpr int PD = NS - 1;              // prefetch depth
    static constexpr int SMEM = NS * BYTES;
};

// ---------------- scratch ----------------
__device__ __align__(16) float  d_h[(size_t)NN * DD];
__device__ __align__(16) __nv_bfloat16 d_xh[(size_t)NN * IND];
__device__ __align__(16) __nv_bfloat16 d_xlo[(size_t)NN * IND];
__device__ __align__(16) __half d_hnh[(size_t)NN * DD];
__device__ __align__(16) __half d_xl[(size_t)NN * DD];
__device__ __align__(16) __half d_xr[(size_t)NN * DD];
__device__ __align__(16) float  d_hsum[(size_t)NN * DD];
__device__ __align__(16) __nv_bfloat16 d_hsh[(size_t)NN * DD];
__device__ __align__(16) __nv_bfloat16 d_hsl[(size_t)NN * DD];
__device__ __align__(16) __nv_bfloat16 d_y1h[(size_t)NN * DD];
__device__ __align__(16) __nv_bfloat16 d_y1l[(size_t)NN * DD];
__device__ __align__(16) float  d_y2[(size_t)NN * (DD / 2)];
__device__ __align__(16) __nv_bfloat16 d_wbh[W_TOT];
__device__ __align__(16) __nv_bfloat16 d_wbl[W_TOT];
__device__ __align__(16) __half d_wlh[(size_t)LL * DD * DD];
__device__ __align__(16) __half d_wrh[(size_t)LL * DD * DD];
__device__ int   d_rowptr[NN + 1];
__device__ int   d_deg[NN];
__device__ int   d_bsum[NB];
__device__ int   d_cursor[NN];
__device__ int   d_csrsrc[EE + NN];
__device__ float d_w[LL];

__device__ __forceinline__ float lrelu(float x, float a) { return x > 0.f ? x : a * x; }

// ---------------- tiny kernels ----------------
__global__ void k_softmax_w(const float* __restrict__ sw, float* __restrict__ w) {
    if (threadIdx.x == 0 && blockIdx.x == 0) {
        float m = -1e30f;
        for (int i = 0; i < LL; i++) m = fmaxf(m, sw[i]);
        float e[LL];
        float s = 0.f;
        for (int i = 0; i < LL; i++) { e[i] = __expf(sw[i] - m); s += e[i]; }
        for (int i = 0; i < LL; i++) w[i] = e[i] / s;
    }
}

__global__ void k_split(const float* __restrict__ in, __nv_bfloat16* __restrict__ hi,
                        __nv_bfloat16* __restrict__ lo, int n4) {
    int i = blockIdx.x * blockDim.x + threadIdx.x;
    if (i >= n4) return;
    float4 v = ((const float4*)in)[i];
    __nv_bfloat16 h[4];
    __nv_bfloat16 l[4];
    h[0] = __float2bfloat16(v.x); l[0] = __float2bfloat16(v.x - __bfloat162float(h[0]));
    h[1] = __float2bfloat16(v.y); l[1] = __float2bfloat16(v.y - __bfloat162float(h[1]));
    h[2] = __float2bfloat16(v.z); l[2] = __float2bfloat16(v.z - __bfloat162float(h[2]));
    h[3] = __float2bfloat16(v.w); l[3] = __float2bfloat16(v.w - __bfloat162float(h[3]));
    ((uint2*)hi)[i] = *(uint2*)h;
    ((uint2*)lo)[i] = *(uint2*)l;
}

// convert two fp32 arrays -> fp16 (Wl and Wr fused)
__global__ void k_cvt2_h(const float* __restrict__ a, const float* __restrict__ b,
                         __half* __restrict__ ah, __half* __restrict__ bh, int n4each) {
    int i = blockIdx.x * blockDim.x + threadIdx.x;
    if (i >= 2 * n4each) return;
    const float* src = (i < n4each) ? a : b;
    __half* dh = (i < n4each) ? ah : bh;
    int j = (i < n4each) ? i : i - n4each;
    float4 v = ((const float4*)src)[j];
    __half h[4];
    h[0] = __float2half(v.x);
    h[1] = __float2half(v.y);
    h[2] = __float2half(v.z);
    h[3] = __float2half(v.w);
    ((uint2*)dh)[j] = *(uint2*)h;
}

__global__ void k_deg_init(int* __restrict__ deg) {
    int i = blockIdx.x * blockDim.x + threadIdx.x;
    if (i < NN) deg[i] = 1;
}

__global__ void k_deg_count(const int* __restrict__ dst, int* __restrict__ deg) {
    int i = blockIdx.x * blockDim.x + threadIdx.x;
    if (i < EE) atomicAdd(&deg[dst[i]], 1);
}

__global__ void k_blocksum(const int* __restrict__ deg, int* __restrict__ bsum) {
    int i = blockIdx.x * 256 + threadIdx.x;
    int v = (i < NN) ? deg[i] : 0;
    int lane = threadIdx.x & 31;
    int wid = threadIdx.x >> 5;
    for (int d = 16; d; d >>= 1) v += __shfl_xor_sync(0xffffffffu, v, d);
    __shared__ int ws[8];
    if (lane == 0) ws[wid] = v;
    __syncthreads();
    if (threadIdx.x == 0) {
        int s = 0;
        for (int k = 0; k < 8; k++) s += ws[k];
        bsum[blockIdx.x] = s;
    }
}

__global__ void k_bscan(int* __restrict__ bsum) {
    int t = threadIdx.x;
    int v = (t < NB) ? bsum[t] : 0;
    int lane = t & 31;
    int wid = t >> 5;
    int x = v;
    for (int d = 1; d < 32; d <<= 1) {
        int u = __shfl_up_sync(0xffffffffu, x, d);
        if (lane >= d) x += u;
    }
    __shared__ int ws[8];
    if (lane == 31) ws[wid] = x;
    __syncthreads();
    if (wid == 0 && lane < 8) {
        int y = ws[lane];
        for (int d = 1; d < 8; d <<= 1) {
            int u = __shfl_up_sync(0xffu, y, d);
            if (lane >= d) y += u;
        }
        ws[lane] = y;
    }
    __syncthreads();
    int incl = x + (wid > 0 ? ws[wid - 1] : 0);
    if (t < NB) bsum[t] = incl - v;
}

// scan-out + self-loop + cursor init fused
__global__ void k_scanout(const int* __restrict__ deg, const int* __restrict__ boff,
                          int* __restrict__ rowptr, int* __restrict__ cursor,
                          int* __restrict__ csrsrc) {
    int t = threadIdx.x;
    int i = blockIdx.x * 256 + t;
    int v = (i < NN) ? deg[i] : 0;
    int lane = t & 31;
    int wid = t >> 5;
    int x = v;
    for (int d = 1; d < 32; d <<= 1) {
        int u = __shfl_up_sync(0xffffffffu, x, d);
        if (lane >= d) x += u;
    }
    __shared__ int ws[8];
    if (lane == 31) ws[wid] = x;
    __syncthreads();
    if (wid == 0 && lane < 8) {
        int y = ws[lane];
        for (int d = 1; d < 8; d <<= 1) {
            int u = __shfl_up_sync(0xffu, y, d);
            if (lane >= d) y += u;
        }
        ws[lane] = y;
    }
    __syncthreads();
    int excl = x - v + (wid > 0 ? ws[wid - 1] : 0) + boff[blockIdx.x];
    if (i < NN) {
        rowptr[i] = excl;
        csrsrc[excl] = i;
        cursor[i] = excl + 1;
    }
    if (i == 0) rowptr[NN] = EE + NN;
}

__global__ void k_scatter(const int* __restrict__ src, const int* __restrict__ dst,
                          int* __restrict__ cursor, int* __restrict__ csrsrc) {
    int i = blockIdx.x * blockDim.x + threadIdx.x;
    if (i < EE) {
        int p = atomicAdd(&cursor[dst[i]], 1);
        csrsrc[p] = src[i];
    }
}

// ---------------- layernorm (layer 0 only): fp32 in -> fp16 out ----------------
__global__ __launch_bounds__(256) void k_layernorm(
    const float* __restrict__ h, const float* __restrict__ g,
    const float* __restrict__ b, __half* __restrict__ hnh) {
    int v = (int)((blockIdx.x * blockDim.x + threadIdx.x) >> 5);
    if (v >= NN) return;
    int lane = threadIdx.x & 31;
    const float4* h4 = (const float4*)(h + (size_t)v * DD);
    float4 x0 = h4[2 * lane];
    float4 x1 = h4[2 * lane + 1];
    float s = x0.x + x0.y + x0.z + x0.w + x1.x + x1.y + x1.z + x1.w;
    float q = x0.x * x0.x + x0.y * x0.y + x0.z * x0.z + x0.w * x0.w
            + x1.x * x1.x + x1.y * x1.y + x1.z * x1.z + x1.w * x1.w;
    for (int d = 16; d; d >>= 1) {
        s += __shfl_xor_sync(0xffffffffu, s, d);
        q += __shfl_xor_sync(0xffffffffu, q, d);
    }
    float mu = s * (1.0f / 256.0f);
    float var = q * (1.0f / 256.0f) - mu * mu;
    float r = rsqrtf(var + EPSF);
    const float4* g4 = (const float4*)g;
    const float4* b4 = (const float4*)b;
    float4 g0 = __ldg(&g4[2 * lane]);
    float4 g1 = __ldg(&g4[2 * lane + 1]);
    float4 b0 = __ldg(&b4[2 * lane]);
    float4 b1 = __ldg(&b4[2 * lane + 1]);
    float o[8];
    o[0] = (x0.x - mu) * r * g0.x + b0.x;
    o[1] = (x0.y - mu) * r * g0.y + b0.y;
    o[2] = (x0.z - mu) * r * g0.z + b0.z;
    o[3] = (x0.w - mu) * r * g0.w + b0.w;
    o[4] = (x1.x - mu) * r * g1.x + b1.x;
    o[5] = (x1.y - mu) * r * g1.y + b1.y;
    o[6] = (x1.z - mu) * r * g1.z + b1.z;
    o[7] = (x1.w - mu) * r * g1.w + b1.w;
    __half ph[8];
#pragma unroll
    for (int j = 0; j < 8; j++) ph[j] = __float2half(o[j]);
    *(uint4*)(hnh + (size_t)v * DD + 8 * lane) = *(uint4*)ph;
}

// ---------------- tensor-core GEMM ----------------
__device__ __forceinline__ void cp16(unsigned int dst, const void* src, int srcsize) {
    asm volatile("cp.async.cg.shared.global [%0], [%1], 16, %2;"
                 :: "r"(dst), "l"(src), "r"(srcsize));
}

template <int N>
__device__ __forceinline__ void waitg() {
    asm volatile("cp.async.wait_group %0;" :: "n"(N));
}

__device__ __forceinline__ void ldsm_x4(unsigned int* r, unsigned int addr) {
    asm volatile("ldmatrix.sync.aligned.m8n8.x4.shared.b16 {%0,%1,%2,%3}, [%4];"
                 : "=r"(r[0]), "=r"(r[1]), "=r"(r[2]), "=r"(r[3]) : "r"(addr));
}

__device__ __forceinline__ void ldsm_x4t(unsigned int* r, unsigned int addr) {
    asm volatile("ldmatrix.sync.aligned.m8n8.x4.trans.shared.b16 {%0,%1,%2,%3}, [%4];"
                 : "=r"(r[0]), "=r"(r[1]), "=r"(r[2]), "=r"(r[3]) : "r"(addr));
}

template <int FP16>
__device__ __forceinline__ void mma16(float* c, const unsigned int* a,
                                      const unsigned int* b) {
    if (FP16) {
        asm volatile(
            "mma.sync.aligned.m16n8k16.row.col.f32.f16.f16.f32 "
            "{%0,%1,%2,%3}, {%4,%5,%6,%7}, {%8,%9}, {%0,%1,%2,%3};"
            : "+f"(c[0]), "+f"(c[1]), "+f"(c[2]), "+f"(c[3])
            : "r"(a[0]), "r"(a[1]), "r"(a[2]), "r"(a[3]), "r"(b[0]), "r"(b[1]));
    } else {
        asm volatile(
            "mma.sync.aligned.m16n8k16.row.col.f32.bf16.bf16.f32 "
            "{%0,%1,%2,%3}, {%4,%5,%6,%7}, {%8,%9}, {%0,%1,%2,%3};"
            : "+f"(c[0]), "+f"(c[1]), "+f"(c[2]), "+f"(c[3])
            : "r"(a[0]), "r"(a[1]), "r"(a[2]), "r"(a[3]), "r"(b[0]), "r"(b[1]));
    }
}

template <int NT>
__device__ __forceinline__ void issue_stage(
    const __nv_bfloat16* __restrict__ Ah, const __nv_bfloat16* __restrict__ Al,
    const __nv_bfloat16* __restrict__ Bh, const __nv_bfloat16* __restrict__ Bl,
    unsigned int sdst, int bm, int bn_l, int M, int K, int ldb, int tid, int kk) {
#pragma unroll
    for (int u = 0; u < 2; u++) {
        int c = tid + u * 256;
        int row = c >> 2;
        int seg = c & 3;
        int gr = bm + row;
        size_t go = (size_t)gr * K + kk + seg * 8;
        unsigned int dd = sdst + SCfg<NT>::AH + row * 80 + seg * 16;
        int p = (gr < M) ? 16 : 0;
        cp16(dd, Ah + go, p);
        if (NT >= 2) cp16(dd + (SCfg<NT>::AL - SCfg<NT>::AH), Al + go, p);
    }
#pragma unroll
    for (int u = 0; u < 2; u++) {
        int c = tid + u * 256;
        int row = c >> 4;
        int seg = c & 15;
        size_t go = (size_t)(kk + row) * ldb + bn_l + seg * 8;
        unsigned int dd = sdst + SCfg<NT>::BH + row * 272 + seg * 16;
        cp16(dd, Bh + go, 16);
        if (NT == 3) cp16(dd + (SCfg<NT>::BL - SCfg<NT>::BH), Bl + go, 16);
    }
}

template <int FP16, int NT>
__device__ __forceinline__ void tile_mma(unsigned int stg, int wm0, int wn0,
                                         int aRow, int aKof, int bRow, int bNof,
                                         float acc[4][4][4]) {
#pragma unroll
    for (int ks = 0; ks < 32; ks += 16) {
        unsigned int ah[4][4];
        unsigned int al[4][4];
        unsigned int bh[4][2];
        unsigned int bl[4][2];
#pragma unroll
        for (int mi = 0; mi < 4; mi++) {
            unsigned int ad = stg + SCfg<NT>::AH
                + (unsigned int)((wm0 + mi * 16 + aRow) * 40 + ks + aKof) * 2u;
            ldsm_x4(ah[mi], ad);
            if (NT >= 2) ldsm_x4(al[mi], ad + (SCfg<NT>::AL - SCfg<NT>::AH));
        }
#pragma unroll
        for (int np = 0; np < 2; np++) {
            unsigned int bd = stg + SCfg<NT>::BH
                + (unsigned int)((ks + bRow) * 136 + wn0 + np * 16 + bNof) * 2u;
            unsigned int tb[4];
            ldsm_x4t(tb, bd);
            bh[np * 2][0] = tb[0];
            bh[np * 2][1] = tb[1];
            bh[np * 2 + 1][0] = tb[2];
            bh[np * 2 + 1][1] = tb[3];
            if (NT == 3) {
                ldsm_x4t(tb, bd + (SCfg<NT>::BL - SCfg<NT>::BH));
                bl[np * 2][0] = tb[0];
                bl[np * 2][1] = tb[1];
                bl[np * 2 + 1][0] = tb[2];
                bl[np * 2 + 1][1] = tb[3];
            }
        }
#pragma unroll
        for (int mi = 0; mi < 4; mi++) {
#pragma unroll
            for (int ni = 0; ni < 4; ni++) {
                mma16<FP16>(acc[mi][ni], ah[mi], bh[ni]);
                if (NT >= 2) mma16<FP16>(acc[mi][ni], al[mi], bh[ni]);
                if (NT == 3) mma16<FP16>(acc[mi][ni], ah[mi], bl[ni]);
            }
        }
    }
}

// EPI 0: layer -> xl/xr (both half). EPI 1: bn+lrelu -> C fp32.
// EPI 2: lrelu -> C fp32. EPI 3: bn+lrelu -> split bf16 (Coh/Col).
template <int EPI, int FP16, int NT>
__global__ __launch_bounds__(256, 2) void k_gemm_tc(
    const __nv_bfloat16* __restrict__ Ah, const __nv_bfloat16* __restrict__ Al,
    const __nv_bfloat16* __restrict__ B0h, const __nv_bfloat16* __restrict__ B0l,
    const __nv_bfloat16* __restrict__ B1h, const __nv_bfloat16* __restrict__ B1l,
    const float* __restrict__ bias0, const float* __restrict__ bias1,
    const float* __restrict__ bng, const float* __restrict__ bnb,
    float* __restrict__ C, __half* __restrict__ Cxl, __half* __restrict__ Cxr,
    __nv_bfloat16* __restrict__ Coh, __nv_bfloat16* __restrict__ Col,
    int M, int K, int ldb, int ldc) {
    extern __shared__ char smem[];
    const int tid = threadIdx.x;
    const int lane = tid & 31;
    const int wid = tid >> 5;
    const int bm = blockIdx.y * 128;
    const int bn = blockIdx.x * 128;
    const __nv_bfloat16* Bh = (bn < 256) ? B0h : B1h;
    const __nv_bfloat16* Bl = (bn < 256) ? B0l : B1l;
    const float* biasp = (bn < 256) ? bias0 : bias1;
    const int bn_l = bn & 255;
    const int wm0 = (wid & 1) * 64;
    const int wn0 = (wid >> 1) * 32;
    unsigned int sbase = (unsigned int)__cvta_generic_to_shared(smem);
    constexpr int NS = SCfg<NT>::NS;
    constexpr int PD = SCfg<NT>::PD;
    constexpr int SB = SCfg<NT>::BYTES;

    float acc[4][4][4];
#pragma unroll
    for (int i = 0; i < 4; i++) {
#pragma unroll
        for (int j = 0; j < 4; j++) {
#pragma unroll
            for (int k = 0; k < 4; k++) acc[i][j][k] = 0.f;
        }
    }

    const int grp = lane & 7;
    const int seg = lane >> 3;
    const int aRow = (seg & 1) * 8 + grp;
    const int aKof = (seg >> 1) * 8;
    const int bRow = (seg & 1) * 8 + grp;
    const int bNof = (seg >> 1) * 8;

    int nk = K / 32;
#pragma unroll
    for (int s = 0; s < PD; s++) {
        if (s < nk)
            issue_stage<NT>(Ah, Al, Bh, Bl, sbase + (unsigned int)s * SB,
                            bm, bn_l, M, K, ldb, tid, s * 32);
        asm volatile("cp.async.commit_group;");
    }

    for (int t = 0; t < nk; t++) {
        waitg<PD - 1>();
        __syncthreads();
        tile_mma<FP16, NT>(sbase + (unsigned int)(t % NS) * SB,
                           wm0, wn0, aRow, aKof, bRow, bNof, acc);
        if (t + PD < nk) {
            issue_stage<NT>(Ah, Al, Bh, Bl,
                            sbase + (unsigned int)((t + PD) % NS) * SB,
                            bm, bn_l, M, K, ldb, tid, (t + PD) * 32);
        }
        asm volatile("cp.async.commit_group;");
    }

    const float rsb = rsqrtf(1.0f + EPSF);
    const int cg = lane >> 2;
    const int cc = lane & 3;
#pragma unroll
    for (int mi = 0; mi < 4; mi++) {
        int r0 = bm + wm0 + mi * 16 + cg;
#pragma unroll
        for (int ni = 0; ni < 4; ni++) {
            int colL = wn0 + ni * 8 + 2 * cc;
            int colB = bn_l + colL;
            float b0v = __ldg(&biasp[colB]);
            float b1v = __ldg(&biasp[colB + 1]);
            float v0 = acc[mi][ni][0] + b0v;
            float v1 = acc[mi][ni][1] + b1v;
            float v2 = acc[mi][ni][2] + b0v;
            float v3 = acc[mi][ni][3] + b1v;
            if (EPI == 0) {
                __half* dst = (bn < 256) ? Cxl : Cxr;
                if (r0 < M)
                    *(__half2*)(dst + (size_t)r0 * DD + colB) = __floats2half2_rn(v0, v1);
                if (r0 + 8 < M)
                    *(__half2*)(dst + (size_t)(r0 + 8) * DD + colB) = __floats2half2_rn(v2, v3);
            } else {
                if (EPI == 1 || EPI == 3) {
                    float g0 = __ldg(&bng[colB]);
                    float g1 = __ldg(&bng[colB + 1]);
                    float q0 = __ldg(&bnb[colB]);
                    float q1 = __ldg(&bnb[colB + 1]);
                    v0 = lrelu(v0 * rsb * g0 + q0, 0.1f);
                    v1 = lrelu(v1 * rsb * g1 + q1, 0.1f);
                    v2 = lrelu(v2 * rsb * g0 + q0, 0.1f);
                    v3 = lrelu(v3 * rsb * g1 + q1, 0.1f);
                }
                if (EPI == 2) {
                    v0 = lrelu(v0, 0.1f);
                    v1 = lrelu(v1, 0.1f);
                    v2 = lrelu(v2, 0.1f);
                    v3 = lrelu(v3, 0.1f);
                }
                int col = bn + colL;
                if (EPI == 3) {
                    __nv_bfloat16 h0 = __float2bfloat16(v0);
                    __nv_bfloat16 h1 = __float2bfloat16(v1);
                    __nv_bfloat16 h2 = __float2bfloat16(v2);
                    __nv_bfloat16 h3 = __float2bfloat16(v3);
                    __nv_bfloat16 l0 = __float2bfloat16(v0 - __bfloat162float(h0));
                    __nv_bfloat16 l1 = __float2bfloat16(v1 - __bfloat162float(h1));
                    __nv_bfloat16 l2 = __float2bfloat16(v2 - __bfloat162float(h2));
                    __nv_bfloat16 l3 = __float2bfloat16(v3 - __bfloat162float(h3));
                    if (r0 < M) {
                        __nv_bfloat16 th[2] = {h0, h1};
                        __nv_bfloat16 tl[2] = {l0, l1};
                        *(unsigned int*)(Coh + (size_t)r0 * ldc + col) = *(unsigned int*)th;
                        *(unsigned int*)(Col + (size_t)r0 * ldc + col) = *(unsigned int*)tl;
                    }
                    if (r0 + 8 < M) {
                        __nv_bfloat16 th[2] = {h2, h3};
                        __nv_bfloat16 tl[2] = {l2, l3};
                        *(unsigned int*)(Coh + (size_t)(r0 + 8) * ldc + col) = *(unsigned int*)th;
                        *(unsigned int*)(Col + (size_t)(r0 + 8) * ldc + col) = *(unsigned int*)tl;
                    }
                } else {
                    if (r0 < M)
                        *(float2*)(C + (size_t)r0 * ldc + col) = make_float2(v0, v1);
                    if (r0 + 8 < M)
                        *(float2*)(C + (size_t)(r0 + 8) * ldc + col) = make_float2(v2, v3);
                }
            }
        }
    }
}

// ---------------- GATv2 aggregation + residual + fused next-layer LN ----------------
__global__ __launch_bounds__(256) void k_gat(
    const __half* __restrict__ xl, const __half* __restrict__ xr,
    const int* __restrict__ rowptr, const int* __restrict__ csrsrc,
    const float* __restrict__ att, const float* __restrict__ convb,
    const float* __restrict__ scales, const float* __restrict__ wvec, int li,
    float* __restrict__ h, float* __restrict__ hsum,
    const float* __restrict__ lng, const float* __restrict__ lnb,
    __half* __restrict__ hnh,
    __nv_bfloat16* __restrict__ hsh, __nv_bfloat16* __restrict__ hsl) {
    int v = (int)((blockIdx.x * blockDim.x + threadIdx.x) >> 5);
    if (v >= NN) return;
    int lane = threadIdx.x & 31;

    const float4* att4 = (const float4*)att;
    float4 a0 = __ldg(&att4[2 * lane]);
    float4 a1 = __ldg(&att4[2 * lane + 1]);
    uint4 rraw = __ldg((const uint4*)(xr + (size_t)v * DD) + lane);
    const __half2* rp = (const __half2*)&rraw;
    float2 xr01 = __half22float2(rp[0]);
    float2 xr23 = __half22float2(rp[1]);
    float2 xr45 = __half22float2(rp[2]);
    float2 xr67 = __half22float2(rp[3]);

    float m = -1e30f;
    float den = 0.f;
    float acc[8];
#pragma unroll
    for (int j = 0; j < 8; j++) acc[j] = 0.f;

    int e0 = __ldg(&rowptr[v]);
    int e1 = __ldg(&rowptr[v + 1]);
    uint4 raw_next = __ldg((const uint4*)(xl + (size_t)__ldg(&csrsrc[e0]) * DD) + lane);
    for (int e = e0; e < e1; e++) {
        uint4 raw = raw_next;
        if (e + 1 < e1)
            raw_next = __ldg((const uint4*)(xl + (size_t)__ldg(&csrsrc[e + 1]) * DD) + lane);
        const __half2* hp = (const __half2*)&raw;
        float2 f0 = __half22float2(hp[0]);
        float2 f1 = __half22float2(hp[1]);
        float2 f2 = __half22float2(hp[2]);
        float2 f3 = __half22float2(hp[3]);
        float p = 0.f;
        p = fmaf(lrelu(f0.x + xr01.x, 0.2f), a0.x, p);
        p = fmaf(lrelu(f0.y + xr01.y, 0.2f), a0.y, p);
        p = fmaf(lrelu(f1.x + xr23.x, 0.2f), a0.z, p);
        p = fmaf(lrelu(f1.y + xr23.y, 0.2f), a0.w, p);
        p = fmaf(lrelu(f2.x + xr45.x, 0.2f), a1.x, p);
        p = fmaf(lrelu(f2.y + xr45.y, 0.2f), a1.y, p);
        p = fmaf(lrelu(f3.x + xr67.x, 0.2f), a1.z, p);
        p = fmaf(lrelu(f3.y + xr67.y, 0.2f), a1.w, p);
        p += __shfl_xor_sync(0xffffffffu, p, 1);
        p += __shfl_xor_sync(0xffffffffu, p, 2);
        float nm = fmaxf(m, p);
        float sc = __expf(m - nm);
        float ep = __expf(p - nm);
        den = den * sc + ep;
        acc[0] = acc[0] * sc + f0.x * ep;
        acc[1] = acc[1] * sc + f0.y * ep;
        acc[2] = acc[2] * sc + f1.x * ep;
        acc[3] = acc[3] * sc + f1.y * ep;
        acc[4] = acc[4] * sc + f2.x * ep;
        acc[5] = acc[5] * sc + f2.y * ep;
        acc[6] = acc[6] * sc + f3.x * ep;
        acc[7] = acc[7] * sc + f3.y * ep;
        m = nm;
    }

    const float4* cb4 = (const float4*)convb;
    float4 cb0 = __ldg(&cb4[2 * lane]);
    float4 cb1 = __ldg(&cb4[2 * lane + 1]);
    float sci = __ldg(&scales[li]);
    float wi = __ldg(&wvec[li]);
    float4* h4 = (float4*)(h + (size_t)v * DD);
    float4 res0 = h4[2 * lane];
    float4 res1 = h4[2 * lane + 1];
    float id = 1.0f / den;
    float nh[8];
    nh[0] = res0.x + sci * lrelu(acc[0] * id + cb0.x, 0.1f);
    nh[1] = res0.y + sci * lrelu(acc[1] * id + cb0.y, 0.1f);
    nh[2] = res0.z + sci * lrelu(acc[2] * id + cb0.z, 0.1f);
    nh[3] = res0.w + sci * lrelu(acc[3] * id + cb0.w, 0.1f);
    nh[4] = res1.x + sci * lrelu(acc[4] * id + cb1.x, 0.1f);
    nh[5] = res1.y + sci * lrelu(acc[5] * id + cb1.y, 0.1f);
    nh[6] = res1.z + sci * lrelu(acc[6] * id + cb1.z, 0.1f);
    nh[7] = res1.w + sci * lrelu(acc[7] * id + cb1.w, 0.1f);
    h4[2 * lane] = make_float4(nh[0], nh[1], nh[2], nh[3]);
    h4[2 * lane + 1] = make_float4(nh[4], nh[5], nh[6], nh[7]);

    float4* hs4 = (float4*)(hsum + (size_t)v * DD);
    float4 sa, sb;
    if (li == 0) {
        sa = make_float4(0.f, 0.f, 0.f, 0.f);
        sb = make_float4(0.f, 0.f, 0.f, 0.f);
    } else {
        sa = hs4[2 * lane];
        sb = hs4[2 * lane + 1];
    }
    sa.x += wi * nh[0]; sa.y += wi * nh[1]; sa.z += wi * nh[2]; sa.w += wi * nh[3];
    sb.x += wi * nh[4]; sb.y += wi * nh[5]; sb.z += wi * nh[6]; sb.w += wi * nh[7];
    hs4[2 * lane] = sa;
    hs4[2 * lane + 1] = sb;

    if (li < LL - 1) {
        float s = 0.f;
        float q = 0.f;
#pragma unroll
        for (int j = 0; j < 8; j++) {
            s += nh[j];
            q += nh[j] * nh[j];
        }
        for (int d = 16; d; d >>= 1) {
            s += __shfl_xor_sync(0xffffffffu, s, d);
            q += __shfl_xor_sync(0xffffffffu, q, d);
        }
        float mu = s * (1.0f / 256.0f);
        float var = q * (1.0f / 256.0f) - mu * mu;
        float rr = rsqrtf(var + EPSF);
        const float4* g4 = (const float4*)lng;
        const float4* b4 = (const float4*)lnb;
        float4 g0 = __ldg(&g4[2 * lane]);
        float4 g1 = __ldg(&g4[2 * lane + 1]);
        float4 bb0 = __ldg(&b4[2 * lane]);
        float4 bb1 = __ldg(&b4[2 * lane + 1]);
        float o[8];
        o[0] = (nh[0] - mu) * rr * g0.x + bb0.x;
        o[1] = (nh[1] - mu) * rr * g0.y + bb0.y;
        o[2] = (nh[2] - mu) * rr * g0.z + bb0.z;
        o[3] = (nh[3] - mu) * rr * g0.w + bb0.w;
        o[4] = (nh[4] - mu) * rr * g1.x + bb1.x;
        o[5] = (nh[5] - mu) * rr * g1.y + bb1.y;
        o[6] = (nh[6] - mu) * rr * g1.z + bb1.z;
        o[7] = (nh[7] - mu) * rr * g1.w + bb1.w;
        __half ph[8];
#pragma unroll
        for (int j = 0; j < 8; j++) ph[j] = __float2half(o[j]);
        *(uint4*)(hnh + (size_t)v * DD + 8 * lane) = *(uint4*)ph;
    } else {
        float sv[8];
        sv[0] = sa.x; sv[1] = sa.y; sv[2] = sa.z; sv[3] = sa.w;
        sv[4] = sb.x; sv[5] = sb.y; sv[6] = sb.z; sv[7] = sb.w;
        __nv_bfloat16 ph[8];
        __nv_bfloat16 pl[8];
#pragma unroll
        for (int j = 0; j < 8; j++) {
            ph[j] = __float2bfloat16(sv[j]);
            pl[j] = __float2bfloat16(sv[j] - __bfloat162float(ph[j]));
        }
        *(uint4*)(hsh + (size_t)v * DD + 8 * lane) = *(uint4*)ph;
        *(uint4*)(hsl + (size_t)v * DD + 8 * lane) = *(uint4*)pl;
    }
}

// ---------------- final projection ----------------
__global__ __launch_bounds__(256) void k_final(
    const float* __restrict__ y2, const float* __restrict__ w,
    const float* __restrict__ b, float* __restrict__ out) {
    int v = (int)((blockIdx.x * blockDim.x + threadIdx.x) >> 5);
    if (v >= NN) return;
    int lane = threadIdx.x & 31;
    const float4* y4 = (const float4*)y2;
    const float4* w4 = (const float4*)w;
    float4 a = y4[v * 32 + lane];
    float4 ww = __ldg(&w4[lane]);
    float p = a.x * ww.x + a.y * ww.y + a.z * ww.z + a.w * ww.w;
    for (int d = 16; d; d >>= 1) p += __shfl_xor_sync(0xffffffffu, p, d);
    if (lane == 0) out[v] = p + __ldg(&b[0]);
}

// ---------------- launcher ----------------
extern "C" void kernel_launch(void* const* d_in, const int* in_sizes, int n_in,
                              void* d_out, int out_size) {
    (void)in_sizes; (void)n_in; (void)out_size;
    const float* x      = (const float*)d_in[0];
    const int*   ei     = (const int*)d_in[1];
    const float* win_w  = (const float*)d_in[2];
    const float* win_b  = (const float*)d_in[3];
    const float* bn1_g  = (const float*)d_in[4];
    const float* bn1_b  = (const float*)d_in[5];
    const float* ln_g   = (const float*)d_in[6];
    const float* ln_b   = (const float*)d_in[7];
    const float* Wl     = (const float*)d_in[8];
    const float* bl     = (const float*)d_in[9];
    const float* Wr     = (const float*)d_in[10];
    const float* br     = (const float*)d_in[11];
    const float* att    = (const float*)d_in[12];
    const float* conv_b = (const float*)d_in[13];
    const float* scales = (const float*)d_in[14];
    const float* sw     = (const float*)d_in[15];
    const float* h1_w   = (const float*)d_in[16];
    const float* h1_b   = (const float*)d_in[17];
    const float* bn2_g  = (const float*)d_in[18];
    const float* bn2_b  = (const float*)d_in[19];
    const float* h2_w   = (const float*)d_in[20];
    const float* h2_b   = (const float*)d_in[21];
    const float* h3_w   = (const float*)d_in[22];
    const float* h3_b   = (const float*)d_in[23];
    float* out = (float*)d_out;

    float *p_h, *p_hsum, *p_y2, *p_w;
    __half *p_xl, *p_xr, *p_hnh, *p_wlh, *p_wrh;
    __nv_bfloat16 *p_xh, *p_xlo, *p_hsh, *p_hsl, *p_y1h, *p_y1l, *p_wbh, *p_wbl;
    int *p_rowptr, *p_deg, *p_bsum, *p_cursor, *p_csr;
    cudaGetSymbolAddress((void**)&p_h, d_h);
    cudaGetSymbolAddress((void**)&p_xh, d_xh);
    cudaGetSymbolAddress((void**)&p_xlo, d_xlo);
    cudaGetSymbolAddress((void**)&p_hnh, d_hnh);
    cudaGetSymbolAddress((void**)&p_xl, d_xl);
    cudaGetSymbolAddress((void**)&p_xr, d_xr);
    cudaGetSymbolAddress((void**)&p_hsum, d_hsum);
    cudaGetSymbolAddress((void**)&p_hsh, d_hsh);
    cudaGetSymbolAddress((void**)&p_hsl, d_hsl);
    cudaGetSymbolAddress((void**)&p_y1h, d_y1h);
    cudaGetSymbolAddress((void**)&p_y1l, d_y1l);
    cudaGetSymbolAddress((void**)&p_y2, d_y2);
    cudaGetSymbolAddress((void**)&p_wbh, d_wbh);
    cudaGetSymbolAddress((void**)&p_wbl, d_wbl);
    cudaGetSymbolAddress((void**)&p_wlh, d_wlh);
    cudaGetSymbolAddress((void**)&p_wrh, d_wrh);
    cudaGetSymbolAddress((void**)&p_w, d_w);
    cudaGetSymbolAddress((void**)&p_rowptr, d_rowptr);
    cudaGetSymbolAddress((void**)&p_deg, d_deg);
    cudaGetSymbolAddress((void**)&p_bsum, d_bsum);
    cudaGetSymbolAddress((void**)&p_cursor, d_cursor);
    cudaGetSymbolAddress((void**)&p_csr, d_csrsrc);

    cudaFuncSetAttribute(k_gemm_tc<0, 1, 1>, cudaFuncAttributeMaxDynamicSharedMemorySize, SCfg<1>::SMEM);
    cudaFuncSetAttribute(k_gemm_tc<1, 0, 3>, cudaFuncAttributeMaxDynamicSharedMemorySize, SCfg<3>::SMEM);
    cudaFuncSetAttribute(k_gemm_tc<2, 0, 3>, cudaFuncAttributeMaxDynamicSharedMemorySize, SCfg<3>::SMEM);
    cudaFuncSetAttribute(k_gemm_tc<3, 0, 3>, cudaFuncAttributeMaxDynamicSharedMemorySize, SCfg<3>::SMEM);

    const int* e_src = ei;
    const int* e_dst = ei + EE;
    const int warpBlocks = (NN * 32 + 255) / 256;

    // launches 0-3: the 4th launch (idx 3) is what ncu profiles
    {
        int n4 = NN * IND / 4;
        k_split<<<(n4 + 255) / 256, 256>>>(x, p_xh, p_xlo, n4);            // 0
    }
    {
        int n4 = IND * DD / 4;
        k_split<<<(n4 + 255) / 256, 256>>>(win_w, p_wbh + W_WIN, p_wbl + W_WIN, n4);  // 1
    }
    {
        int n4e = LL * DD * DD / 4;
        k_cvt2_h<<<(2 * n4e + 255) / 256, 256>>>(Wl, Wr, p_wlh, p_wrh, n4e);  // 2
    }
    {
        dim3 g(2, (NN + 127) / 128);                                       // 3: PROFILED
        k_gemm_tc<1, 0, 3><<<g, 256, SCfg<3>::SMEM>>>(
            p_xh, p_xlo, p_wbh + W_WIN, p_wbl + W_WIN, p_wbh + W_WIN, p_wbl + W_WIN,
            win_b, win_b, bn1_g, bn1_b, p_h, NULL, NULL, NULL, NULL,
            NN, IND, DD, DD);
    }
    {
        int n4 = DD * DD / 4;
        k_split<<<(n4 + 255) / 256, 256>>>(h1_w, p_wbh + W_H1, p_wbl + W_H1, n4);
    }
    {
        int n4 = DD * (DD / 2) / 4;
        k_split<<<(n4 + 255) / 256, 256>>>(h2_w, p_wbh + W_H2, p_wbl + W_H2, n4);
    }
    k_softmax_w<<<1, 32>>>(sw, p_w);
    k_layernorm<<<warpBlocks, 256>>>(p_h, ln_g, ln_b, p_hnh);

    k_deg_init<<<(NN + 255) / 256, 256>>>(p_deg);
    k_deg_count<<<(EE + 255) / 256, 256>>>(e_dst, p_deg);
    k_blocksum<<<NB, 256>>>(p_deg, p_bsum);
    k_bscan<<<1, 256>>>(p_bsum);
    k_scanout<<<NB, 256>>>(p_deg, p_bsum, p_rowptr, p_cursor, p_csr);
    k_scatter<<<(EE + 255) / 256, 256>>>(e_src, e_dst, p_cursor, p_csr);

    for (int i = 0; i < LL; i++) {
        dim3 g(4, (NN + 127) / 128);
        k_gemm_tc<0, 1, 1><<<g, 256, SCfg<1>::SMEM>>>(
            (const __nv_bfloat16*)p_hnh, NULL,
            (const __nv_bfloat16*)(p_wlh + (size_t)i * DD * DD), NULL,
            (const __nv_bfloat16*)(p_wrh + (size_t)i * DD * DD), NULL,
            bl + i * DD, br + i * DD, NULL, NULL,
            NULL, p_xl, p_xr, NULL, NULL, NN, DD, DD, 0);
        k_gat<<<warpBlocks, 256>>>(p_xl, p_xr, p_rowptr, p_csr, att + i * DD,
                                   conv_b + i * DD, scales, p_w, i, p_h, p_hsum,
                                   ln_g + (i + 1 < LL ? (i + 1) * DD : 0),
                                   ln_b + (i + 1 < LL ? (i + 1) * DD : 0),
                                   p_hnh, p_hsh, p_hsl);
    }

    {
        dim3 g(2, (NN + 127) / 128);
        k_gemm_tc<3, 0, 3><<<g, 256, SCfg<3>::SMEM>>>(
            p_hsh, p_hsl, p_wbh + W_H1, p_wbl + W_H1, p_wbh + W_H1, p_wbl + W_H1,
            h1_b, h1_b, bn2_g, bn2_b, NULL, NULL, NULL, p_y1h, p_y1l,
            NN, DD, DD, DD);
        dim3 g2(1, (NN + 127) / 128);
        k_gemm_tc<2, 0, 3><<<g2, 256, SCfg<3>::SMEM>>>(
            p_y1h, p_y1l, p_wbh + W_H2, p_wbl + W_H2, p_wbh + W_H2, p_wbl + W_H2,
            h2_b, h2_b, NULL, NULL, p_y2, NULL, NULL, NULL, NULL,
            NN, DD, DD / 2, DD / 2);
    }
    k_final<<<warpBlocks, 256>>>(p_y2, h3_w, h3_b, out);
}

// round 14
// speedup vs baseline: 3.7685x; 1.1351x over previous
#include <cuda_runtime.h>
#include <cuda_bf16.h>
#include <cuda_fp16.h>
#include <stdint.h>
#include <math.h>

#define NN 50000
#define EE 800000
#define IND 128
#define DD 256
#define LL 6
#define EPSF 1e-5f
#define NB 196

// bf16 weight-split pool offsets (elements): win | h1 | h2
#define W_WIN 0
#define W_H1 32768
#define W_H2 98304
#define W_TOT 131072

// per-NT smem stage config. A: 128 rows x 40 b16 stride; B: 32 rows x 136 b16 stride
template <int NT> struct SCfg {
    static constexpr int AH = 0;
    static constexpr int AL = 10240;
    static constexpr int BH = (NT >= 2) ? 20480 : 10240;
    static constexpr int BL = 29184;
    static constexpr int BYTES = (NT == 3) ? 37888 : ((NT == 2) ? 29184 : 18944);
    static constexpr int NS = (NT == 1) ? 5 : 3;   // pipeline stages
    static constexpr int PD = NS - 1;              // prefetch depth
    static constexpr int SMEM = NS * BYTES;
};

// ---------------- scratch ----------------
__device__ __align__(16) float  d_h[(size_t)NN * DD];
__device__ __align__(16) __nv_bfloat16 d_xh[(size_t)NN * IND];
__device__ __align__(16) __nv_bfloat16 d_xlo[(size_t)NN * IND];
__device__ __align__(16) __half d_hnh[(size_t)NN * DD];
__device__ __align__(16) __half d_xl[(size_t)NN * DD];
__device__ __align__(16) __half d_xr[(size_t)NN * DD];
__device__ __align__(16) float  d_hsum[(size_t)NN * DD];
__device__ __align__(16) __nv_bfloat16 d_hsh[(size_t)NN * DD];
__device__ __align__(16) __nv_bfloat16 d_hsl[(size_t)NN * DD];
__device__ __align__(16) __nv_bfloat16 d_y1h[(size_t)NN * DD];
__device__ __align__(16) __nv_bfloat16 d_y1l[(size_t)NN * DD];
__device__ __align__(16) float  d_y2[(size_t)NN * (DD / 2)];
__device__ __align__(16) __nv_bfloat16 d_wbh[W_TOT];
__device__ __align__(16) __nv_bfloat16 d_wbl[W_TOT];
__device__ __align__(16) __half d_wlh[(size_t)LL * DD * DD];
__device__ __align__(16) __half d_wrh[(size_t)LL * DD * DD];
__device__ int   d_rowptr[NN + 1];
__device__ int   d_deg[NN];
__device__ int   d_bsum[NB];
__device__ int   d_cursor[NN];
__device__ int   d_csrsrc[EE + NN];
__device__ float d_w[LL];

__device__ __forceinline__ float lrelu(float x, float a) { return x > 0.f ? x : a * x; }

// ---------------- tiny kernels ----------------
__global__ void k_softmax_w(const float* __restrict__ sw, float* __restrict__ w) {
    if (threadIdx.x == 0 && blockIdx.x == 0) {
        float m = -1e30f;
        for (int i = 0; i < LL; i++) m = fmaxf(m, sw[i]);
        float e[LL];
        float s = 0.f;
        for (int i = 0; i < LL; i++) { e[i] = __expf(sw[i] - m); s += e[i]; }
        for (int i = 0; i < LL; i++) w[i] = e[i] / s;
    }
}

__global__ void k_split(const float* __restrict__ in, __nv_bfloat16* __restrict__ hi,
                        __nv_bfloat16* __restrict__ lo, int n4) {
    int i = blockIdx.x * blockDim.x + threadIdx.x;
    if (i >= n4) return;
    float4 v = ((const float4*)in)[i];
    __nv_bfloat16 h[4];
    __nv_bfloat16 l[4];
    h[0] = __float2bfloat16(v.x); l[0] = __float2bfloat16(v.x - __bfloat162float(h[0]));
    h[1] = __float2bfloat16(v.y); l[1] = __float2bfloat16(v.y - __bfloat162float(h[1]));
    h[2] = __float2bfloat16(v.z); l[2] = __float2bfloat16(v.z - __bfloat162float(h[2]));
    h[3] = __float2bfloat16(v.w); l[3] = __float2bfloat16(v.w - __bfloat162float(h[3]));
    ((uint2*)hi)[i] = *(uint2*)h;
    ((uint2*)lo)[i] = *(uint2*)l;
}

// convert two fp32 arrays -> fp16 (Wl and Wr fused)
__global__ void k_cvt2_h(const float* __restrict__ a, const float* __restrict__ b,
                         __half* __restrict__ ah, __half* __restrict__ bh, int n4each) {
    int i = blockIdx.x * blockDim.x + threadIdx.x;
    if (i >= 2 * n4each) return;
    const float* src = (i < n4each) ? a : b;
    __half* dh = (i < n4each) ? ah : bh;
    int j = (i < n4each) ? i : i - n4each;
    float4 v = ((const float4*)src)[j];
    __half h[4];
    h[0] = __float2half(v.x);
    h[1] = __float2half(v.y);
    h[2] = __float2half(v.z);
    h[3] = __float2half(v.w);
    ((uint2*)dh)[j] = *(uint2*)h;
}

__global__ void k_deg_init(int* __restrict__ deg) {
    int i = blockIdx.x * blockDim.x + threadIdx.x;
    if (i < NN) deg[i] = 1;
}

__global__ void k_deg_count(const int* __restrict__ dst, int* __restrict__ deg) {
    int i = blockIdx.x * blockDim.x + threadIdx.x;
    if (i < EE) atomicAdd(&deg[dst[i]], 1);
}

__global__ void k_blocksum(const int* __restrict__ deg, int* __restrict__ bsum) {
    int i = blockIdx.x * 256 + threadIdx.x;
    int v = (i < NN) ? deg[i] : 0;
    int lane = threadIdx.x & 31;
    int wid = threadIdx.x >> 5;
    for (int d = 16; d; d >>= 1) v += __shfl_xor_sync(0xffffffffu, v, d);
    __shared__ int ws[8];
    if (lane == 0) ws[wid] = v;
    __syncthreads();
    if (threadIdx.x == 0) {
        int s = 0;
        for (int k = 0; k < 8; k++) s += ws[k];
        bsum[blockIdx.x] = s;
    }
}

__global__ void k_bscan(int* __restrict__ bsum) {
    int t = threadIdx.x;
    int v = (t < NB) ? bsum[t] : 0;
    int lane = t & 31;
    int wid = t >> 5;
    int x = v;
    for (int d = 1; d < 32; d <<= 1) {
        int u = __shfl_up_sync(0xffffffffu, x, d);
        if (lane >= d) x += u;
    }
    __shared__ int ws[8];
    if (lane == 31) ws[wid] = x;
    __syncthreads();
    if (wid == 0 && lane < 8) {
        int y = ws[lane];
        for (int d = 1; d < 8; d <<= 1) {
            int u = __shfl_up_sync(0xffu, y, d);
            if (lane >= d) y += u;
        }
        ws[lane] = y;
    }
    __syncthreads();
    int incl = x + (wid > 0 ? ws[wid - 1] : 0);
    if (t < NB) bsum[t] = incl - v;
}

// scan-out + self-loop + cursor init fused
__global__ void k_scanout(const int* __restrict__ deg, const int* __restrict__ boff,
                          int* __restrict__ rowptr, int* __restrict__ cursor,
                          int* __restrict__ csrsrc) {
    int t = threadIdx.x;
    int i = blockIdx.x * 256 + t;
    int v = (i < NN) ? deg[i] : 0;
    int lane = t & 31;
    int wid = t >> 5;
    int x = v;
    for (int d = 1; d < 32; d <<= 1) {
        int u = __shfl_up_sync(0xffffffffu, x, d);
        if (lane >= d) x += u;
    }
    __shared__ int ws[8];
    if (lane == 31) ws[wid] = x;
    __syncthreads();
    if (wid == 0 && lane < 8) {
        int y = ws[lane];
        for (int d = 1; d < 8; d <<= 1) {
            int u = __shfl_up_sync(0xffu, y, d);
            if (lane >= d) y += u;
        }
        ws[lane] = y;
    }
    __syncthreads();
    int excl = x - v + (wid > 0 ? ws[wid - 1] : 0) + boff[blockIdx.x];
    if (i < NN) {
        rowptr[i] = excl;
        csrsrc[excl] = i;
        cursor[i] = excl + 1;
    }
    if (i == 0) rowptr[NN] = EE + NN;
}

__global__ void k_scatter(const int* __restrict__ src, const int* __restrict__ dst,
                          int* __restrict__ cursor, int* __restrict__ csrsrc) {
    int i = blockIdx.x * blockDim.x + threadIdx.x;
    if (i < EE) {
        int p = atomicAdd(&cursor[dst[i]], 1);
        csrsrc[p] = src[i];
    }
}

// ---------------- layernorm (layer 0 only): fp32 in -> fp16 out ----------------
__global__ __launch_bounds__(256) void k_layernorm(
    const float* __restrict__ h, const float* __restrict__ g,
    const float* __restrict__ b, __half* __restrict__ hnh) {
    int v = (int)((blockIdx.x * blockDim.x + threadIdx.x) >> 5);
    if (v >= NN) return;
    int lane = threadIdx.x & 31;
    const float4* h4 = (const float4*)(h + (size_t)v * DD);
    float4 x0 = h4[2 * lane];
    float4 x1 = h4[2 * lane + 1];
    float s = x0.x + x0.y + x0.z + x0.w + x1.x + x1.y + x1.z + x1.w;
    float q = x0.x * x0.x + x0.y * x0.y + x0.z * x0.z + x0.w * x0.w
            + x1.x * x1.x + x1.y * x1.y + x1.z * x1.z + x1.w * x1.w;
    for (int d = 16; d; d >>= 1) {
        s += __shfl_xor_sync(0xffffffffu, s, d);
        q += __shfl_xor_sync(0xffffffffu, q, d);
    }
    float mu = s * (1.0f / 256.0f);
    float var = q * (1.0f / 256.0f) - mu * mu;
    float r = rsqrtf(var + EPSF);
    const float4* g4 = (const float4*)g;
    const float4* b4 = (const float4*)b;
    float4 g0 = __ldg(&g4[2 * lane]);
    float4 g1 = __ldg(&g4[2 * lane + 1]);
    float4 b0 = __ldg(&b4[2 * lane]);
    float4 b1 = __ldg(&b4[2 * lane + 1]);
    float o[8];
    o[0] = (x0.x - mu) * r * g0.x + b0.x;
    o[1] = (x0.y - mu) * r * g0.y + b0.y;
    o[2] = (x0.z - mu) * r * g0.z + b0.z;
    o[3] = (x0.w - mu) * r * g0.w + b0.w;
    o[4] = (x1.x - mu) * r * g1.x + b1.x;
    o[5] = (x1.y - mu) * r * g1.y + b1.y;
    o[6] = (x1.z - mu) * r * g1.z + b1.z;
    o[7] = (x1.w - mu) * r * g1.w + b1.w;
    __half ph[8];
#pragma unroll
    for (int j = 0; j < 8; j++) ph[j] = __float2half(o[j]);
    *(uint4*)(hnh + (size_t)v * DD + 8 * lane) = *(uint4*)ph;
}

// ---------------- tensor-core GEMM ----------------
__device__ __forceinline__ void cp16(unsigned int dst, const void* src, int srcsize) {
    asm volatile("cp.async.cg.shared.global [%0], [%1], 16, %2;"
                 :: "r"(dst), "l"(src), "r"(srcsize));
}

template <int N>
__device__ __forceinline__ void waitg() {
    asm volatile("cp.async.wait_group %0;" :: "n"(N));
}

__device__ __forceinline__ void ldsm_x4(unsigned int* r, unsigned int addr) {
    asm volatile("ldmatrix.sync.aligned.m8n8.x4.shared.b16 {%0,%1,%2,%3}, [%4];"
                 : "=r"(r[0]), "=r"(r[1]), "=r"(r[2]), "=r"(r[3]) : "r"(addr));
}

__device__ __forceinline__ void ldsm_x4t(unsigned int* r, unsigned int addr) {
    asm volatile("ldmatrix.sync.aligned.m8n8.x4.trans.shared.b16 {%0,%1,%2,%3}, [%4];"
                 : "=r"(r[0]), "=r"(r[1]), "=r"(r[2]), "=r"(r[3]) : "r"(addr));
}

template <int FP16>
__device__ __forceinline__ void mma16(float* c, const unsigned int* a,
                                      const unsigned int* b) {
    if (FP16) {
        asm volatile(
            "mma.sync.aligned.m16n8k16.row.col.f32.f16.f16.f32 "
            "{%0,%1,%2,%3}, {%4,%5,%6,%7}, {%8,%9}, {%0,%1,%2,%3};"
            : "+f"(c[0]), "+f"(c[1]), "+f"(c[2]), "+f"(c[3])
            : "r"(a[0]), "r"(a[1]), "r"(a[2]), "r"(a[3]), "r"(b[0]), "r"(b[1]));
    } else {
        asm volatile(
            "mma.sync.aligned.m16n8k16.row.col.f32.bf16.bf16.f32 "
            "{%0,%1,%2,%3}, {%4,%5,%6,%7}, {%8,%9}, {%0,%1,%2,%3};"
            : "+f"(c[0]), "+f"(c[1]), "+f"(c[2]), "+f"(c[3])
            : "r"(a[0]), "r"(a[1]), "r"(a[2]), "r"(a[3]), "r"(b[0]), "r"(b[1]));
    }
}

template <int NT>
__device__ __forceinline__ void issue_stage(
    const __nv_bfloat16* __restrict__ Ah, const __nv_bfloat16* __restrict__ Al,
    const __nv_bfloat16* __restrict__ Bh, const __nv_bfloat16* __restrict__ Bl,
    unsigned int sdst, int bm, int bn_l, int M, int K, int ldb, int tid, int kk) {
#pragma unroll
    for (int u = 0; u < 2; u++) {
        int c = tid + u * 256;
        int row = c >> 2;
        int seg = c & 3;
        int gr = bm + row;
        size_t go = (size_t)gr * K + kk + seg * 8;
        unsigned int dd = sdst + SCfg<NT>::AH + row * 80 + seg * 16;
        int p = (gr < M) ? 16 : 0;
        cp16(dd, Ah + go, p);
        if (NT >= 2) cp16(dd + (SCfg<NT>::AL - SCfg<NT>::AH), Al + go, p);
    }
#pragma unroll
    for (int u = 0; u < 2; u++) {
        int c = tid + u * 256;
        int row = c >> 4;
        int seg = c & 15;
        size_t go = (size_t)(kk + row) * ldb + bn_l + seg * 8;
        unsigned int dd = sdst + SCfg<NT>::BH + row * 272 + seg * 16;
        cp16(dd, Bh + go, 16);
        if (NT == 3) cp16(dd + (SCfg<NT>::BL - SCfg<NT>::BH), Bl + go, 16);
    }
}

template <int FP16, int NT>
__device__ __forceinline__ void tile_mma(unsigned int stg, int wm0, int wn0,
                                         int aRow, int aKof, int bRow, int bNof,
                                         float acc[4][4][4]) {
#pragma unroll
    for (int ks = 0; ks < 32; ks += 16) {
        unsigned int ah[4][4];
        unsigned int al[4][4];
        unsigned int bh[4][2];
        unsigned int bl[4][2];
#pragma unroll
        for (int mi = 0; mi < 4; mi++) {
            unsigned int ad = stg + SCfg<NT>::AH
                + (unsigned int)((wm0 + mi * 16 + aRow) * 40 + ks + aKof) * 2u;
            ldsm_x4(ah[mi], ad);
            if (NT >= 2) ldsm_x4(al[mi], ad + (SCfg<NT>::AL - SCfg<NT>::AH));
        }
#pragma unroll
        for (int np = 0; np < 2; np++) {
            unsigned int bd = stg + SCfg<NT>::BH
                + (unsigned int)((ks + bRow) * 136 + wn0 + np * 16 + bNof) * 2u;
            unsigned int tb[4];
            ldsm_x4t(tb, bd);
            bh[np * 2][0] = tb[0];
            bh[np * 2][1] = tb[1];
            bh[np * 2 + 1][0] = tb[2];
            bh[np * 2 + 1][1] = tb[3];
            if (NT == 3) {
                ldsm_x4t(tb, bd + (SCfg<NT>::BL - SCfg<NT>::BH));
                bl[np * 2][0] = tb[0];
                bl[np * 2][1] = tb[1];
                bl[np * 2 + 1][0] = tb[2];
                bl[np * 2 + 1][1] = tb[3];
            }
        }
#pragma unroll
        for (int mi = 0; mi < 4; mi++) {
#pragma unroll
            for (int ni = 0; ni < 4; ni++) {
                mma16<FP16>(acc[mi][ni], ah[mi], bh[ni]);
                if (NT >= 2) mma16<FP16>(acc[mi][ni], al[mi], bh[ni]);
                if (NT == 3) mma16<FP16>(acc[mi][ni], ah[mi], bl[ni]);
            }
        }
    }
}

// EPI 0: layer -> xl/xr (both half). EPI 1: bn+lrelu -> C fp32.
// EPI 2: lrelu -> C fp32. EPI 3: bn+lrelu -> split bf16 (Coh/Col).
template <int EPI, int FP16, int NT>
__global__ __launch_bounds__(256, 2) void k_gemm_tc(
    const __nv_bfloat16* __restrict__ Ah, const __nv_bfloat16* __restrict__ Al,
    const __nv_bfloat16* __restrict__ B0h, const __nv_bfloat16* __restrict__ B0l,
    const __nv_bfloat16* __restrict__ B1h, const __nv_bfloat16* __restrict__ B1l,
    const float* __restrict__ bias0, const float* __restrict__ bias1,
    const float* __restrict__ bng, const float* __restrict__ bnb,
    float* __restrict__ C, __half* __restrict__ Cxl, __half* __restrict__ Cxr,
    __nv_bfloat16* __restrict__ Coh, __nv_bfloat16* __restrict__ Col,
    int M, int K, int ldb, int ldc) {
    extern __shared__ char smem[];
    const int tid = threadIdx.x;
    const int lane = tid & 31;
    const int wid = tid >> 5;
    const int bm = blockIdx.y * 128;
    const int bn = blockIdx.x * 128;
    const __nv_bfloat16* Bh = (bn < 256) ? B0h : B1h;
    const __nv_bfloat16* Bl = (bn < 256) ? B0l : B1l;
    const float* biasp = (bn < 256) ? bias0 : bias1;
    const int bn_l = bn & 255;
    const int wm0 = (wid & 1) * 64;
    const int wn0 = (wid >> 1) * 32;
    unsigned int sbase = (unsigned int)__cvta_generic_to_shared(smem);
    constexpr int NS = SCfg<NT>::NS;
    constexpr int PD = SCfg<NT>::PD;
    constexpr int SB = SCfg<NT>::BYTES;

    float acc[4][4][4];
#pragma unroll
    for (int i = 0; i < 4; i++) {
#pragma unroll
        for (int j = 0; j < 4; j++) {
#pragma unroll
            for (int k = 0; k < 4; k++) acc[i][j][k] = 0.f;
        }
    }

    const int grp = lane & 7;
    const int seg = lane >> 3;
    const int aRow = (seg & 1) * 8 + grp;
    const int aKof = (seg >> 1) * 8;
    const int bRow = (seg & 1) * 8 + grp;
    const int bNof = (seg >> 1) * 8;

    int nk = K / 32;
#pragma unroll
    for (int s = 0; s < PD; s++) {
        if (s < nk)
            issue_stage<NT>(Ah, Al, Bh, Bl, sbase + (unsigned int)s * SB,
                            bm, bn_l, M, K, ldb, tid, s * 32);
        asm volatile("cp.async.commit_group;");
    }

    for (int t = 0; t < nk; t++) {
        waitg<PD - 1>();
        __syncthreads();
        tile_mma<FP16, NT>(sbase + (unsigned int)(t % NS) * SB,
                           wm0, wn0, aRow, aKof, bRow, bNof, acc);
        if (t + PD < nk) {
            issue_stage<NT>(Ah, Al, Bh, Bl,
                            sbase + (unsigned int)((t + PD) % NS) * SB,
                            bm, bn_l, M, K, ldb, tid, (t + PD) * 32);
        }
        asm volatile("cp.async.commit_group;");
    }

    const float rsb = rsqrtf(1.0f + EPSF);
    const int cg = lane >> 2;
    const int cc = lane & 3;
#pragma unroll
    for (int mi = 0; mi < 4; mi++) {
        int r0 = bm + wm0 + mi * 16 + cg;
#pragma unroll
        for (int ni = 0; ni < 4; ni++) {
            int colL = wn0 + ni * 8 + 2 * cc;
            int colB = bn_l + colL;
            float b0v = __ldg(&biasp[colB]);
            float b1v = __ldg(&biasp[colB + 1]);
            float v0 = acc[mi][ni][0] + b0v;
            float v1 = acc[mi][ni][1] + b1v;
            float v2 = acc[mi][ni][2] + b0v;
            float v3 = acc[mi][ni][3] + b1v;
            if (EPI == 0) {
                __half* dst = (bn < 256) ? Cxl : Cxr;
                if (r0 < M)
                    *(__half2*)(dst + (size_t)r0 * DD + colB) = __floats2half2_rn(v0, v1);
                if (r0 + 8 < M)
                    *(__half2*)(dst + (size_t)(r0 + 8) * DD + colB) = __floats2half2_rn(v2, v3);
            } else {
                if (EPI == 1 || EPI == 3) {
                    float g0 = __ldg(&bng[colB]);
                    float g1 = __ldg(&bng[colB + 1]);
                    float q0 = __ldg(&bnb[colB]);
                    float q1 = __ldg(&bnb[colB + 1]);
                    v0 = lrelu(v0 * rsb * g0 + q0, 0.1f);
                    v1 = lrelu(v1 * rsb * g1 + q1, 0.1f);
                    v2 = lrelu(v2 * rsb * g0 + q0, 0.1f);
                    v3 = lrelu(v3 * rsb * g1 + q1, 0.1f);
                }
                if (EPI == 2) {
                    v0 = lrelu(v0, 0.1f);
                    v1 = lrelu(v1, 0.1f);
                    v2 = lrelu(v2, 0.1f);
                    v3 = lrelu(v3, 0.1f);
                }
                int col = bn + colL;
                if (EPI == 3) {
                    __nv_bfloat16 h0 = __float2bfloat16(v0);
                    __nv_bfloat16 h1 = __float2bfloat16(v1);
                    __nv_bfloat16 h2 = __float2bfloat16(v2);
                    __nv_bfloat16 h3 = __float2bfloat16(v3);
                    __nv_bfloat16 l0 = __float2bfloat16(v0 - __bfloat162float(h0));
                    __nv_bfloat16 l1 = __float2bfloat16(v1 - __bfloat162float(h1));
                    __nv_bfloat16 l2 = __float2bfloat16(v2 - __bfloat162float(h2));
                    __nv_bfloat16 l3 = __float2bfloat16(v3 - __bfloat162float(h3));
                    if (r0 < M) {
                        __nv_bfloat16 th[2] = {h0, h1};
                        __nv_bfloat16 tl[2] = {l0, l1};
                        *(unsigned int*)(Coh + (size_t)r0 * ldc + col) = *(unsigned int*)th;
                        *(unsigned int*)(Col + (size_t)r0 * ldc + col) = *(unsigned int*)tl;
                    }
                    if (r0 + 8 < M) {
                        __nv_bfloat16 th[2] = {h2, h3};
                        __nv_bfloat16 tl[2] = {l2, l3};
                        *(unsigned int*)(Coh + (size_t)(r0 + 8) * ldc + col) = *(unsigned int*)th;
                        *(unsigned int*)(Col + (size_t)(r0 + 8) * ldc + col) = *(unsigned int*)tl;
                    }
                } else {
                    if (r0 < M)
                        *(float2*)(C + (size_t)r0 * ldc + col) = make_float2(v0, v1);
                    if (r0 + 8 < M)
                        *(float2*)(C + (size_t)(r0 + 8) * ldc + col) = make_float2(v2, v3);
                }
            }
        }
    }
}

// ---------------- GATv2 aggregation (half2 inner loop) + residual + fused LN ----------------
__global__ __launch_bounds__(256) void k_gat(
    const __half* __restrict__ xl, const __half* __restrict__ xr,
    const int* __restrict__ rowptr, const int* __restrict__ csrsrc,
    const float* __restrict__ att, const float* __restrict__ convb,
    const float* __restrict__ scales, const float* __restrict__ wvec, int li,
    float* __restrict__ h, float* __restrict__ hsum,
    const float* __restrict__ lng, const float* __restrict__ lnb,
    __half* __restrict__ hnh,
    __nv_bfloat16* __restrict__ hsh, __nv_bfloat16* __restrict__ hsl) {
    int v = (int)((blockIdx.x * blockDim.x + threadIdx.x) >> 5);
    if (v >= NN) return;
    int lane = threadIdx.x & 31;

    const float4* att4 = (const float4*)att;
    float4 a0 = __ldg(&att4[2 * lane]);
    float4 a1 = __ldg(&att4[2 * lane + 1]);
    __half2 at2[4];
    at2[0] = __floats2half2_rn(a0.x, a0.y);
    at2[1] = __floats2half2_rn(a0.z, a0.w);
    at2[2] = __floats2half2_rn(a1.x, a1.y);
    at2[3] = __floats2half2_rn(a1.z, a1.w);
    uint4 rraw = __ldg((const uint4*)(xr + (size_t)v * DD) + lane);
    __half2 xr2[4];
    xr2[0] = ((const __half2*)&rraw)[0];
    xr2[1] = ((const __half2*)&rraw)[1];
    xr2[2] = ((const __half2*)&rraw)[2];
    xr2[3] = ((const __half2*)&rraw)[3];
    const __half2 k02 = __float2half2_rn(0.2f);

    float m = -1e30f;
    float den = 0.f;
    __half2 acc2[4];
#pragma unroll
    for (int j = 0; j < 4; j++) acc2[j] = __float2half2_rn(0.f);

    int e0 = __ldg(&rowptr[v]);
    int e1 = __ldg(&rowptr[v + 1]);
    uint4 raw_next = __ldg((const uint4*)(xl + (size_t)__ldg(&csrsrc[e0]) * DD) + lane);
    for (int e = e0; e < e1; e++) {
        uint4 raw = raw_next;
        if (e + 1 < e1)
            raw_next = __ldg((const uint4*)(xl + (size_t)__ldg(&csrsrc[e + 1]) * DD) + lane);
        __half2 f[4];
        f[0] = ((const __half2*)&raw)[0];
        f[1] = ((const __half2*)&raw)[1];
        f[2] = ((const __half2*)&raw)[2];
        f[3] = ((const __half2*)&raw)[3];
        __half2 p2 = __float2half2_rn(0.f);
#pragma unroll
        for (int j = 0; j < 4; j++) {
            __half2 s2 = __hadd2(f[j], xr2[j]);
            __half2 lr = __hmax2(s2, __hmul2(s2, k02));
            p2 = __hfma2(lr, at2[j], p2);
        }
        float p = __low2float(p2) + __high2float(p2);
        p += __shfl_xor_sync(0xffffffffu, p, 1);
        p += __shfl_xor_sync(0xffffffffu, p, 2);
        float nm = fmaxf(m, p);
        float sc = __expf(m - nm);
        float ep = __expf(p - nm);
        den = den * sc + ep;
        __half2 sc2 = __float2half2_rn(sc);
        __half2 ep2 = __float2half2_rn(ep);
#pragma unroll
        for (int j = 0; j < 4; j++)
            acc2[j] = __hfma2(f[j], ep2, __hmul2(acc2[j], sc2));
        m = nm;
    }

    float acc[8];
    {
        float2 t0 = __half22float2(acc2[0]);
        float2 t1 = __half22float2(acc2[1]);
        float2 t2 = __half22float2(acc2[2]);
        float2 t3 = __half22float2(acc2[3]);
        acc[0] = t0.x; acc[1] = t0.y; acc[2] = t1.x; acc[3] = t1.y;
        acc[4] = t2.x; acc[5] = t2.y; acc[6] = t3.x; acc[7] = t3.y;
    }

    const float4* cb4 = (const float4*)convb;
    float4 cb0 = __ldg(&cb4[2 * lane]);
    float4 cb1 = __ldg(&cb4[2 * lane + 1]);
    float sci = __ldg(&scales[li]);
    float wi = __ldg(&wvec[li]);
    float4* h4 = (float4*)(h + (size_t)v * DD);
    float4 res0 = h4[2 * lane];
    float4 res1 = h4[2 * lane + 1];
    float id = 1.0f / den;
    float nh[8];
    nh[0] = res0.x + sci * lrelu(acc[0] * id + cb0.x, 0.1f);
    nh[1] = res0.y + sci * lrelu(acc[1] * id + cb0.y, 0.1f);
    nh[2] = res0.z + sci * lrelu(acc[2] * id + cb0.z, 0.1f);
    nh[3] = res0.w + sci * lrelu(acc[3] * id + cb0.w, 0.1f);
    nh[4] = res1.x + sci * lrelu(acc[4] * id + cb1.x, 0.1f);
    nh[5] = res1.y + sci * lrelu(acc[5] * id + cb1.y, 0.1f);
    nh[6] = res1.z + sci * lrelu(acc[6] * id + cb1.z, 0.1f);
    nh[7] = res1.w + sci * lrelu(acc[7] * id + cb1.w, 0.1f);
    h4[2 * lane] = make_float4(nh[0], nh[1], nh[2], nh[3]);
    h4[2 * lane + 1] = make_float4(nh[4], nh[5], nh[6], nh[7]);

    float4* hs4 = (float4*)(hsum + (size_t)v * DD);
    float4 sa, sb;
    if (li == 0) {
        sa = make_float4(0.f, 0.f, 0.f, 0.f);
        sb = make_float4(0.f, 0.f, 0.f, 0.f);
    } else {
        sa = hs4[2 * lane];
        sb = hs4[2 * lane + 1];
    }
    sa.x += wi * nh[0]; sa.y += wi * nh[1]; sa.z += wi * nh[2]; sa.w += wi * nh[3];
    sb.x += wi * nh[4]; sb.y += wi * nh[5]; sb.z += wi * nh[6]; sb.w += wi * nh[7];
    hs4[2 * lane] = sa;
    hs4[2 * lane + 1] = sb;

    if (li < LL - 1) {
        float s = 0.f;
        float q = 0.f;
#pragma unroll
        for (int j = 0; j < 8; j++) {
            s += nh[j];
            q += nh[j] * nh[j];
        }
        for (int d = 16; d; d >>= 1) {
            s += __shfl_xor_sync(0xffffffffu, s, d);
            q += __shfl_xor_sync(0xffffffffu, q, d);
        }
        float mu = s * (1.0f / 256.0f);
        float var = q * (1.0f / 256.0f) - mu * mu;
        float rr = rsqrtf(var + EPSF);
        const float4* g4 = (const float4*)lng;
        const float4* b4 = (const float4*)lnb;
        float4 g0 = __ldg(&g4[2 * lane]);
        float4 g1 = __ldg(&g4[2 * lane + 1]);
        float4 bb0 = __ldg(&b4[2 * lane]);
        float4 bb1 = __ldg(&b4[2 * lane + 1]);
        float o[8];
        o[0] = (nh[0] - mu) * rr * g0.x + bb0.x;
        o[1] = (nh[1] - mu) * rr * g0.y + bb0.y;
        o[2] = (nh[2] - mu) * rr * g0.z + bb0.z;
        o[3] = (nh[3] - mu) * rr * g0.w + bb0.w;
        o[4] = (nh[4] - mu) * rr * g1.x + bb1.x;
        o[5] = (nh[5] - mu) * rr * g1.y + bb1.y;
        o[6] = (nh[6] - mu) * rr * g1.z + bb1.z;
        o[7] = (nh[7] - mu) * rr * g1.w + bb1.w;
        __half ph[8];
#pragma unroll
        for (int j = 0; j < 8; j++) ph[j] = __float2half(o[j]);
        *(uint4*)(hnh + (size_t)v * DD + 8 * lane) = *(uint4*)ph;
    } else {
        float sv[8];
        sv[0] = sa.x; sv[1] = sa.y; sv[2] = sa.z; sv[3] = sa.w;
        sv[4] = sb.x; sv[5] = sb.y; sv[6] = sb.z; sv[7] = sb.w;
        __nv_bfloat16 ph[8];
        __nv_bfloat16 pl[8];
#pragma unroll
        for (int j = 0; j < 8; j++) {
            ph[j] = __float2bfloat16(sv[j]);
            pl[j] = __float2bfloat16(sv[j] - __bfloat162float(ph[j]));
        }
        *(uint4*)(hsh + (size_t)v * DD + 8 * lane) = *(uint4*)ph;
        *(uint4*)(hsl + (size_t)v * DD + 8 * lane) = *(uint4*)pl;
    }
}

// ---------------- final projection ----------------
__global__ __launch_bounds__(256) void k_final(
    const float* __restrict__ y2, const float* __restrict__ w,
    const float* __restrict__ b, float* __restrict__ out) {
    int v = (int)((blockIdx.x * blockDim.x + threadIdx.x) >> 5);
    if (v >= NN) return;
    int lane = threadIdx.x & 31;
    const float4* y4 = (const float4*)y2;
    const float4* w4 = (const float4*)w;
    float4 a = y4[v * 32 + lane];
    float4 ww = __ldg(&w4[lane]);
    float p = a.x * ww.x + a.y * ww.y + a.z * ww.z + a.w * ww.w;
    for (int d = 16; d; d >>= 1) p += __shfl_xor_sync(0xffffffffu, p, d);
    if (lane == 0) out[v] = p + __ldg(&b[0]);
}

// ---------------- launcher ----------------
extern "C" void kernel_launch(void* const* d_in, const int* in_sizes, int n_in,
                              void* d_out, int out_size) {
    (void)in_sizes; (void)n_in; (void)out_size;
    const float* x      = (const float*)d_in[0];
    const int*   ei     = (const int*)d_in[1];
    const float* win_w  = (const float*)d_in[2];
    const float* win_b  = (const float*)d_in[3];
    const float* bn1_g  = (const float*)d_in[4];
    const float* bn1_b  = (const float*)d_in[5];
    const float* ln_g   = (const float*)d_in[6];
    const float* ln_b   = (const float*)d_in[7];
    const float* Wl     = (const float*)d_in[8];
    const float* bl     = (const float*)d_in[9];
    const float* Wr     = (const float*)d_in[10];
    const float* br     = (const float*)d_in[11];
    const float* att    = (const float*)d_in[12];
    const float* conv_b = (const float*)d_in[13];
    const float* scales = (const float*)d_in[14];
    const float* sw     = (const float*)d_in[15];
    const float* h1_w   = (const float*)d_in[16];
    const float* h1_b   = (const float*)d_in[17];
    const float* bn2_g  = (const float*)d_in[18];
    const float* bn2_b  = (const float*)d_in[19];
    const float* h2_w   = (const float*)d_in[20];
    const float* h2_b   = (const float*)d_in[21];
    const float* h3_w   = (const float*)d_in[22];
    const float* h3_b   = (const float*)d_in[23];
    float* out = (float*)d_out;

    float *p_h, *p_hsum, *p_y2, *p_w;
    __half *p_xl, *p_xr, *p_hnh, *p_wlh, *p_wrh;
    __nv_bfloat16 *p_xh, *p_xlo, *p_hsh, *p_hsl, *p_y1h, *p_y1l, *p_wbh, *p_wbl;
    int *p_rowptr, *p_deg, *p_bsum, *p_cursor, *p_csr;
    cudaGetSymbolAddress((void**)&p_h, d_h);
    cudaGetSymbolAddress((void**)&p_xh, d_xh);
    cudaGetSymbolAddress((void**)&p_xlo, d_xlo);
    cudaGetSymbolAddress((void**)&p_hnh, d_hnh);
    cudaGetSymbolAddress((void**)&p_xl, d_xl);
    cudaGetSymbolAddress((void**)&p_xr, d_xr);
    cudaGetSymbolAddress((void**)&p_hsum, d_hsum);
    cudaGetSymbolAddress((void**)&p_hsh, d_hsh);
    cudaGetSymbolAddress((void**)&p_hsl, d_hsl);
    cudaGetSymbolAddress((void**)&p_y1h, d_y1h);
    cudaGetSymbolAddress((void**)&p_y1l, d_y1l);
    cudaGetSymbolAddress((void**)&p_y2, d_y2);
    cudaGetSymbolAddress((void**)&p_wbh, d_wbh);
    cudaGetSymbolAddress((void**)&p_wbl, d_wbl);
    cudaGetSymbolAddress((void**)&p_wlh, d_wlh);
    cudaGetSymbolAddress((void**)&p_wrh, d_wrh);
    cudaGetSymbolAddress((void**)&p_w, d_w);
    cudaGetSymbolAddress((void**)&p_rowptr, d_rowptr);
    cudaGetSymbolAddress((void**)&p_deg, d_deg);
    cudaGetSymbolAddress((void**)&p_bsum, d_bsum);
    cudaGetSymbolAddress((void**)&p_cursor, d_cursor);
    cudaGetSymbolAddress((void**)&p_csr, d_csrsrc);

    cudaFuncSetAttribute(k_gemm_tc<0, 1, 1>, cudaFuncAttributeMaxDynamicSharedMemorySize, SCfg<1>::SMEM);
    cudaFuncSetAttribute(k_gemm_tc<1, 0, 3>, cudaFuncAttributeMaxDynamicSharedMemorySize, SCfg<3>::SMEM);
    cudaFuncSetAttribute(k_gemm_tc<2, 0, 3>, cudaFuncAttributeMaxDynamicSharedMemorySize, SCfg<3>::SMEM);
    cudaFuncSetAttribute(k_gemm_tc<3, 0, 3>, cudaFuncAttributeMaxDynamicSharedMemorySize, SCfg<3>::SMEM);

    const int* e_src = ei;
    const int* e_dst = ei + EE;
    const int warpBlocks = (NN * 32 + 255) / 256;

    // launches 0-3: the 4th launch (idx 3) is what ncu profiles
    {
        int n4 = NN * IND / 4;
        k_split<<<(n4 + 255) / 256, 256>>>(x, p_xh, p_xlo, n4);            // 0
    }
    {
        int n4 = IND * DD / 4;
        k_split<<<(n4 + 255) / 256, 256>>>(win_w, p_wbh + W_WIN, p_wbl + W_WIN, n4);  // 1
    }
    {
        int n4e = LL * DD * DD / 4;
        k_cvt2_h<<<(2 * n4e + 255) / 256, 256>>>(Wl, Wr, p_wlh, p_wrh, n4e);  // 2
    }
    {
        dim3 g(2, (NN + 127) / 128);                                       // 3: PROFILED
        k_gemm_tc<1, 0, 3><<<g, 256, SCfg<3>::SMEM>>>(
            p_xh, p_xlo, p_wbh + W_WIN, p_wbl + W_WIN, p_wbh + W_WIN, p_wbl + W_WIN,
            win_b, win_b, bn1_g, bn1_b, p_h, NULL, NULL, NULL, NULL,
            NN, IND, DD, DD);
    }
    {
        int n4 = DD * DD / 4;
        k_split<<<(n4 + 255) / 256, 256>>>(h1_w, p_wbh + W_H1, p_wbl + W_H1, n4);
    }
    {
        int n4 = DD * (DD / 2) / 4;
        k_split<<<(n4 + 255) / 256, 256>>>(h2_w, p_wbh + W_H2, p_wbl + W_H2, n4);
    }
    k_softmax_w<<<1, 32>>>(sw, p_w);
    k_layernorm<<<warpBlocks, 256>>>(p_h, ln_g, ln_b, p_hnh);

    k_deg_init<<<(NN + 255) / 256, 256>>>(p_deg);
    k_deg_count<<<(EE + 255) / 256, 256>>>(e_dst, p_deg);
    k_blocksum<<<NB, 256>>>(p_deg, p_bsum);
    k_bscan<<<1, 256>>>(p_bsum);
    k_scanout<<<NB, 256>>>(p_deg, p_bsum, p_rowptr, p_cursor, p_csr);
    k_scatter<<<(EE + 255) / 256, 256>>>(e_src, e_dst, p_cursor, p_csr);

    for (int i = 0; i < LL; i++) {
        dim3 g(4, (NN + 127) / 128);
        k_gemm_tc<0, 1, 1><<<g, 256, SCfg<1>::SMEM>>>(
            (const __nv_bfloat16*)p_hnh, NULL,
            (const __nv_bfloat16*)(p_wlh + (size_t)i * DD * DD), NULL,
            (const __nv_bfloat16*)(p_wrh + (size_t)i * DD * DD), NULL,
            bl + i * DD, br + i * DD, NULL, NULL,
            NULL, p_xl, p_xr, NULL, NULL, NN, DD, DD, 0);
        k_gat<<<warpBlocks, 256>>>(p_xl, p_xr, p_rowptr, p_csr, att + i * DD,
                                   conv_b + i * DD, scales, p_w, i, p_h, p_hsum,
                                   ln_g + (i + 1 < LL ? (i + 1) * DD : 0),
                                   ln_b + (i + 1 < LL ? (i + 1) * DD : 0),
                                   p_hnh, p_hsh, p_hsl);
    }

    {
        dim3 g(2, (NN + 127) / 128);
        k_gemm_tc<3, 0, 3><<<g, 256, SCfg<3>::SMEM>>>(
            p_hsh, p_hsl, p_wbh + W_H1, p_wbl + W_H1, p_wbh + W_H1, p_wbl + W_H1,
            h1_b, h1_b, bn2_g, bn2_b, NULL, NULL, NULL, p_y1h, p_y1l,
            NN, DD, DD, DD);
        dim3 g2(1, (NN + 127) / 128);
        k_gemm_tc<2, 0, 3><<<g2, 256, SCfg<3>::SMEM>>>(
            p_y1h, p_y1l, p_wbh + W_H2, p_wbl + W_H2, p_wbh + W_H2, p_wbl + W_H2,
            h2_b, h2_b, NULL, NULL, p_y2, NULL, NULL, NULL, NULL,
            NN, DD, DD / 2, DD / 2);
    }
    k_final<<<warpBlocks, 256>>>(p_y2, h3_w, h3_b, out);
}